// round 10
// baseline (speedup 1.0000x reference)
#include <cuda_runtime.h>
#include <cuda_bf16.h>
#include <cstdint>
#include <math.h>

typedef unsigned int u32;

#define B_   2
#define T_   2048
#define C_   1024
#define H_   16
#define D_   64
#define NTOK (B_*T_)
#define DFF  4096
#define C3   (3*C_)

// ---------------- scratch (no allocation allowed) ----------------
__device__ __nv_bfloat16 g_hb  [NTOK*C_];
__device__ __nv_bfloat16 g_h2b [NTOK*C_];
__device__ __nv_bfloat16 g_qkv [NTOK*C3];
__device__ __nv_bfloat16 g_attb[NTOK*C_];
__device__ __nv_bfloat16 g_f1b [(size_t)NTOK*DFF];
__device__ float         g_x1  [NTOK*C_];
__device__ __nv_bfloat16 g_wqkv[C_*C3];
__device__ __nv_bfloat16 g_wo  [C_*C_];
__device__ __nv_bfloat16 g_wf1 [C_*DFF];
__device__ __nv_bfloat16 g_wf2 [DFF*C_];
__device__ float         g_bqkv[C3];

// ---------------- small helpers ----------------
__device__ __forceinline__ u32 pack_bf16(float x, float y) {
    __nv_bfloat162 t = __floats2bfloat162_rn(x, y);
    u32 r; memcpy(&r, &t, 4); return r;
}
__device__ __forceinline__ void cp16(u32 sdst, const void* gsrc) {
    asm volatile("cp.async.cg.shared.global [%0], [%1], 16;" :: "r"(sdst), "l"(gsrc));
}
__device__ __forceinline__ void cp_commit() { asm volatile("cp.async.commit_group;"); }
__device__ __forceinline__ void ldsm_x4(u32& r0, u32& r1, u32& r2, u32& r3, u32 addr) {
    asm volatile("ldmatrix.sync.aligned.m8n8.x4.shared.b16 {%0,%1,%2,%3},[%4];"
                 : "=r"(r0), "=r"(r1), "=r"(r2), "=r"(r3) : "r"(addr));
}
__device__ __forceinline__ void ldsm_x4_t(u32& r0, u32& r1, u32& r2, u32& r3, u32 addr) {
    asm volatile("ldmatrix.sync.aligned.m8n8.x4.trans.shared.b16 {%0,%1,%2,%3},[%4];"
                 : "=r"(r0), "=r"(r1), "=r"(r2), "=r"(r3) : "r"(addr));
}
__device__ __forceinline__ void mma_bf16(float* c, const u32* a, u32 b0, u32 b1) {
    asm volatile("mma.sync.aligned.m16n8k16.row.col.f32.bf16.bf16.f32 "
                 "{%0,%1,%2,%3},{%4,%5,%6,%7},{%8,%9},{%0,%1,%2,%3};"
                 : "+f"(c[0]), "+f"(c[1]), "+f"(c[2]), "+f"(c[3])
                 : "r"(a[0]), "r"(a[1]), "r"(a[2]), "r"(a[3]), "r"(b0), "r"(b1));
}
// FFMA-only exp (no MUFU).
__device__ __forceinline__ float fexp(float x) {
    x = fmaxf(x, -80.0f);
    float y = x * 1.4426950408889634f;
    float k = rintf(y);
    float t = (y - k) * 0.6931471805599453f;
    float p = fmaf(t, fmaf(t, fmaf(t, fmaf(t, fmaf(t, 8.3333333e-3f, 4.1666667e-2f),
                 0.16666667f), 0.5f), 1.0f), 1.0f);
    int ki = (int)k;
    return __int_as_float(__float_as_int(p) + (ki << 23));
}

// ---------------- weight conversion ----------------
__global__ void cvt_qkv_kernel(const float* __restrict__ qw, const float* __restrict__ kw,
                               const float* __restrict__ vw, const float* __restrict__ qb,
                               const float* __restrict__ kb, const float* __restrict__ vb)
{
    int gtid = blockIdx.x * blockDim.x + threadIdx.x;
    int stride = gridDim.x * blockDim.x;
    for (int i = gtid; i < C_*C_/4; i += stride) {
        int c = i / (C_/4), j = (i % (C_/4)) * 4;
        float4 q4 = *(const float4*)(qw + (size_t)c*C_ + j);
        float4 k4 = *(const float4*)(kw + (size_t)c*C_ + j);
        float4 v4 = *(const float4*)(vw + (size_t)c*C_ + j);
        *(uint2*)(g_wqkv + (size_t)c*C3 + j)        = make_uint2(pack_bf16(q4.x,q4.y), pack_bf16(q4.z,q4.w));
        *(uint2*)(g_wqkv + (size_t)c*C3 + C_ + j)   = make_uint2(pack_bf16(k4.x,k4.y), pack_bf16(k4.z,k4.w));
        *(uint2*)(g_wqkv + (size_t)c*C3 + 2*C_ + j) = make_uint2(pack_bf16(v4.x,v4.y), pack_bf16(v4.z,v4.w));
    }
    if (gtid < C_) {
        g_bqkv[gtid]        = qb[gtid];
        g_bqkv[C_ + gtid]   = kb[gtid];
        g_bqkv[2*C_ + gtid] = vb[gtid];
    }
}
// fused convert of O/FF1/FF2 weights (one launch)
__global__ void cvt3_kernel(const float* __restrict__ ow, const float* __restrict__ f1w,
                            const float* __restrict__ f2w)
{
    int gtid = blockIdx.x * blockDim.x + threadIdx.x;
    int stride = gridDim.x * blockDim.x;
    const int n_o  = C_*C_/4;
    const int n_f  = C_*DFF/4;
    for (int i = gtid; i < n_o; i += stride) {
        float4 s = *(const float4*)(ow + (size_t)i*4);
        *(uint2*)(g_wo + (size_t)i*4) = make_uint2(pack_bf16(s.x,s.y), pack_bf16(s.z,s.w));
    }
    for (int i = gtid; i < n_f; i += stride) {
        float4 s = *(const float4*)(f1w + (size_t)i*4);
        *(uint2*)(g_wf1 + (size_t)i*4) = make_uint2(pack_bf16(s.x,s.y), pack_bf16(s.z,s.w));
    }
    for (int i = gtid; i < n_f; i += stride) {
        float4 s = *(const float4*)(f2w + (size_t)i*4);
        *(uint2*)(g_wf2 + (size_t)i*4) = make_uint2(pack_bf16(s.x,s.y), pack_bf16(s.z,s.w));
    }
}

// ---------------- LayerNorm: fp32 in -> bf16 out ----------------
__global__ void __launch_bounds__(256) ln_kernel(const float* __restrict__ x,
                                                 const float* __restrict__ w,
                                                 const float* __restrict__ b,
                                                 __nv_bfloat16* __restrict__ y)
{
    __shared__ float red[8];
    int row = blockIdx.x, tid = threadIdx.x;
    const float* xr = x + (size_t)row * C_;
    float4 v = *(const float4*)(xr + 4*tid);

    float s = v.x + v.y + v.z + v.w;
#pragma unroll
    for (int o = 16; o > 0; o >>= 1) s += __shfl_xor_sync(~0u, s, o);
    if ((tid & 31) == 0) red[tid >> 5] = s;
    __syncthreads();
    if (tid < 32) {
        float t = (tid < 8) ? red[tid] : 0.f;
#pragma unroll
        for (int o = 4; o > 0; o >>= 1) t += __shfl_xor_sync(~0u, t, o);
        if (tid == 0) red[0] = t;
    }
    __syncthreads();
    float mu = red[0] * (1.0f / C_);
    __syncthreads();

    float dx = v.x-mu, dy = v.y-mu, dz = v.z-mu, dw = v.w-mu;
    float sq = dx*dx + dy*dy + dz*dz + dw*dw;
#pragma unroll
    for (int o = 16; o > 0; o >>= 1) sq += __shfl_xor_sync(~0u, sq, o);
    if ((tid & 31) == 0) red[tid >> 5] = sq;
    __syncthreads();
    if (tid < 32) {
        float t = (tid < 8) ? red[tid] : 0.f;
#pragma unroll
        for (int o = 4; o > 0; o >>= 1) t += __shfl_xor_sync(~0u, t, o);
        if (tid == 0) red[0] = t;
    }
    __syncthreads();
    float rs = rsqrtf(red[0] * (1.0f / C_) + 1e-5f);
    float4 w4 = *(const float4*)(w + 4*tid);
    float4 b4 = *(const float4*)(b + 4*tid);
    float o0 = dx*rs*w4.x + b4.x, o1 = dy*rs*w4.y + b4.y;
    float o2 = dz*rs*w4.z + b4.z, o3 = dw*rs*w4.w + b4.w;
    *(uint2*)(y + (size_t)row*C_ + 4*tid) = make_uint2(pack_bf16(o0,o1), pack_bf16(o2,o3));
}

// ---------------- GEMM 128x128x32, 4 warps, warp tile 64x64, 4-stage ----------------
#define GA_ROWB   80
#define GB_ROWB   272
#define GA_BYTES  (128*GA_ROWB)
#define GB_BYTES  (32*GB_ROWB)
#define STAGE_B   (GA_BYTES + GB_BYTES)
#define NSTAGE    4
#define GEMM_SMEM (NSTAGE*STAGE_B)

template<int MODE, int OBF>
__global__ void __launch_bounds__(128) bgemm_kernel(
    const __nv_bfloat16* __restrict__ A, const __nv_bfloat16* __restrict__ Bw,
    const float* __restrict__ bias,
    const float* __restrict__ resid, const float* __restrict__ gamma,
    void* __restrict__ CoutV, int M, int N, int K)
{
    extern __shared__ char gsm[];
    const u32 smb = (u32)__cvta_generic_to_shared(gsm);

    const int tid  = threadIdx.x;
    const int lane = tid & 31, warp = tid >> 5;
    const int warp_m = warp >> 1, warp_n = warp & 1;
    const int m_blk = blockIdx.y << 7, n_blk = blockIdx.x << 7;

    const int ar = tid >> 2, ac = tid & 3;
    const int br = tid >> 4, bc = tid & 15;
    const __nv_bfloat16* Ag = A  + (size_t)(m_blk + ar) * K + ac*8;
    const __nv_bfloat16* Bg = Bw + (size_t)br * N + n_blk + bc*8;
    const u32 dA0 = smb + ar*GA_ROWB + ac*16;
    const u32 dB0 = smb + GA_BYTES + br*GB_ROWB + bc*16;

    const int g  = lane >> 3;
    const int r8 = lane & 7;
    const u32 aAddr0 = smb + (u32)(warp_m*64 + r8 + (g&1)*8) * GA_ROWB + (u32)((g>>1)*16);
    const u32 bAddr0 = smb + GA_BYTES + (u32)(r8 + (g&1)*8) * GB_ROWB
                           + (u32)(warp_n*64 + (g>>1)*8) * 2;

    float acc[4][8][4];
#pragma unroll
    for (int mt = 0; mt < 4; mt++)
#pragma unroll
        for (int nt = 0; nt < 8; nt++)
#pragma unroll
            for (int i = 0; i < 4; i++) acc[mt][nt][i] = 0.f;

    const int nk = K >> 5;

    auto issue = [&](int kt) {
        const u32 sb = (kt & (NSTAGE-1)) * STAGE_B;
        const __nv_bfloat16* Ak = Ag + (kt << 5);
        const __nv_bfloat16* Bk = Bg + (size_t)(kt << 5) * N;
#pragma unroll
        for (int p = 0; p < 4; p++)
            cp16(dA0 + sb + p*32*GA_ROWB, Ak + (size_t)(p*32)*K);
#pragma unroll
        for (int p = 0; p < 4; p++)
            cp16(dB0 + sb + p*8*GB_ROWB,  Bk + (size_t)(p*8)*N);
        cp_commit();
    };

    issue(0);
    if (nk > 1) issue(1);
    if (nk > 2) issue(2);

    for (int kt = 0; kt < nk; kt++) {
        if      (kt + 2 < nk) asm volatile("cp.async.wait_group 2;");
        else if (kt + 1 < nk) asm volatile("cp.async.wait_group 1;");
        else                  asm volatile("cp.async.wait_group 0;");
        __syncthreads();

        if (kt + 3 < nk) issue(kt + 3);

        const u32 sb = (kt & (NSTAGE-1)) * STAGE_B;
        const u32 aB = aAddr0 + sb;
        const u32 bB = bAddr0 + sb;
#pragma unroll
        for (int ks = 0; ks < 2; ks++) {
            // ---- batch ALL fragment loads first (volatile asm keeps order) ----
            u32 af[4][4], bf[4][4];
#pragma unroll
            for (int mt = 0; mt < 4; mt++)
                ldsm_x4(af[mt][0], af[mt][1], af[mt][2], af[mt][3],
                        aB + (u32)(mt*16) * GA_ROWB + (u32)(ks*32));
#pragma unroll
            for (int np = 0; np < 4; np++)
                ldsm_x4_t(bf[np][0], bf[np][1], bf[np][2], bf[np][3],
                          bB + (u32)(ks*16) * GB_ROWB + (u32)(np*32));
            // ---- then an unbroken mma stream ----
#pragma unroll
            for (int np = 0; np < 4; np++)
#pragma unroll
                for (int mt = 0; mt < 4; mt++) {
                    mma_bf16(acc[mt][2*np],   af[mt], bf[np][0], bf[np][1]);
                    mma_bf16(acc[mt][2*np+1], af[mt], bf[np][2], bf[np][3]);
                }
        }
    }

    const int rr = lane >> 2, cc = (lane & 3) << 1;
    const int row0 = m_blk + warp_m * 64;
    const int col0 = n_blk + warp_n * 64;
#pragma unroll
    for (int mt = 0; mt < 4; mt++) {
#pragma unroll
        for (int nt = 0; nt < 8; nt++) {
            const int col = col0 + nt * 8 + cc;
            float2 b2 = *(const float2*)(bias + col);
            float2 g2 = make_float2(0.f, 0.f);
            if (MODE == 1) g2 = *(const float2*)(gamma + col);
#pragma unroll
            for (int half = 0; half < 2; half++) {
                const int row = row0 + mt * 16 + rr + half * 8;
                const size_t off = (size_t)row * N + col;
                float v0 = acc[mt][nt][half*2 + 0] + b2.x;
                float v1 = acc[mt][nt][half*2 + 1] + b2.y;
                if (MODE == 1) {
                    float2 rv = *(const float2*)(resid + off);
                    v0 = rv.x + g2.x * v0;
                    v1 = rv.y + g2.y * v1;
                } else if (MODE == 2) {
                    v0 = 0.5f * v0 * (1.0f + erff(v0 * 0.70710678118654752f));
                    v1 = 0.5f * v1 * (1.0f + erff(v1 * 0.70710678118654752f));
                }
                if (OBF) *(u32*)((__nv_bfloat16*)CoutV + off) = pack_bf16(v0, v1);
                else     *(float2*)((float*)CoutV + off) = make_float2(v0, v1);
            }
        }
    }
}

// ---------------- Flash attention: 128 queries/CTA, 8 warps ----------------
#define KV_ROWB  144
#define QTILE_B  (128*KV_ROWB)
#define KVTILE_B (64*KV_ROWB)
#define SQ_OFF   0
#define SK_OFF   (QTILE_B)
#define SV_OFF   (QTILE_B + 2*KVTILE_B)
#define SMSK_OFF (QTILE_B + 4*KVTILE_B)
#define ATTN_SMEM (SMSK_OFF + 2*64*4)

__device__ __forceinline__ void attn_issue_kv(const __nv_bfloat16* __restrict__ qkv,
                                              u32 smb, int buf, int kt, int b, int h, int tid)
{
    const __nv_bfloat16* gK = qkv + ((size_t)(b*T_) + kt*64) * C3 + C_ + h*D_;
    const __nv_bfloat16* gV = gK + C_;
    u32 dK = smb + SK_OFF + buf*KVTILE_B;
    u32 dV = smb + SV_OFF + buf*KVTILE_B;
#pragma unroll
    for (int k = 0; k < 2; k++) {
        int c = tid + k*256;
        int row = c >> 3, col16 = c & 7;
        cp16(dK + row*KV_ROWB + col16*16, gK + (size_t)row*C3 + col16*8);
        cp16(dV + row*KV_ROWB + col16*16, gV + (size_t)row*C3 + col16*8);
    }
}

__global__ void __launch_bounds__(256) attn_kernel(
    const __nv_bfloat16* __restrict__ qkv, const int* __restrict__ mask,
    __nv_bfloat16* __restrict__ Out)
{
    extern __shared__ char attn_sm[];
    u32 smb = (u32)__cvta_generic_to_shared(attn_sm);
    float* sMask = (float*)(attn_sm + SMSK_OFF);

    const int tid = threadIdx.x;
    const int lane = tid & 31, warp = tid >> 5;
    const int b = blockIdx.z, h = blockIdx.y;
    const int q0 = blockIdx.x << 7;
    const int g = lane >> 3, r8 = lane & 7;
    const int qd = lane >> 2, qi = lane & 3;

    {
        const __nv_bfloat16* gQ = qkv + ((size_t)(b*T_ + q0)) * C3 + h*D_;
#pragma unroll
        for (int k = 0; k < 4; k++) {
            int c = tid + k*256;
            int row = c >> 3, col16 = c & 7;
            cp16(smb + SQ_OFF + row*KV_ROWB + col16*16, gQ + (size_t)row*C3 + col16*8);
        }
        attn_issue_kv(qkv, smb, 0, 0, b, h, tid);
        if (tid < 64) sMask[tid] = mask[b*T_ + tid] ? 0.f : -1e30f;
        cp_commit();
    }

    float ofrag[8][4];
#pragma unroll
    for (int nt = 0; nt < 8; nt++)
#pragma unroll
        for (int i = 0; i < 4; i++) ofrag[nt][i] = 0.f;
    float mrow0 = -1e30f, mrow1 = -1e30f, lrow0 = 0.f, lrow1 = 0.f;
    u32 qf[4][4];

    const int NKT = T_ / 64;
    for (int kt = 0; kt < NKT; kt++) {
        const int cur = kt & 1;
        if (kt + 1 < NKT) {
            attn_issue_kv(qkv, smb, cur ^ 1, kt + 1, b, h, tid);
            if (tid < 64) sMask[(cur^1)*64 + tid] = mask[b*T_ + (kt+1)*64 + tid] ? 0.f : -1e30f;
            cp_commit();
            asm volatile("cp.async.wait_group 1;");
        } else {
            asm volatile("cp.async.wait_group 0;");
        }
        __syncthreads();

        if (kt == 0) {
#pragma unroll
            for (int ks = 0; ks < 4; ks++) {
                u32 addr = smb + SQ_OFF
                         + (u32)(warp*16 + r8 + (g&1)*8) * KV_ROWB
                         + (u32)(ks*16 + (g>>1)*8) * 2;
                ldsm_x4(qf[ks][0], qf[ks][1], qf[ks][2], qf[ks][3], addr);
            }
        }

        float sfrag[8][4];
#pragma unroll
        for (int nt = 0; nt < 8; nt++)
#pragma unroll
            for (int i = 0; i < 4; i++) sfrag[nt][i] = 0.f;
        const u32 kBase = smb + SK_OFF + cur*KVTILE_B;
#pragma unroll
        for (int ks = 0; ks < 4; ks++) {
            // batch K-fragment loads, then mma stream
            u32 kf[4][4];
#pragma unroll
            for (int np = 0; np < 4; np++)
                ldsm_x4(kf[np][0], kf[np][1], kf[np][2], kf[np][3],
                        kBase + (u32)(np*16 + (g>>1)*8 + r8) * KV_ROWB
                              + (u32)(ks*16 + (g&1)*8) * 2);
#pragma unroll
            for (int np = 0; np < 4; np++) {
                mma_bf16(sfrag[2*np],   qf[ks], kf[np][0], kf[np][1]);
                mma_bf16(sfrag[2*np+1], qf[ks], kf[np][2], kf[np][3]);
            }
        }

        const float* msk = sMask + cur*64;
        float mx0 = -1e30f, mx1 = -1e30f;
#pragma unroll
        for (int nt = 0; nt < 8; nt++) {
            float2 am = *(const float2*)(msk + nt*8 + 2*qi);
            sfrag[nt][0] = fmaf(sfrag[nt][0], 0.125f, am.x);
            sfrag[nt][1] = fmaf(sfrag[nt][1], 0.125f, am.y);
            sfrag[nt][2] = fmaf(sfrag[nt][2], 0.125f, am.x);
            sfrag[nt][3] = fmaf(sfrag[nt][3], 0.125f, am.y);
            mx0 = fmaxf(mx0, fmaxf(sfrag[nt][0], sfrag[nt][1]));
            mx1 = fmaxf(mx1, fmaxf(sfrag[nt][2], sfrag[nt][3]));
        }
        mx0 = fmaxf(mx0, __shfl_xor_sync(~0u, mx0, 1));
        mx0 = fmaxf(mx0, __shfl_xor_sync(~0u, mx0, 2));
        mx1 = fmaxf(mx1, __shfl_xor_sync(~0u, mx1, 1));
        mx1 = fmaxf(mx1, __shfl_xor_sync(~0u, mx1, 2));
        float mnew0 = fmaxf(mrow0, mx0), mnew1 = fmaxf(mrow1, mx1);
        float cor0 = fexp(mrow0 - mnew0), cor1 = fexp(mrow1 - mnew1);
        mrow0 = mnew0; mrow1 = mnew1;
        float ps0 = 0.f, ps1 = 0.f;
#pragma unroll
        for (int nt = 0; nt < 8; nt++) {
            sfrag[nt][0] = fexp(sfrag[nt][0] - mnew0);
            sfrag[nt][1] = fexp(sfrag[nt][1] - mnew0);
            sfrag[nt][2] = fexp(sfrag[nt][2] - mnew1);
            sfrag[nt][3] = fexp(sfrag[nt][3] - mnew1);
            ps0 += sfrag[nt][0] + sfrag[nt][1];
            ps1 += sfrag[nt][2] + sfrag[nt][3];
        }
        ps0 += __shfl_xor_sync(~0u, ps0, 1);
        ps0 += __shfl_xor_sync(~0u, ps0, 2);
        ps1 += __shfl_xor_sync(~0u, ps1, 1);
        ps1 += __shfl_xor_sync(~0u, ps1, 2);
        lrow0 = lrow0 * cor0 + ps0;
        lrow1 = lrow1 * cor1 + ps1;
#pragma unroll
        for (int nt = 0; nt < 8; nt++) {
            ofrag[nt][0] *= cor0; ofrag[nt][1] *= cor0;
            ofrag[nt][2] *= cor1; ofrag[nt][3] *= cor1;
        }

        const u32 vBase = smb + SV_OFF + cur*KVTILE_B;
#pragma unroll
        for (int kk = 0; kk < 4; kk++) {
            u32 a[4];
            a[0] = pack_bf16(sfrag[2*kk][0],   sfrag[2*kk][1]);
            a[1] = pack_bf16(sfrag[2*kk][2],   sfrag[2*kk][3]);
            a[2] = pack_bf16(sfrag[2*kk+1][0], sfrag[2*kk+1][1]);
            a[3] = pack_bf16(sfrag[2*kk+1][2], sfrag[2*kk+1][3]);
            // batch V-fragment loads, then mma stream
            u32 vf[4][4];
#pragma unroll
            for (int dp = 0; dp < 4; dp++)
                ldsm_x4_t(vf[dp][0], vf[dp][1], vf[dp][2], vf[dp][3],
                          vBase + (u32)(kk*16 + r8 + (g&1)*8) * KV_ROWB
                                + (u32)(dp*16 + (g>>1)*8) * 2);
#pragma unroll
            for (int dp = 0; dp < 4; dp++) {
                mma_bf16(ofrag[2*dp],   a, vf[dp][0], vf[dp][1]);
                mma_bf16(ofrag[2*dp+1], a, vf[dp][2], vf[dp][3]);
            }
        }
        __syncthreads();
    }

    const float inv0 = 1.0f / lrow0, inv1 = 1.0f / lrow1;
    const int r0 = q0 + warp*16 + qd;
    const int r1 = r0 + 8;
    __nv_bfloat16* o0 = Out + (size_t)(b*T_ + r0) * C_ + h*D_ + 2*qi;
    __nv_bfloat16* o1 = Out + (size_t)(b*T_ + r1) * C_ + h*D_ + 2*qi;
#pragma unroll
    for (int nt = 0; nt < 8; nt++) {
        *(u32*)(o0 + nt*8) = pack_bf16(ofrag[nt][0]*inv0, ofrag[nt][1]*inv0);
        *(u32*)(o1 + nt*8) = pack_bf16(ofrag[nt][2]*inv1, ofrag[nt][3]*inv1);
    }
}

// ---------------- host launcher ----------------
extern "C" void kernel_launch(void* const* d_in, const int* in_sizes, int n_in,
                              void* d_out, int out_size)
{
    const float* x    = (const float*)d_in[0];
    const int*   mask = (const int*)  d_in[1];
    const float* ln1w = (const float*)d_in[2];
    const float* ln1b = (const float*)d_in[3];
    const float* ln2w = (const float*)d_in[4];
    const float* ln2b = (const float*)d_in[5];
    const float* qw   = (const float*)d_in[6];
    const float* qb   = (const float*)d_in[7];
    const float* kw   = (const float*)d_in[8];
    const float* kb   = (const float*)d_in[9];
    const float* vw   = (const float*)d_in[10];
    const float* vb   = (const float*)d_in[11];
    const float* ow   = (const float*)d_in[12];
    const float* ob   = (const float*)d_in[13];
    const float* f1w  = (const float*)d_in[14];
    const float* f1b  = (const float*)d_in[15];
    const float* f2w  = (const float*)d_in[16];
    const float* f2b  = (const float*)d_in[17];
    const float* gm1  = (const float*)d_in[18];
    const float* gm2  = (const float*)d_in[19];
    float* out = (float*)d_out;

    __nv_bfloat16 *b_h, *b_h2, *b_qkv, *b_att, *b_f1, *b_wqkv, *b_wo, *b_wf1, *b_wf2;
    float *b_x1, *b_bqkv;
    cudaGetSymbolAddress((void**)&b_h,    g_hb);
    cudaGetSymbolAddress((void**)&b_h2,   g_h2b);
    cudaGetSymbolAddress((void**)&b_qkv,  g_qkv);
    cudaGetSymbolAddress((void**)&b_att,  g_attb);
    cudaGetSymbolAddress((void**)&b_f1,   g_f1b);
    cudaGetSymbolAddress((void**)&b_x1,   g_x1);
    cudaGetSymbolAddress((void**)&b_wqkv, g_wqkv);
    cudaGetSymbolAddress((void**)&b_wo,   g_wo);
    cudaGetSymbolAddress((void**)&b_wf1,  g_wf1);
    cudaGetSymbolAddress((void**)&b_wf2,  g_wf2);
    cudaGetSymbolAddress((void**)&b_bqkv, g_bqkv);

    cudaFuncSetAttribute(attn_kernel,
                         cudaFuncAttributeMaxDynamicSharedMemorySize, ATTN_SMEM);
    cudaFuncSetAttribute(bgemm_kernel<0,1>,
                         cudaFuncAttributeMaxDynamicSharedMemorySize, GEMM_SMEM);
    cudaFuncSetAttribute(bgemm_kernel<1,0>,
                         cudaFuncAttributeMaxDynamicSharedMemorySize, GEMM_SMEM);
    cudaFuncSetAttribute(bgemm_kernel<2,1>,
                         cudaFuncAttributeMaxDynamicSharedMemorySize, GEMM_SMEM);

    cvt_qkv_kernel<<<1024, 256>>>(qw, kw, vw, qb, kb, vb);
    cvt3_kernel<<<2048, 256>>>(ow, f1w, f2w);

    dim3 gridQKV(C3 / 128, NTOK / 128);
    dim3 gridC  (C_ / 128, NTOK / 128);
    dim3 gridF  (DFF / 128, NTOK / 128);

    ln_kernel<<<NTOK, 256>>>(x, ln1w, ln1b, b_h);
    bgemm_kernel<0,1><<<gridQKV, 128, GEMM_SMEM>>>(b_h, b_wqkv, b_bqkv, nullptr, nullptr, b_qkv, NTOK, C3, C_);
    attn_kernel<<<dim3(T_/128, H_, B_), 256, ATTN_SMEM>>>(b_qkv, mask, b_att);
    bgemm_kernel<1,0><<<gridC, 128, GEMM_SMEM>>>(b_att, b_wo, ob, x, gm1, b_x1, NTOK, C_, C_);
    ln_kernel<<<NTOK, 256>>>(b_x1, ln2w, ln2b, b_h2);
    bgemm_kernel<2,1><<<gridF, 128, GEMM_SMEM>>>(b_h2, b_wf1, f1b, nullptr, nullptr, b_f1, NTOK, DFF, C_);
    bgemm_kernel<1,0><<<gridC, 128, GEMM_SMEM>>>(b_f1, b_wf2, f2b, b_x1, gm2, out, NTOK, C_, DFF);
}

// round 11
// speedup vs baseline: 1.1016x; 1.1016x over previous
#include <cuda_runtime.h>
#include <cuda_bf16.h>
#include <cstdint>
#include <math.h>

typedef unsigned int u32;

#define B_   2
#define T_   2048
#define C_   1024
#define H_   16
#define D_   64
#define NTOK (B_*T_)
#define DFF  4096
#define C3   (3*C_)

// ---------------- scratch (no allocation allowed) ----------------
__device__ __nv_bfloat16 g_hb  [NTOK*C_];
__device__ __nv_bfloat16 g_h2b [NTOK*C_];
__device__ __nv_bfloat16 g_qkv [NTOK*C3];
__device__ __nv_bfloat16 g_attb[NTOK*C_];
__device__ __nv_bfloat16 g_f1b [(size_t)NTOK*DFF];
__device__ float         g_x1  [NTOK*C_];
__device__ __nv_bfloat16 g_wqkv[C_*C3];
__device__ __nv_bfloat16 g_wo  [C_*C_];
__device__ __nv_bfloat16 g_wf1 [C_*DFF];
__device__ __nv_bfloat16 g_wf2 [DFF*C_];
__device__ float         g_bqkv[C3];

// ---------------- small helpers ----------------
__device__ __forceinline__ u32 pack_bf16(float x, float y) {
    __nv_bfloat162 t = __floats2bfloat162_rn(x, y);
    u32 r; memcpy(&r, &t, 4); return r;
}
__device__ __forceinline__ void cp16(u32 sdst, const void* gsrc) {
    asm volatile("cp.async.cg.shared.global [%0], [%1], 16;" :: "r"(sdst), "l"(gsrc));
}
__device__ __forceinline__ void cp_commit() { asm volatile("cp.async.commit_group;"); }
__device__ __forceinline__ void ldsm_x4(u32& r0, u32& r1, u32& r2, u32& r3, u32 addr) {
    asm volatile("ldmatrix.sync.aligned.m8n8.x4.shared.b16 {%0,%1,%2,%3},[%4];"
                 : "=r"(r0), "=r"(r1), "=r"(r2), "=r"(r3) : "r"(addr));
}
__device__ __forceinline__ void ldsm_x4_t(u32& r0, u32& r1, u32& r2, u32& r3, u32 addr) {
    asm volatile("ldmatrix.sync.aligned.m8n8.x4.trans.shared.b16 {%0,%1,%2,%3},[%4];"
                 : "=r"(r0), "=r"(r1), "=r"(r2), "=r"(r3) : "r"(addr));
}
__device__ __forceinline__ void mma_bf16(float* c, const u32* a, u32 b0, u32 b1) {
    asm volatile("mma.sync.aligned.m16n8k16.row.col.f32.bf16.bf16.f32 "
                 "{%0,%1,%2,%3},{%4,%5,%6,%7},{%8,%9},{%0,%1,%2,%3};"
                 : "+f"(c[0]), "+f"(c[1]), "+f"(c[2]), "+f"(c[3])
                 : "r"(a[0]), "r"(a[1]), "r"(a[2]), "r"(a[3]), "r"(b0), "r"(b1));
}
// FFMA-only exp (no MUFU).
__device__ __forceinline__ float fexp(float x) {
    x = fmaxf(x, -80.0f);
    float y = x * 1.4426950408889634f;
    float k = rintf(y);
    float t = (y - k) * 0.6931471805599453f;
    float p = fmaf(t, fmaf(t, fmaf(t, fmaf(t, fmaf(t, 8.3333333e-3f, 4.1666667e-2f),
                 0.16666667f), 0.5f), 1.0f), 1.0f);
    int ki = (int)k;
    return __int_as_float(__float_as_int(p) + (ki << 23));
}

// ---------------- weight conversion ----------------
__global__ void cvt_qkv_kernel(const float* __restrict__ qw, const float* __restrict__ kw,
                               const float* __restrict__ vw, const float* __restrict__ qb,
                               const float* __restrict__ kb, const float* __restrict__ vb)
{
    int gtid = blockIdx.x * blockDim.x + threadIdx.x;
    int stride = gridDim.x * blockDim.x;
    for (int i = gtid; i < C_*C_/4; i += stride) {
        int c = i / (C_/4), j = (i % (C_/4)) * 4;
        float4 q4 = *(const float4*)(qw + (size_t)c*C_ + j);
        float4 k4 = *(const float4*)(kw + (size_t)c*C_ + j);
        float4 v4 = *(const float4*)(vw + (size_t)c*C_ + j);
        *(uint2*)(g_wqkv + (size_t)c*C3 + j)        = make_uint2(pack_bf16(q4.x,q4.y), pack_bf16(q4.z,q4.w));
        *(uint2*)(g_wqkv + (size_t)c*C3 + C_ + j)   = make_uint2(pack_bf16(k4.x,k4.y), pack_bf16(k4.z,k4.w));
        *(uint2*)(g_wqkv + (size_t)c*C3 + 2*C_ + j) = make_uint2(pack_bf16(v4.x,v4.y), pack_bf16(v4.z,v4.w));
    }
    if (gtid < C_) {
        g_bqkv[gtid]        = qb[gtid];
        g_bqkv[C_ + gtid]   = kb[gtid];
        g_bqkv[2*C_ + gtid] = vb[gtid];
    }
}
// fused convert of O/FF1/FF2 weights (one launch)
__global__ void cvt3_kernel(const float* __restrict__ ow, const float* __restrict__ f1w,
                            const float* __restrict__ f2w)
{
    int gtid = blockIdx.x * blockDim.x + threadIdx.x;
    int stride = gridDim.x * blockDim.x;
    const int n_o  = C_*C_/4;
    const int n_f  = C_*DFF/4;
    for (int i = gtid; i < n_o; i += stride) {
        float4 s = *(const float4*)(ow + (size_t)i*4);
        *(uint2*)(g_wo + (size_t)i*4) = make_uint2(pack_bf16(s.x,s.y), pack_bf16(s.z,s.w));
    }
    for (int i = gtid; i < n_f; i += stride) {
        float4 s = *(const float4*)(f1w + (size_t)i*4);
        *(uint2*)(g_wf1 + (size_t)i*4) = make_uint2(pack_bf16(s.x,s.y), pack_bf16(s.z,s.w));
    }
    for (int i = gtid; i < n_f; i += stride) {
        float4 s = *(const float4*)(f2w + (size_t)i*4);
        *(uint2*)(g_wf2 + (size_t)i*4) = make_uint2(pack_bf16(s.x,s.y), pack_bf16(s.z,s.w));
    }
}

// ---------------- LayerNorm: fp32 in -> bf16 out ----------------
__global__ void __launch_bounds__(256) ln_kernel(const float* __restrict__ x,
                                                 const float* __restrict__ w,
                                                 const float* __restrict__ b,
                                                 __nv_bfloat16* __restrict__ y)
{
    __shared__ float red[8];
    int row = blockIdx.x, tid = threadIdx.x;
    const float* xr = x + (size_t)row * C_;
    float4 v = *(const float4*)(xr + 4*tid);

    float s = v.x + v.y + v.z + v.w;
#pragma unroll
    for (int o = 16; o > 0; o >>= 1) s += __shfl_xor_sync(~0u, s, o);
    if ((tid & 31) == 0) red[tid >> 5] = s;
    __syncthreads();
    if (tid < 32) {
        float t = (tid < 8) ? red[tid] : 0.f;
#pragma unroll
        for (int o = 4; o > 0; o >>= 1) t += __shfl_xor_sync(~0u, t, o);
        if (tid == 0) red[0] = t;
    }
    __syncthreads();
    float mu = red[0] * (1.0f / C_);
    __syncthreads();

    float dx = v.x-mu, dy = v.y-mu, dz = v.z-mu, dw = v.w-mu;
    float sq = dx*dx + dy*dy + dz*dz + dw*dw;
#pragma unroll
    for (int o = 16; o > 0; o >>= 1) sq += __shfl_xor_sync(~0u, sq, o);
    if ((tid & 31) == 0) red[tid >> 5] = sq;
    __syncthreads();
    if (tid < 32) {
        float t = (tid < 8) ? red[tid] : 0.f;
#pragma unroll
        for (int o = 4; o > 0; o >>= 1) t += __shfl_xor_sync(~0u, t, o);
        if (tid == 0) red[0] = t;
    }
    __syncthreads();
    float rs = rsqrtf(red[0] * (1.0f / C_) + 1e-5f);
    float4 w4 = *(const float4*)(w + 4*tid);
    float4 b4 = *(const float4*)(b + 4*tid);
    float o0 = dx*rs*w4.x + b4.x, o1 = dy*rs*w4.y + b4.y;
    float o2 = dz*rs*w4.z + b4.z, o3 = dw*rs*w4.w + b4.w;
    *(uint2*)(y + (size_t)row*C_ + 4*tid) = make_uint2(pack_bf16(o0,o1), pack_bf16(o2,o3));
}

// ---------------- GEMM 128x128x32, 4 warps, warp tile 64x64, 4-stage ----------------
#define GA_ROWB   80
#define GB_ROWB   272
#define GA_BYTES  (128*GA_ROWB)
#define GB_BYTES  (32*GB_ROWB)
#define STAGE_B   (GA_BYTES + GB_BYTES)
#define NSTAGE    4
#define GEMM_SMEM (NSTAGE*STAGE_B)

template<int MODE, int OBF>
__global__ void __launch_bounds__(128) bgemm_kernel(
    const __nv_bfloat16* __restrict__ A, const __nv_bfloat16* __restrict__ Bw,
    const float* __restrict__ bias,
    const float* __restrict__ resid, const float* __restrict__ gamma,
    void* __restrict__ CoutV, int M, int N, int K)
{
    extern __shared__ char gsm[];
    const u32 smb = (u32)__cvta_generic_to_shared(gsm);

    const int tid  = threadIdx.x;
    const int lane = tid & 31, warp = tid >> 5;
    const int warp_m = warp >> 1, warp_n = warp & 1;
    const int m_blk = blockIdx.y << 7, n_blk = blockIdx.x << 7;

    const int ar = tid >> 2, ac = tid & 3;
    const int br = tid >> 4, bc = tid & 15;
    const __nv_bfloat16* Ag = A  + (size_t)(m_blk + ar) * K + ac*8;
    const __nv_bfloat16* Bg = Bw + (size_t)br * N + n_blk + bc*8;
    const u32 dA0 = smb + ar*GA_ROWB + ac*16;
    const u32 dB0 = smb + GA_BYTES + br*GB_ROWB + bc*16;

    const int g  = lane >> 3;
    const int r8 = lane & 7;
    const u32 aAddr0 = smb + (u32)(warp_m*64 + r8 + (g&1)*8) * GA_ROWB + (u32)((g>>1)*16);
    const u32 bAddr0 = smb + GA_BYTES + (u32)(r8 + (g&1)*8) * GB_ROWB
                           + (u32)(warp_n*64 + (g>>1)*8) * 2;

    float acc[4][8][4];
#pragma unroll
    for (int mt = 0; mt < 4; mt++)
#pragma unroll
        for (int nt = 0; nt < 8; nt++)
#pragma unroll
            for (int i = 0; i < 4; i++) acc[mt][nt][i] = 0.f;

    const int nk = K >> 5;

    auto issue = [&](int kt) {
        const u32 sb = (kt & (NSTAGE-1)) * STAGE_B;
        const __nv_bfloat16* Ak = Ag + (kt << 5);
        const __nv_bfloat16* Bk = Bg + (size_t)(kt << 5) * N;
#pragma unroll
        for (int p = 0; p < 4; p++)
            cp16(dA0 + sb + p*32*GA_ROWB, Ak + (size_t)(p*32)*K);
#pragma unroll
        for (int p = 0; p < 4; p++)
            cp16(dB0 + sb + p*8*GB_ROWB,  Bk + (size_t)(p*8)*N);
        cp_commit();
    };

    issue(0);
    if (nk > 1) issue(1);
    if (nk > 2) issue(2);

    for (int kt = 0; kt < nk; kt++) {
        if      (kt + 2 < nk) asm volatile("cp.async.wait_group 2;");
        else if (kt + 1 < nk) asm volatile("cp.async.wait_group 1;");
        else                  asm volatile("cp.async.wait_group 0;");
        __syncthreads();

        if (kt + 3 < nk) issue(kt + 3);

        const u32 sb = (kt & (NSTAGE-1)) * STAGE_B;
        const u32 aB = aAddr0 + sb;
        const u32 bB = bAddr0 + sb;

        // ---- rotation pipeline: 1 ldsm in flight per 8-mma stream ----
        u32 af[2][4][4];   // A frags double-buffered across ks
        u32 bf[2][4];      // B frag double buffer across np
#pragma unroll
        for (int mt = 0; mt < 4; mt++)
            ldsm_x4(af[0][mt][0], af[0][mt][1], af[0][mt][2], af[0][mt][3],
                    aB + (u32)(mt*16) * GA_ROWB);
        ldsm_x4_t(bf[0][0], bf[0][1], bf[0][2], bf[0][3], bB);

#pragma unroll
        for (int ks = 0; ks < 2; ks++) {
#pragma unroll
            for (int np = 0; np < 4; np++) {
                const int cb = np & 1;
                if (np < 3) {
                    ldsm_x4_t(bf[cb^1][0], bf[cb^1][1], bf[cb^1][2], bf[cb^1][3],
                              bB + (u32)(ks*16) * GB_ROWB + (u32)((np+1)*32));
                } else if (ks == 0) {
#pragma unroll
                    for (int mt = 0; mt < 4; mt++)
                        ldsm_x4(af[1][mt][0], af[1][mt][1], af[1][mt][2], af[1][mt][3],
                                aB + (u32)(mt*16) * GA_ROWB + 32u);
                    ldsm_x4_t(bf[cb^1][0], bf[cb^1][1], bf[cb^1][2], bf[cb^1][3],
                              bB + (u32)(16) * GB_ROWB);
                }
#pragma unroll
                for (int mt = 0; mt < 4; mt++) {
                    mma_bf16(acc[mt][2*np],   af[ks][mt], bf[cb][0], bf[cb][1]);
                    mma_bf16(acc[mt][2*np+1], af[ks][mt], bf[cb][2], bf[cb][3]);
                }
            }
        }
    }

    const int rr = lane >> 2, cc = (lane & 3) << 1;
    const int row0 = m_blk + warp_m * 64;
    const int col0 = n_blk + warp_n * 64;
#pragma unroll
    for (int mt = 0; mt < 4; mt++) {
#pragma unroll
        for (int nt = 0; nt < 8; nt++) {
            const int col = col0 + nt * 8 + cc;
            float2 b2 = *(const float2*)(bias + col);
            float2 g2 = make_float2(0.f, 0.f);
            if (MODE == 1) g2 = *(const float2*)(gamma + col);
#pragma unroll
            for (int half = 0; half < 2; half++) {
                const int row = row0 + mt * 16 + rr + half * 8;
                const size_t off = (size_t)row * N + col;
                float v0 = acc[mt][nt][half*2 + 0] + b2.x;
                float v1 = acc[mt][nt][half*2 + 1] + b2.y;
                if (MODE == 1) {
                    float2 rv = *(const float2*)(resid + off);
                    v0 = rv.x + g2.x * v0;
                    v1 = rv.y + g2.y * v1;
                } else if (MODE == 2) {
                    v0 = 0.5f * v0 * (1.0f + erff(v0 * 0.70710678118654752f));
                    v1 = 0.5f * v1 * (1.0f + erff(v1 * 0.70710678118654752f));
                }
                if (OBF) *(u32*)((__nv_bfloat16*)CoutV + off) = pack_bf16(v0, v1);
                else     *(float2*)((float*)CoutV + off) = make_float2(v0, v1);
            }
        }
    }
}

// ---------------- Flash attention: 128 queries/CTA, 8 warps (round-9 form) ----------------
#define KV_ROWB  144
#define QTILE_B  (128*KV_ROWB)
#define KVTILE_B (64*KV_ROWB)
#define SQ_OFF   0
#define SK_OFF   (QTILE_B)
#define SV_OFF   (QTILE_B + 2*KVTILE_B)
#define SMSK_OFF (QTILE_B + 4*KVTILE_B)
#define ATTN_SMEM (SMSK_OFF + 2*64*4)

__device__ __forceinline__ void attn_issue_kv(const __nv_bfloat16* __restrict__ qkv,
                                              u32 smb, int buf, int kt, int b, int h, int tid)
{
    const __nv_bfloat16* gK = qkv + ((size_t)(b*T_) + kt*64) * C3 + C_ + h*D_;
    const __nv_bfloat16* gV = gK + C_;
    u32 dK = smb + SK_OFF + buf*KVTILE_B;
    u32 dV = smb + SV_OFF + buf*KVTILE_B;
#pragma unroll
    for (int k = 0; k < 2; k++) {
        int c = tid + k*256;
        int row = c >> 3, col16 = c & 7;
        cp16(dK + row*KV_ROWB + col16*16, gK + (size_t)row*C3 + col16*8);
        cp16(dV + row*KV_ROWB + col16*16, gV + (size_t)row*C3 + col16*8);
    }
}

__global__ void __launch_bounds__(256) attn_kernel(
    const __nv_bfloat16* __restrict__ qkv, const int* __restrict__ mask,
    __nv_bfloat16* __restrict__ Out)
{
    extern __shared__ char attn_sm[];
    u32 smb = (u32)__cvta_generic_to_shared(attn_sm);
    float* sMask = (float*)(attn_sm + SMSK_OFF);

    const int tid = threadIdx.x;
    const int lane = tid & 31, warp = tid >> 5;
    const int b = blockIdx.z, h = blockIdx.y;
    const int q0 = blockIdx.x << 7;
    const int g = lane >> 3, r8 = lane & 7;
    const int qd = lane >> 2, qi = lane & 3;

    {
        const __nv_bfloat16* gQ = qkv + ((size_t)(b*T_ + q0)) * C3 + h*D_;
#pragma unroll
        for (int k = 0; k < 4; k++) {
            int c = tid + k*256;
            int row = c >> 3, col16 = c & 7;
            cp16(smb + SQ_OFF + row*KV_ROWB + col16*16, gQ + (size_t)row*C3 + col16*8);
        }
        attn_issue_kv(qkv, smb, 0, 0, b, h, tid);
        if (tid < 64) sMask[tid] = mask[b*T_ + tid] ? 0.f : -1e30f;
        cp_commit();
    }

    float ofrag[8][4];
#pragma unroll
    for (int nt = 0; nt < 8; nt++)
#pragma unroll
        for (int i = 0; i < 4; i++) ofrag[nt][i] = 0.f;
    float mrow0 = -1e30f, mrow1 = -1e30f, lrow0 = 0.f, lrow1 = 0.f;
    u32 qf[4][4];

    const int NKT = T_ / 64;
    for (int kt = 0; kt < NKT; kt++) {
        const int cur = kt & 1;
        if (kt + 1 < NKT) {
            attn_issue_kv(qkv, smb, cur ^ 1, kt + 1, b, h, tid);
            if (tid < 64) sMask[(cur^1)*64 + tid] = mask[b*T_ + (kt+1)*64 + tid] ? 0.f : -1e30f;
            cp_commit();
            asm volatile("cp.async.wait_group 1;");
        } else {
            asm volatile("cp.async.wait_group 0;");
        }
        __syncthreads();

        if (kt == 0) {
#pragma unroll
            for (int ks = 0; ks < 4; ks++) {
                u32 addr = smb + SQ_OFF
                         + (u32)(warp*16 + r8 + (g&1)*8) * KV_ROWB
                         + (u32)(ks*16 + (g>>1)*8) * 2;
                ldsm_x4(qf[ks][0], qf[ks][1], qf[ks][2], qf[ks][3], addr);
            }
        }

        float sfrag[8][4];
#pragma unroll
        for (int nt = 0; nt < 8; nt++)
#pragma unroll
            for (int i = 0; i < 4; i++) sfrag[nt][i] = 0.f;
        const u32 kBase = smb + SK_OFF + cur*KVTILE_B;
#pragma unroll
        for (int ks = 0; ks < 4; ks++) {
#pragma unroll
            for (int np = 0; np < 4; np++) {
                u32 k0, k1, k2, k3;
                u32 addr = kBase + (u32)(np*16 + (g>>1)*8 + r8) * KV_ROWB
                                 + (u32)(ks*16 + (g&1)*8) * 2;
                ldsm_x4(k0, k1, k2, k3, addr);
                mma_bf16(sfrag[2*np],   qf[ks], k0, k1);
                mma_bf16(sfrag[2*np+1], qf[ks], k2, k3);
            }
        }

        const float* msk = sMask + cur*64;
        float mx0 = -1e30f, mx1 = -1e30f;
#pragma unroll
        for (int nt = 0; nt < 8; nt++) {
            float2 am = *(const float2*)(msk + nt*8 + 2*qi);
            sfrag[nt][0] = fmaf(sfrag[nt][0], 0.125f, am.x);
            sfrag[nt][1] = fmaf(sfrag[nt][1], 0.125f, am.y);
            sfrag[nt][2] = fmaf(sfrag[nt][2], 0.125f, am.x);
            sfrag[nt][3] = fmaf(sfrag[nt][3], 0.125f, am.y);
            mx0 = fmaxf(mx0, fmaxf(sfrag[nt][0], sfrag[nt][1]));
            mx1 = fmaxf(mx1, fmaxf(sfrag[nt][2], sfrag[nt][3]));
        }
        mx0 = fmaxf(mx0, __shfl_xor_sync(~0u, mx0, 1));
        mx0 = fmaxf(mx0, __shfl_xor_sync(~0u, mx0, 2));
        mx1 = fmaxf(mx1, __shfl_xor_sync(~0u, mx1, 1));
        mx1 = fmaxf(mx1, __shfl_xor_sync(~0u, mx1, 2));
        float mnew0 = fmaxf(mrow0, mx0), mnew1 = fmaxf(mrow1, mx1);
        float cor0 = fexp(mrow0 - mnew0), cor1 = fexp(mrow1 - mnew1);
        mrow0 = mnew0; mrow1 = mnew1;
        float ps0 = 0.f, ps1 = 0.f;
#pragma unroll
        for (int nt = 0; nt < 8; nt++) {
            sfrag[nt][0] = fexp(sfrag[nt][0] - mnew0);
            sfrag[nt][1] = fexp(sfrag[nt][1] - mnew0);
            sfrag[nt][2] = fexp(sfrag[nt][2] - mnew1);
            sfrag[nt][3] = fexp(sfrag[nt][3] - mnew1);
            ps0 += sfrag[nt][0] + sfrag[nt][1];
            ps1 += sfrag[nt][2] + sfrag[nt][3];
        }
        ps0 += __shfl_xor_sync(~0u, ps0, 1);
        ps0 += __shfl_xor_sync(~0u, ps0, 2);
        ps1 += __shfl_xor_sync(~0u, ps1, 1);
        ps1 += __shfl_xor_sync(~0u, ps1, 2);
        lrow0 = lrow0 * cor0 + ps0;
        lrow1 = lrow1 * cor1 + ps1;
#pragma unroll
        for (int nt = 0; nt < 8; nt++) {
            ofrag[nt][0] *= cor0; ofrag[nt][1] *= cor0;
            ofrag[nt][2] *= cor1; ofrag[nt][3] *= cor1;
        }

        const u32 vBase = smb + SV_OFF + cur*KVTILE_B;
#pragma unroll
        for (int kk = 0; kk < 4; kk++) {
            u32 a[4];
            a[0] = pack_bf16(sfrag[2*kk][0],   sfrag[2*kk][1]);
            a[1] = pack_bf16(sfrag[2*kk][2],   sfrag[2*kk][3]);
            a[2] = pack_bf16(sfrag[2*kk+1][0], sfrag[2*kk+1][1]);
            a[3] = pack_bf16(sfrag[2*kk+1][2], sfrag[2*kk+1][3]);
#pragma unroll
            for (int dp = 0; dp < 4; dp++) {
                u32 v0, v1, v2, v3;
                u32 addr = vBase + (u32)(kk*16 + r8 + (g&1)*8) * KV_ROWB
                                 + (u32)(dp*16 + (g>>1)*8) * 2;
                ldsm_x4_t(v0, v1, v2, v3, addr);
                mma_bf16(ofrag[2*dp],   a, v0, v1);
                mma_bf16(ofrag[2*dp+1], a, v2, v3);
            }
        }
        __syncthreads();
    }

    const float inv0 = 1.0f / lrow0, inv1 = 1.0f / lrow1;
    const int r0 = q0 + warp*16 + qd;
    const int r1 = r0 + 8;
    __nv_bfloat16* o0 = Out + (size_t)(b*T_ + r0) * C_ + h*D_ + 2*qi;
    __nv_bfloat16* o1 = Out + (size_t)(b*T_ + r1) * C_ + h*D_ + 2*qi;
#pragma unroll
    for (int nt = 0; nt < 8; nt++) {
        *(u32*)(o0 + nt*8) = pack_bf16(ofrag[nt][0]*inv0, ofrag[nt][1]*inv0);
        *(u32*)(o1 + nt*8) = pack_bf16(ofrag[nt][2]*inv1, ofrag[nt][3]*inv1);
    }
}

// ---------------- host launcher ----------------
extern "C" void kernel_launch(void* const* d_in, const int* in_sizes, int n_in,
                              void* d_out, int out_size)
{
    const float* x    = (const float*)d_in[0];
    const int*   mask = (const int*)  d_in[1];
    const float* ln1w = (const float*)d_in[2];
    const float* ln1b = (const float*)d_in[3];
    const float* ln2w = (const float*)d_in[4];
    const float* ln2b = (const float*)d_in[5];
    const float* qw   = (const float*)d_in[6];
    const float* qb   = (const float*)d_in[7];
    const float* kw   = (const float*)d_in[8];
    const float* kb   = (const float*)d_in[9];
    const float* vw   = (const float*)d_in[10];
    const float* vb   = (const float*)d_in[11];
    const float* ow   = (const float*)d_in[12];
    const float* ob   = (const float*)d_in[13];
    const float* f1w  = (const float*)d_in[14];
    const float* f1b  = (const float*)d_in[15];
    const float* f2w  = (const float*)d_in[16];
    const float* f2b  = (const float*)d_in[17];
    const float* gm1  = (const float*)d_in[18];
    const float* gm2  = (const float*)d_in[19];
    float* out = (float*)d_out;

    __nv_bfloat16 *b_h, *b_h2, *b_qkv, *b_att, *b_f1, *b_wqkv, *b_wo, *b_wf1, *b_wf2;
    float *b_x1, *b_bqkv;
    cudaGetSymbolAddress((void**)&b_h,    g_hb);
    cudaGetSymbolAddress((void**)&b_h2,   g_h2b);
    cudaGetSymbolAddress((void**)&b_qkv,  g_qkv);
    cudaGetSymbolAddress((void**)&b_att,  g_attb);
    cudaGetSymbolAddress((void**)&b_f1,   g_f1b);
    cudaGetSymbolAddress((void**)&b_x1,   g_x1);
    cudaGetSymbolAddress((void**)&b_wqkv, g_wqkv);
    cudaGetSymbolAddress((void**)&b_wo,   g_wo);
    cudaGetSymbolAddress((void**)&b_wf1,  g_wf1);
    cudaGetSymbolAddress((void**)&b_wf2,  g_wf2);
    cudaGetSymbolAddress((void**)&b_bqkv, g_bqkv);

    cudaFuncSetAttribute(attn_kernel,
                         cudaFuncAttributeMaxDynamicSharedMemorySize, ATTN_SMEM);
    cudaFuncSetAttribute(bgemm_kernel<0,1>,
                         cudaFuncAttributeMaxDynamicSharedMemorySize, GEMM_SMEM);
    cudaFuncSetAttribute(bgemm_kernel<1,0>,
                         cudaFuncAttributeMaxDynamicSharedMemorySize, GEMM_SMEM);
    cudaFuncSetAttribute(bgemm_kernel<2,1>,
                         cudaFuncAttributeMaxDynamicSharedMemorySize, GEMM_SMEM);

    cvt_qkv_kernel<<<1024, 256>>>(qw, kw, vw, qb, kb, vb);
    cvt3_kernel<<<2048, 256>>>(ow, f1w, f2w);

    dim3 gridQKV(C3 / 128, NTOK / 128);
    dim3 gridC  (C_ / 128, NTOK / 128);
    dim3 gridF  (DFF / 128, NTOK / 128);

    ln_kernel<<<NTOK, 256>>>(x, ln1w, ln1b, b_h);
    bgemm_kernel<0,1><<<gridQKV, 128, GEMM_SMEM>>>(b_h, b_wqkv, b_bqkv, nullptr, nullptr, b_qkv, NTOK, C3, C_);
    attn_kernel<<<dim3(T_/128, H_, B_), 256, ATTN_SMEM>>>(b_qkv, mask, b_att);
    bgemm_kernel<1,0><<<gridC, 128, GEMM_SMEM>>>(b_att, b_wo, ob, x, gm1, b_x1, NTOK, C_, C_);
    ln_kernel<<<NTOK, 256>>>(b_x1, ln2w, ln2b, b_h2);
    bgemm_kernel<2,1><<<gridF, 128, GEMM_SMEM>>>(b_h2, b_wf1, f1b, nullptr, nullptr, b_f1, NTOK, DFF, C_);
    bgemm_kernel<1,0><<<gridC, 128, GEMM_SMEM>>>(b_f1, b_wf2, f2b, b_x1, gm2, out, NTOK, C_, DFF);
}

// round 12
// speedup vs baseline: 1.1205x; 1.0171x over previous
#include <cuda_runtime.h>
#include <cuda_bf16.h>
#include <cstdint>
#include <math.h>

typedef unsigned int u32;

#define B_   2
#define T_   2048
#define C_   1024
#define H_   16
#define D_   64
#define NTOK (B_*T_)
#define DFF  4096
#define C3   (3*C_)

// ---------------- scratch (no allocation allowed) ----------------
__device__ __nv_bfloat16 g_hb  [NTOK*C_];
__device__ __nv_bfloat16 g_h2b [NTOK*C_];
__device__ __nv_bfloat16 g_qkv [NTOK*C3];
__device__ __nv_bfloat16 g_attb[NTOK*C_];
__device__ __nv_bfloat16 g_f1b [(size_t)NTOK*DFF];
__device__ float         g_x1  [NTOK*C_];
__device__ __nv_bfloat16 g_wqkv[C_*C3];
__device__ __nv_bfloat16 g_wo  [C_*C_];
__device__ __nv_bfloat16 g_wf1 [C_*DFF];
__device__ __nv_bfloat16 g_wf2 [DFF*C_];
__device__ float         g_bqkv[C3];

// ---------------- small helpers ----------------
__device__ __forceinline__ u32 pack_bf16(float x, float y) {
    __nv_bfloat162 t = __floats2bfloat162_rn(x, y);
    u32 r; memcpy(&r, &t, 4); return r;
}
__device__ __forceinline__ void cp16(u32 sdst, const void* gsrc) {
    asm volatile("cp.async.cg.shared.global [%0], [%1], 16;" :: "r"(sdst), "l"(gsrc));
}
__device__ __forceinline__ void cp_commit() { asm volatile("cp.async.commit_group;"); }
__device__ __forceinline__ void ldsm_x4(u32& r0, u32& r1, u32& r2, u32& r3, u32 addr) {
    asm volatile("ldmatrix.sync.aligned.m8n8.x4.shared.b16 {%0,%1,%2,%3},[%4];"
                 : "=r"(r0), "=r"(r1), "=r"(r2), "=r"(r3) : "r"(addr));
}
__device__ __forceinline__ void ldsm_x4_t(u32& r0, u32& r1, u32& r2, u32& r3, u32 addr) {
    asm volatile("ldmatrix.sync.aligned.m8n8.x4.trans.shared.b16 {%0,%1,%2,%3},[%4];"
                 : "=r"(r0), "=r"(r1), "=r"(r2), "=r"(r3) : "r"(addr));
}
__device__ __forceinline__ void mma_bf16(float* c, const u32* a, u32 b0, u32 b1) {
    asm volatile("mma.sync.aligned.m16n8k16.row.col.f32.bf16.bf16.f32 "
                 "{%0,%1,%2,%3},{%4,%5,%6,%7},{%8,%9},{%0,%1,%2,%3};"
                 : "+f"(c[0]), "+f"(c[1]), "+f"(c[2]), "+f"(c[3])
                 : "r"(a[0]), "r"(a[1]), "r"(a[2]), "r"(a[3]), "r"(b0), "r"(b1));
}
// FFMA-only exp (no MUFU).
__device__ __forceinline__ float fexp(float x) {
    x = fmaxf(x, -80.0f);
    float y = x * 1.4426950408889634f;
    float k = rintf(y);
    float t = (y - k) * 0.6931471805599453f;
    float p = fmaf(t, fmaf(t, fmaf(t, fmaf(t, fmaf(t, 8.3333333e-3f, 4.1666667e-2f),
                 0.16666667f), 0.5f), 1.0f), 1.0f);
    int ki = (int)k;
    return __int_as_float(__float_as_int(p) + (ki << 23));
}

// ---------------- weight conversion ----------------
__global__ void cvt_qkv_kernel(const float* __restrict__ qw, const float* __restrict__ kw,
                               const float* __restrict__ vw, const float* __restrict__ qb,
                               const float* __restrict__ kb, const float* __restrict__ vb)
{
    int gtid = blockIdx.x * blockDim.x + threadIdx.x;
    int stride = gridDim.x * blockDim.x;
    for (int i = gtid; i < C_*C_/4; i += stride) {
        int c = i / (C_/4), j = (i % (C_/4)) * 4;
        float4 q4 = *(const float4*)(qw + (size_t)c*C_ + j);
        float4 k4 = *(const float4*)(kw + (size_t)c*C_ + j);
        float4 v4 = *(const float4*)(vw + (size_t)c*C_ + j);
        *(uint2*)(g_wqkv + (size_t)c*C3 + j)        = make_uint2(pack_bf16(q4.x,q4.y), pack_bf16(q4.z,q4.w));
        *(uint2*)(g_wqkv + (size_t)c*C3 + C_ + j)   = make_uint2(pack_bf16(k4.x,k4.y), pack_bf16(k4.z,k4.w));
        *(uint2*)(g_wqkv + (size_t)c*C3 + 2*C_ + j) = make_uint2(pack_bf16(v4.x,v4.y), pack_bf16(v4.z,v4.w));
    }
    if (gtid < C_) {
        g_bqkv[gtid]        = qb[gtid];
        g_bqkv[C_ + gtid]   = kb[gtid];
        g_bqkv[2*C_ + gtid] = vb[gtid];
    }
}
// fused convert of O/FF1/FF2 weights (one launch)
__global__ void cvt3_kernel(const float* __restrict__ ow, const float* __restrict__ f1w,
                            const float* __restrict__ f2w)
{
    int gtid = blockIdx.x * blockDim.x + threadIdx.x;
    int stride = gridDim.x * blockDim.x;
    const int n_o  = C_*C_/4;
    const int n_f  = C_*DFF/4;
    for (int i = gtid; i < n_o; i += stride) {
        float4 s = *(const float4*)(ow + (size_t)i*4);
        *(uint2*)(g_wo + (size_t)i*4) = make_uint2(pack_bf16(s.x,s.y), pack_bf16(s.z,s.w));
    }
    for (int i = gtid; i < n_f; i += stride) {
        float4 s = *(const float4*)(f1w + (size_t)i*4);
        *(uint2*)(g_wf1 + (size_t)i*4) = make_uint2(pack_bf16(s.x,s.y), pack_bf16(s.z,s.w));
    }
    for (int i = gtid; i < n_f; i += stride) {
        float4 s = *(const float4*)(f2w + (size_t)i*4);
        *(uint2*)(g_wf2 + (size_t)i*4) = make_uint2(pack_bf16(s.x,s.y), pack_bf16(s.z,s.w));
    }
}

// ---------------- LayerNorm: fp32 in -> bf16 out ----------------
__global__ void __launch_bounds__(256) ln_kernel(const float* __restrict__ x,
                                                 const float* __restrict__ w,
                                                 const float* __restrict__ b,
                                                 __nv_bfloat16* __restrict__ y)
{
    __shared__ float red[8];
    int row = blockIdx.x, tid = threadIdx.x;
    const float* xr = x + (size_t)row * C_;
    float4 v = *(const float4*)(xr + 4*tid);

    float s = v.x + v.y + v.z + v.w;
#pragma unroll
    for (int o = 16; o > 0; o >>= 1) s += __shfl_xor_sync(~0u, s, o);
    if ((tid & 31) == 0) red[tid >> 5] = s;
    __syncthreads();
    if (tid < 32) {
        float t = (tid < 8) ? red[tid] : 0.f;
#pragma unroll
        for (int o = 4; o > 0; o >>= 1) t += __shfl_xor_sync(~0u, t, o);
        if (tid == 0) red[0] = t;
    }
    __syncthreads();
    float mu = red[0] * (1.0f / C_);
    __syncthreads();

    float dx = v.x-mu, dy = v.y-mu, dz = v.z-mu, dw = v.w-mu;
    float sq = dx*dx + dy*dy + dz*dz + dw*dw;
#pragma unroll
    for (int o = 16; o > 0; o >>= 1) sq += __shfl_xor_sync(~0u, sq, o);
    if ((tid & 31) == 0) red[tid >> 5] = sq;
    __syncthreads();
    if (tid < 32) {
        float t = (tid < 8) ? red[tid] : 0.f;
#pragma unroll
        for (int o = 4; o > 0; o >>= 1) t += __shfl_xor_sync(~0u, t, o);
        if (tid == 0) red[0] = t;
    }
    __syncthreads();
    float rs = rsqrtf(red[0] * (1.0f / C_) + 1e-5f);
    float4 w4 = *(const float4*)(w + 4*tid);
    float4 b4 = *(const float4*)(b + 4*tid);
    float o0 = dx*rs*w4.x + b4.x, o1 = dy*rs*w4.y + b4.y;
    float o2 = dz*rs*w4.z + b4.z, o3 = dw*rs*w4.w + b4.w;
    *(uint2*)(y + (size_t)row*C_ + 4*tid) = make_uint2(pack_bf16(o0,o1), pack_bf16(o2,o3));
}

// ---------------- GEMM 128x128x32, 4 warps, warp tile 64x64, 5-stage ----------------
#define GA_ROWB   80
#define GB_ROWB   272
#define GA_BYTES  (128*GA_ROWB)
#define GB_BYTES  (32*GB_ROWB)
#define STAGE_B   (GA_BYTES + GB_BYTES)
#define NSTAGE    5
#define GEMM_SMEM (NSTAGE*STAGE_B)      // 94720

template<int MODE, int OBF>
__global__ void __launch_bounds__(128) bgemm_kernel(
    const __nv_bfloat16* __restrict__ A, const __nv_bfloat16* __restrict__ Bw,
    const float* __restrict__ bias,
    const float* __restrict__ resid, const float* __restrict__ gamma,
    void* __restrict__ CoutV, int M, int N, int K)
{
    extern __shared__ char gsm[];
    const u32 smb = (u32)__cvta_generic_to_shared(gsm);

    const int tid  = threadIdx.x;
    const int lane = tid & 31, warp = tid >> 5;
    const int warp_m = warp >> 1, warp_n = warp & 1;
    const int m_blk = blockIdx.y << 7, n_blk = blockIdx.x << 7;

    const int ar = tid >> 2, ac = tid & 3;
    const int br = tid >> 4, bc = tid & 15;
    const __nv_bfloat16* Ag = A  + (size_t)(m_blk + ar) * K + ac*8;
    const __nv_bfloat16* Bg = Bw + (size_t)br * N + n_blk + bc*8;
    const u32 dA0 = smb + ar*GA_ROWB + ac*16;
    const u32 dB0 = smb + GA_BYTES + br*GB_ROWB + bc*16;

    const int g  = lane >> 3;
    const int r8 = lane & 7;
    const u32 aAddr0 = smb + (u32)(warp_m*64 + r8 + (g&1)*8) * GA_ROWB + (u32)((g>>1)*16);
    const u32 bAddr0 = smb + GA_BYTES + (u32)(r8 + (g&1)*8) * GB_ROWB
                           + (u32)(warp_n*64 + (g>>1)*8) * 2;

    float acc[4][8][4];
#pragma unroll
    for (int mt = 0; mt < 4; mt++)
#pragma unroll
        for (int nt = 0; nt < 8; nt++)
#pragma unroll
            for (int i = 0; i < 4; i++) acc[mt][nt][i] = 0.f;

    const int nk = K >> 5;

    auto issue = [&](int kt) {
        const u32 sb = (kt % NSTAGE) * STAGE_B;
        const __nv_bfloat16* Ak = Ag + (kt << 5);
        const __nv_bfloat16* Bk = Bg + (size_t)(kt << 5) * N;
#pragma unroll
        for (int p = 0; p < 4; p++)
            cp16(dA0 + sb + p*32*GA_ROWB, Ak + (size_t)(p*32)*K);
#pragma unroll
        for (int p = 0; p < 4; p++)
            cp16(dB0 + sb + p*8*GB_ROWB,  Bk + (size_t)(p*8)*N);
        cp_commit();
    };

    issue(0);
    if (nk > 1) issue(1);
    if (nk > 2) issue(2);
    if (nk > 3) issue(3);

    for (int kt = 0; kt < nk; kt++) {
        if      (kt + 3 < nk) asm volatile("cp.async.wait_group 3;");
        else if (kt + 2 < nk) asm volatile("cp.async.wait_group 2;");
        else if (kt + 1 < nk) asm volatile("cp.async.wait_group 1;");
        else                  asm volatile("cp.async.wait_group 0;");
        __syncthreads();   // stage (kt+4)%5 was consumed in iter kt-1

        if (kt + 4 < nk) issue(kt + 4);

        const u32 sb = (kt % NSTAGE) * STAGE_B;
        const u32 aB = aAddr0 + sb;
        const u32 bB = bAddr0 + sb;
#pragma unroll
        for (int ks = 0; ks < 2; ks++) {
            u32 af[4][4];
#pragma unroll
            for (int mt = 0; mt < 4; mt++)
                ldsm_x4(af[mt][0], af[mt][1], af[mt][2], af[mt][3],
                        aB + (u32)(mt*16) * GA_ROWB + (u32)(ks*32));
#pragma unroll
            for (int np = 0; np < 4; np++) {
                u32 b0, b1, b2, b3;
                ldsm_x4_t(b0, b1, b2, b3,
                          bB + (u32)(ks*16) * GB_ROWB + (u32)(np*32));
#pragma unroll
                for (int mt = 0; mt < 4; mt++) {
                    mma_bf16(acc[mt][2*np],   af[mt], b0, b1);
                    mma_bf16(acc[mt][2*np+1], af[mt], b2, b3);
                }
            }
        }
    }

    const int rr = lane >> 2, cc = (lane & 3) << 1;
    const int row0 = m_blk + warp_m * 64;
    const int col0 = n_blk + warp_n * 64;
#pragma unroll
    for (int mt = 0; mt < 4; mt++) {
#pragma unroll
        for (int nt = 0; nt < 8; nt++) {
            const int col = col0 + nt * 8 + cc;
            float2 b2 = *(const float2*)(bias + col);
            float2 g2 = make_float2(0.f, 0.f);
            if (MODE == 1) g2 = *(const float2*)(gamma + col);
#pragma unroll
            for (int half = 0; half < 2; half++) {
                const int row = row0 + mt * 16 + rr + half * 8;
                const size_t off = (size_t)row * N + col;
                float v0 = acc[mt][nt][half*2 + 0] + b2.x;
                float v1 = acc[mt][nt][half*2 + 1] + b2.y;
                if (MODE == 1) {
                    float2 rv = *(const float2*)(resid + off);
                    v0 = rv.x + g2.x * v0;
                    v1 = rv.y + g2.y * v1;
                } else if (MODE == 2) {
                    v0 = 0.5f * v0 * (1.0f + erff(v0 * 0.70710678118654752f));
                    v1 = 0.5f * v1 * (1.0f + erff(v1 * 0.70710678118654752f));
                }
                if (OBF) *(u32*)((__nv_bfloat16*)CoutV + off) = pack_bf16(v0, v1);
                else     *(float2*)((float*)CoutV + off) = make_float2(v0, v1);
            }
        }
    }
}

// ---------------- Flash attention: 128 queries/CTA, 8 warps ----------------
#define KV_ROWB  144
#define QTILE_B  (128*KV_ROWB)
#define KVTILE_B (64*KV_ROWB)
#define SQ_OFF   0
#define SK_OFF   (QTILE_B)
#define SV_OFF   (QTILE_B + 2*KVTILE_B)
#define SMSK_OFF (QTILE_B + 4*KVTILE_B)
#define ATTN_SMEM (SMSK_OFF + 2*64*4)

__device__ __forceinline__ void attn_issue_kv(const __nv_bfloat16* __restrict__ qkv,
                                              u32 smb, int buf, int kt, int b, int h, int tid)
{
    const __nv_bfloat16* gK = qkv + ((size_t)(b*T_) + kt*64) * C3 + C_ + h*D_;
    const __nv_bfloat16* gV = gK + C_;
    u32 dK = smb + SK_OFF + buf*KVTILE_B;
    u32 dV = smb + SV_OFF + buf*KVTILE_B;
#pragma unroll
    for (int k = 0; k < 2; k++) {
        int c = tid + k*256;
        int row = c >> 3, col16 = c & 7;
        cp16(dK + row*KV_ROWB + col16*16, gK + (size_t)row*C3 + col16*8);
        cp16(dV + row*KV_ROWB + col16*16, gV + (size_t)row*C3 + col16*8);
    }
}

__global__ void __launch_bounds__(256) attn_kernel(
    const __nv_bfloat16* __restrict__ qkv, const int* __restrict__ mask,
    __nv_bfloat16* __restrict__ Out)
{
    extern __shared__ char attn_sm[];
    u32 smb = (u32)__cvta_generic_to_shared(attn_sm);
    float* sMask = (float*)(attn_sm + SMSK_OFF);

    const int tid = threadIdx.x;
    const int lane = tid & 31, warp = tid >> 5;
    const int b = blockIdx.z, h = blockIdx.y;
    const int q0 = blockIdx.x << 7;
    const int g = lane >> 3, r8 = lane & 7;
    const int qd = lane >> 2, qi = lane & 3;

    {
        const __nv_bfloat16* gQ = qkv + ((size_t)(b*T_ + q0)) * C3 + h*D_;
#pragma unroll
        for (int k = 0; k < 4; k++) {
            int c = tid + k*256;
            int row = c >> 3, col16 = c & 7;
            cp16(smb + SQ_OFF + row*KV_ROWB + col16*16, gQ + (size_t)row*C3 + col16*8);
        }
        attn_issue_kv(qkv, smb, 0, 0, b, h, tid);
        if (tid < 64) sMask[tid] = mask[b*T_ + tid] ? 0.f : -1e30f;
        cp_commit();
    }

    float ofrag[8][4];
#pragma unroll
    for (int nt = 0; nt < 8; nt++)
#pragma unroll
        for (int i = 0; i < 4; i++) ofrag[nt][i] = 0.f;
    float mrow0 = -1e30f, mrow1 = -1e30f, lrow0 = 0.f, lrow1 = 0.f;
    u32 qf[4][4];

    const int NKT = T_ / 64;
    for (int kt = 0; kt < NKT; kt++) {
        const int cur = kt & 1;
        if (kt + 1 < NKT) {
            attn_issue_kv(qkv, smb, cur ^ 1, kt + 1, b, h, tid);
            if (tid < 64) sMask[(cur^1)*64 + tid] = mask[b*T_ + (kt+1)*64 + tid] ? 0.f : -1e30f;
            cp_commit();
            asm volatile("cp.async.wait_group 1;");
        } else {
            asm volatile("cp.async.wait_group 0;");
        }
        __syncthreads();

        if (kt == 0) {
#pragma unroll
            for (int ks = 0; ks < 4; ks++) {
                u32 addr = smb + SQ_OFF
                         + (u32)(warp*16 + r8 + (g&1)*8) * KV_ROWB
                         + (u32)(ks*16 + (g>>1)*8) * 2;
                ldsm_x4(qf[ks][0], qf[ks][1], qf[ks][2], qf[ks][3], addr);
            }
        }

        float sfrag[8][4];
#pragma unroll
        for (int nt = 0; nt < 8; nt++)
#pragma unroll
            for (int i = 0; i < 4; i++) sfrag[nt][i] = 0.f;
        const u32 kBase = smb + SK_OFF + cur*KVTILE_B;
#pragma unroll
        for (int ks = 0; ks < 4; ks++) {
#pragma unroll
            for (int np = 0; np < 4; np++) {
                u32 k0, k1, k2, k3;
                u32 addr = kBase + (u32)(np*16 + (g>>1)*8 + r8) * KV_ROWB
                                 + (u32)(ks*16 + (g&1)*8) * 2;
                ldsm_x4(k0, k1, k2, k3, addr);
                mma_bf16(sfrag[2*np],   qf[ks], k0, k1);
                mma_bf16(sfrag[2*np+1], qf[ks], k2, k3);
            }
        }

        const float* msk = sMask + cur*64;
        float mx0 = -1e30f, mx1 = -1e30f;
#pragma unroll
        for (int nt = 0; nt < 8; nt++) {
            float2 am = *(const float2*)(msk + nt*8 + 2*qi);
            sfrag[nt][0] = fmaf(sfrag[nt][0], 0.125f, am.x);
            sfrag[nt][1] = fmaf(sfrag[nt][1], 0.125f, am.y);
            sfrag[nt][2] = fmaf(sfrag[nt][2], 0.125f, am.x);
            sfrag[nt][3] = fmaf(sfrag[nt][3], 0.125f, am.y);
            mx0 = fmaxf(mx0, fmaxf(sfrag[nt][0], sfrag[nt][1]));
            mx1 = fmaxf(mx1, fmaxf(sfrag[nt][2], sfrag[nt][3]));
        }
        mx0 = fmaxf(mx0, __shfl_xor_sync(~0u, mx0, 1));
        mx0 = fmaxf(mx0, __shfl_xor_sync(~0u, mx0, 2));
        mx1 = fmaxf(mx1, __shfl_xor_sync(~0u, mx1, 1));
        mx1 = fmaxf(mx1, __shfl_xor_sync(~0u, mx1, 2));
        float mnew0 = fmaxf(mrow0, mx0), mnew1 = fmaxf(mrow1, mx1);
        float cor0 = fexp(mrow0 - mnew0), cor1 = fexp(mrow1 - mnew1);
        mrow0 = mnew0; mrow1 = mnew1;
        float ps0 = 0.f, ps1 = 0.f;
#pragma unroll
        for (int nt = 0; nt < 8; nt++) {
            sfrag[nt][0] = fexp(sfrag[nt][0] - mnew0);
            sfrag[nt][1] = fexp(sfrag[nt][1] - mnew0);
            sfrag[nt][2] = fexp(sfrag[nt][2] - mnew1);
            sfrag[nt][3] = fexp(sfrag[nt][3] - mnew1);
            ps0 += sfrag[nt][0] + sfrag[nt][1];
            ps1 += sfrag[nt][2] + sfrag[nt][3];
        }
        ps0 += __shfl_xor_sync(~0u, ps0, 1);
        ps0 += __shfl_xor_sync(~0u, ps0, 2);
        ps1 += __shfl_xor_sync(~0u, ps1, 1);
        ps1 += __shfl_xor_sync(~0u, ps1, 2);
        lrow0 = lrow0 * cor0 + ps0;
        lrow1 = lrow1 * cor1 + ps1;
#pragma unroll
        for (int nt = 0; nt < 8; nt++) {
            ofrag[nt][0] *= cor0; ofrag[nt][1] *= cor0;
            ofrag[nt][2] *= cor1; ofrag[nt][3] *= cor1;
        }

        const u32 vBase = smb + SV_OFF + cur*KVTILE_B;
#pragma unroll
        for (int kk = 0; kk < 4; kk++) {
            u32 a[4];
            a[0] = pack_bf16(sfrag[2*kk][0],   sfrag[2*kk][1]);
            a[1] = pack_bf16(sfrag[2*kk][2],   sfrag[2*kk][3]);
            a[2] = pack_bf16(sfrag[2*kk+1][0], sfrag[2*kk+1][1]);
            a[3] = pack_bf16(sfrag[2*kk+1][2], sfrag[2*kk+1][3]);
#pragma unroll
            for (int dp = 0; dp < 4; dp++) {
                u32 v0, v1, v2, v3;
                u32 addr = vBase + (u32)(kk*16 + r8 + (g&1)*8) * KV_ROWB
                                 + (u32)(dp*16 + (g>>1)*8) * 2;
                ldsm_x4_t(v0, v1, v2, v3, addr);
                mma_bf16(ofrag[2*dp],   a, v0, v1);
                mma_bf16(ofrag[2*dp+1], a, v2, v3);
            }
        }
        __syncthreads();
    }

    const float inv0 = 1.0f / lrow0, inv1 = 1.0f / lrow1;
    const int r0 = q0 + warp*16 + qd;
    const int r1 = r0 + 8;
    __nv_bfloat16* o0 = Out + (size_t)(b*T_ + r0) * C_ + h*D_ + 2*qi;
    __nv_bfloat16* o1 = Out + (size_t)(b*T_ + r1) * C_ + h*D_ + 2*qi;
#pragma unroll
    for (int nt = 0; nt < 8; nt++) {
        *(u32*)(o0 + nt*8) = pack_bf16(ofrag[nt][0]*inv0, ofrag[nt][1]*inv0);
        *(u32*)(o1 + nt*8) = pack_bf16(ofrag[nt][2]*inv1, ofrag[nt][3]*inv1);
    }
}

// ---------------- host launcher ----------------
extern "C" void kernel_launch(void* const* d_in, const int* in_sizes, int n_in,
                              void* d_out, int out_size)
{
    const float* x    = (const float*)d_in[0];
    const int*   mask = (const int*)  d_in[1];
    const float* ln1w = (const float*)d_in[2];
    const float* ln1b = (const float*)d_in[3];
    const float* ln2w = (const float*)d_in[4];
    const float* ln2b = (const float*)d_in[5];
    const float* qw   = (const float*)d_in[6];
    const float* qb   = (const float*)d_in[7];
    const float* kw   = (const float*)d_in[8];
    const float* kb   = (const float*)d_in[9];
    const float* vw   = (const float*)d_in[10];
    const float* vb   = (const float*)d_in[11];
    const float* ow   = (const float*)d_in[12];
    const float* ob   = (const float*)d_in[13];
    const float* f1w  = (const float*)d_in[14];
    const float* f1b  = (const float*)d_in[15];
    const float* f2w  = (const float*)d_in[16];
    const float* f2b  = (const float*)d_in[17];
    const float* gm1  = (const float*)d_in[18];
    const float* gm2  = (const float*)d_in[19];
    float* out = (float*)d_out;

    __nv_bfloat16 *b_h, *b_h2, *b_qkv, *b_att, *b_f1, *b_wqkv, *b_wo, *b_wf1, *b_wf2;
    float *b_x1, *b_bqkv;
    cudaGetSymbolAddress((void**)&b_h,    g_hb);
    cudaGetSymbolAddress((void**)&b_h2,   g_h2b);
    cudaGetSymbolAddress((void**)&b_qkv,  g_qkv);
    cudaGetSymbolAddress((void**)&b_att,  g_attb);
    cudaGetSymbolAddress((void**)&b_f1,   g_f1b);
    cudaGetSymbolAddress((void**)&b_x1,   g_x1);
    cudaGetSymbolAddress((void**)&b_wqkv, g_wqkv);
    cudaGetSymbolAddress((void**)&b_wo,   g_wo);
    cudaGetSymbolAddress((void**)&b_wf1,  g_wf1);
    cudaGetSymbolAddress((void**)&b_wf2,  g_wf2);
    cudaGetSymbolAddress((void**)&b_bqkv, g_bqkv);

    cudaFuncSetAttribute(attn_kernel,
                         cudaFuncAttributeMaxDynamicSharedMemorySize, ATTN_SMEM);
    cudaFuncSetAttribute(bgemm_kernel<0,1>,
                         cudaFuncAttributeMaxDynamicSharedMemorySize, GEMM_SMEM);
    cudaFuncSetAttribute(bgemm_kernel<1,0>,
                         cudaFuncAttributeMaxDynamicSharedMemorySize, GEMM_SMEM);
    cudaFuncSetAttribute(bgemm_kernel<2,1>,
                         cudaFuncAttributeMaxDynamicSharedMemorySize, GEMM_SMEM);

    cvt_qkv_kernel<<<1024, 256>>>(qw, kw, vw, qb, kb, vb);
    cvt3_kernel<<<2048, 256>>>(ow, f1w, f2w);

    dim3 gridQKV(C3 / 128, NTOK / 128);
    dim3 gridC  (C_ / 128, NTOK / 128);
    dim3 gridF  (DFF / 128, NTOK / 128);

    ln_kernel<<<NTOK, 256>>>(x, ln1w, ln1b, b_h);
    bgemm_kernel<0,1><<<gridQKV, 128, GEMM_SMEM>>>(b_h, b_wqkv, b_bqkv, nullptr, nullptr, b_qkv, NTOK, C3, C_);
    attn_kernel<<<dim3(T_/128, H_, B_), 256, ATTN_SMEM>>>(b_qkv, mask, b_att);
    bgemm_kernel<1,0><<<gridC, 128, GEMM_SMEM>>>(b_att, b_wo, ob, x, gm1, b_x1, NTOK, C_, C_);
    ln_kernel<<<NTOK, 256>>>(b_x1, ln2w, ln2b, b_h2);
    bgemm_kernel<2,1><<<gridF, 128, GEMM_SMEM>>>(b_h2, b_wf1, f1b, nullptr, nullptr, b_f1, NTOK, DFF, C_);
    bgemm_kernel<1,0><<<gridC, 128, GEMM_SMEM>>>(b_f1, b_wf2, f2b, b_x1, gm2, out, NTOK, C_, DFF);
}

// round 13
// speedup vs baseline: 1.2316x; 1.0991x over previous
#include <cuda_runtime.h>
#include <cuda_bf16.h>
#include <cstdint>
#include <math.h>

typedef unsigned int u32;

#define B_   2
#define T_   2048
#define C_   1024
#define H_   16
#define D_   64
#define NTOK (B_*T_)
#define DFF  4096
#define C3   (3*C_)

// ---------------- scratch (no allocation allowed) ----------------
__device__ __nv_bfloat16 g_hb  [NTOK*C_];
__device__ __nv_bfloat16 g_h2b [NTOK*C_];
__device__ __nv_bfloat16 g_qkv [NTOK*C3];
__device__ __nv_bfloat16 g_attb[NTOK*C_];
__device__ __nv_bfloat16 g_f1b [(size_t)NTOK*DFF];
__device__ float         g_x1  [NTOK*C_];
__device__ __nv_bfloat16 g_wqkv[C_*C3];
__device__ __nv_bfloat16 g_wo  [C_*C_];
__device__ __nv_bfloat16 g_wf1 [C_*DFF];
__device__ __nv_bfloat16 g_wf2 [DFF*C_];
__device__ float         g_bqkv[C3];

// ---------------- small helpers ----------------
__device__ __forceinline__ u32 pack_bf16(float x, float y) {
    __nv_bfloat162 t = __floats2bfloat162_rn(x, y);
    u32 r; memcpy(&r, &t, 4); return r;
}
__device__ __forceinline__ void cp16(u32 sdst, const void* gsrc) {
    asm volatile("cp.async.cg.shared.global [%0], [%1], 16;" :: "r"(sdst), "l"(gsrc));
}
__device__ __forceinline__ void cp_commit() { asm volatile("cp.async.commit_group;"); }
__device__ __forceinline__ void ldsm_x4(u32& r0, u32& r1, u32& r2, u32& r3, u32 addr) {
    asm volatile("ldmatrix.sync.aligned.m8n8.x4.shared.b16 {%0,%1,%2,%3},[%4];"
                 : "=r"(r0), "=r"(r1), "=r"(r2), "=r"(r3) : "r"(addr));
}
__device__ __forceinline__ void ldsm_x4_t(u32& r0, u32& r1, u32& r2, u32& r3, u32 addr) {
    asm volatile("ldmatrix.sync.aligned.m8n8.x4.trans.shared.b16 {%0,%1,%2,%3},[%4];"
                 : "=r"(r0), "=r"(r1), "=r"(r2), "=r"(r3) : "r"(addr));
}
__device__ __forceinline__ void mma_bf16(float* c, const u32* a, u32 b0, u32 b1) {
    asm volatile("mma.sync.aligned.m16n8k16.row.col.f32.bf16.bf16.f32 "
                 "{%0,%1,%2,%3},{%4,%5,%6,%7},{%8,%9},{%0,%1,%2,%3};"
                 : "+f"(c[0]), "+f"(c[1]), "+f"(c[2]), "+f"(c[3])
                 : "r"(a[0]), "r"(a[1]), "r"(a[2]), "r"(a[3]), "r"(b0), "r"(b1));
}
// FFMA-only exp (no MUFU).
__device__ __forceinline__ float fexp(float x) {
    x = fmaxf(x, -80.0f);
    float y = x * 1.4426950408889634f;
    float k = rintf(y);
    float t = (y - k) * 0.6931471805599453f;
    float p = fmaf(t, fmaf(t, fmaf(t, fmaf(t, fmaf(t, 8.3333333e-3f, 4.1666667e-2f),
                 0.16666667f), 0.5f), 1.0f), 1.0f);
    int ki = (int)k;
    return __int_as_float(__float_as_int(p) + (ki << 23));
}

// ---------------- single fused weight conversion ----------------
__global__ void cvt_all_kernel(const float* __restrict__ qw, const float* __restrict__ kw,
                               const float* __restrict__ vw, const float* __restrict__ qb,
                               const float* __restrict__ kb, const float* __restrict__ vb,
                               const float* __restrict__ ow, const float* __restrict__ f1w,
                               const float* __restrict__ f2w)
{
    int gtid = blockIdx.x * blockDim.x + threadIdx.x;
    int stride = gridDim.x * blockDim.x;
    const int n_qkv = C_*C_/4;
    const int n_o   = C_*C_/4;
    const int n_f   = C_*DFF/4;
    for (int i = gtid; i < n_qkv; i += stride) {
        int c = i / (C_/4), j = (i % (C_/4)) * 4;
        float4 q4 = *(const float4*)(qw + (size_t)c*C_ + j);
        float4 k4 = *(const float4*)(kw + (size_t)c*C_ + j);
        float4 v4 = *(const float4*)(vw + (size_t)c*C_ + j);
        *(uint2*)(g_wqkv + (size_t)c*C3 + j)        = make_uint2(pack_bf16(q4.x,q4.y), pack_bf16(q4.z,q4.w));
        *(uint2*)(g_wqkv + (size_t)c*C3 + C_ + j)   = make_uint2(pack_bf16(k4.x,k4.y), pack_bf16(k4.z,k4.w));
        *(uint2*)(g_wqkv + (size_t)c*C3 + 2*C_ + j) = make_uint2(pack_bf16(v4.x,v4.y), pack_bf16(v4.z,v4.w));
    }
    for (int i = gtid; i < n_o; i += stride) {
        float4 s = *(const float4*)(ow + (size_t)i*4);
        *(uint2*)(g_wo + (size_t)i*4) = make_uint2(pack_bf16(s.x,s.y), pack_bf16(s.z,s.w));
    }
    for (int i = gtid; i < n_f; i += stride) {
        float4 s = *(const float4*)(f1w + (size_t)i*4);
        *(uint2*)(g_wf1 + (size_t)i*4) = make_uint2(pack_bf16(s.x,s.y), pack_bf16(s.z,s.w));
    }
    for (int i = gtid; i < n_f; i += stride) {
        float4 s = *(const float4*)(f2w + (size_t)i*4);
        *(uint2*)(g_wf2 + (size_t)i*4) = make_uint2(pack_bf16(s.x,s.y), pack_bf16(s.z,s.w));
    }
    if (gtid < C_) {
        g_bqkv[gtid]        = qb[gtid];
        g_bqkv[C_ + gtid]   = kb[gtid];
        g_bqkv[2*C_ + gtid] = vb[gtid];
    }
}

// ---------------- LayerNorm: fp32 in -> bf16 out ----------------
__global__ void __launch_bounds__(256) ln_kernel(const float* __restrict__ x,
                                                 const float* __restrict__ w,
                                                 const float* __restrict__ b,
                                                 __nv_bfloat16* __restrict__ y)
{
    __shared__ float red[8];
    int row = blockIdx.x, tid = threadIdx.x;
    const float* xr = x + (size_t)row * C_;
    float4 v = *(const float4*)(xr + 4*tid);

    float s = v.x + v.y + v.z + v.w;
#pragma unroll
    for (int o = 16; o > 0; o >>= 1) s += __shfl_xor_sync(~0u, s, o);
    if ((tid & 31) == 0) red[tid >> 5] = s;
    __syncthreads();
    if (tid < 32) {
        float t = (tid < 8) ? red[tid] : 0.f;
#pragma unroll
        for (int o = 4; o > 0; o >>= 1) t += __shfl_xor_sync(~0u, t, o);
        if (tid == 0) red[0] = t;
    }
    __syncthreads();
    float mu = red[0] * (1.0f / C_);
    __syncthreads();

    float dx = v.x-mu, dy = v.y-mu, dz = v.z-mu, dw = v.w-mu;
    float sq = dx*dx + dy*dy + dz*dz + dw*dw;
#pragma unroll
    for (int o = 16; o > 0; o >>= 1) sq += __shfl_xor_sync(~0u, sq, o);
    if ((tid & 31) == 0) red[tid >> 5] = sq;
    __syncthreads();
    if (tid < 32) {
        float t = (tid < 8) ? red[tid] : 0.f;
#pragma unroll
        for (int o = 4; o > 0; o >>= 1) t += __shfl_xor_sync(~0u, t, o);
        if (tid == 0) red[0] = t;
    }
    __syncthreads();
    float rs = rsqrtf(red[0] * (1.0f / C_) + 1e-5f);
    float4 w4 = *(const float4*)(w + 4*tid);
    float4 b4 = *(const float4*)(b + 4*tid);
    float o0 = dx*rs*w4.x + b4.x, o1 = dy*rs*w4.y + b4.y;
    float o2 = dz*rs*w4.z + b4.z, o3 = dw*rs*w4.w + b4.w;
    *(uint2*)(y + (size_t)row*C_ + 4*tid) = make_uint2(pack_bf16(o0,o1), pack_bf16(o2,o3));
}

// ---------------- GEMM 128x128x32, 4 warps, warp tile 64x64, 4-stage ----------------
#define GA_ROWB   80
#define GB_ROWB   272
#define GA_BYTES  (128*GA_ROWB)
#define GB_BYTES  (32*GB_ROWB)
#define STAGE_B   (GA_BYTES + GB_BYTES)
#define NSTAGE    4
#define GEMM_SMEM (NSTAGE*STAGE_B)

template<int MODE, int OBF>
__global__ void __launch_bounds__(128) bgemm_kernel(
    const __nv_bfloat16* __restrict__ A, const __nv_bfloat16* __restrict__ Bw,
    const float* __restrict__ bias,
    const float* __restrict__ resid, const float* __restrict__ gamma,
    void* __restrict__ CoutV, int M, int N, int K)
{
    extern __shared__ char gsm[];
    const u32 smb = (u32)__cvta_generic_to_shared(gsm);

    const int tid  = threadIdx.x;
    const int lane = tid & 31, warp = tid >> 5;
    const int warp_m = warp >> 1, warp_n = warp & 1;
    const int m_blk = blockIdx.y << 7, n_blk = blockIdx.x << 7;

    const int ar = tid >> 2, ac = tid & 3;
    const int br = tid >> 4, bc = tid & 15;
    const __nv_bfloat16* Ag = A  + (size_t)(m_blk + ar) * K + ac*8;
    const __nv_bfloat16* Bg = Bw + (size_t)br * N + n_blk + bc*8;
    const u32 dA0 = smb + ar*GA_ROWB + ac*16;
    const u32 dB0 = smb + GA_BYTES + br*GB_ROWB + bc*16;

    const int g  = lane >> 3;
    const int r8 = lane & 7;
    const u32 aAddr0 = smb + (u32)(warp_m*64 + r8 + (g&1)*8) * GA_ROWB + (u32)((g>>1)*16);
    const u32 bAddr0 = smb + GA_BYTES + (u32)(r8 + (g&1)*8) * GB_ROWB
                           + (u32)(warp_n*64 + (g>>1)*8) * 2;

    float acc[4][8][4];
#pragma unroll
    for (int mt = 0; mt < 4; mt++)
#pragma unroll
        for (int nt = 0; nt < 8; nt++)
#pragma unroll
            for (int i = 0; i < 4; i++) acc[mt][nt][i] = 0.f;

    const int nk = K >> 5;

    auto issue = [&](int kt) {
        const u32 sb = (kt & (NSTAGE-1)) * STAGE_B;
        const __nv_bfloat16* Ak = Ag + (kt << 5);
        const __nv_bfloat16* Bk = Bg + (size_t)(kt << 5) * N;
#pragma unroll
        for (int p = 0; p < 4; p++)
            cp16(dA0 + sb + p*32*GA_ROWB, Ak + (size_t)(p*32)*K);
#pragma unroll
        for (int p = 0; p < 4; p++)
            cp16(dB0 + sb + p*8*GB_ROWB,  Bk + (size_t)(p*8)*N);
        cp_commit();
    };

    issue(0);
    if (nk > 1) issue(1);
    if (nk > 2) issue(2);

    for (int kt = 0; kt < nk; kt++) {
        if      (kt + 2 < nk) asm volatile("cp.async.wait_group 2;");
        else if (kt + 1 < nk) asm volatile("cp.async.wait_group 1;");
        else                  asm volatile("cp.async.wait_group 0;");
        __syncthreads();

        if (kt + 3 < nk) issue(kt + 3);

        const u32 sb = (kt & (NSTAGE-1)) * STAGE_B;
        const u32 aB = aAddr0 + sb;
        const u32 bB = bAddr0 + sb;
#pragma unroll
        for (int ks = 0; ks < 2; ks++) {
            u32 af[4][4];
#pragma unroll
            for (int mt = 0; mt < 4; mt++)
                ldsm_x4(af[mt][0], af[mt][1], af[mt][2], af[mt][3],
                        aB + (u32)(mt*16) * GA_ROWB + (u32)(ks*32));
#pragma unroll
            for (int np = 0; np < 4; np++) {
                u32 b0, b1, b2, b3;
                ldsm_x4_t(b0, b1, b2, b3,
                          bB + (u32)(ks*16) * GB_ROWB + (u32)(np*32));
#pragma unroll
                for (int mt = 0; mt < 4; mt++) {
                    mma_bf16(acc[mt][2*np],   af[mt], b0, b1);
                    mma_bf16(acc[mt][2*np+1], af[mt], b2, b3);
                }
            }
        }
    }

    const int rr = lane >> 2, cc = (lane & 3) << 1;
    const int row0 = m_blk + warp_m * 64;
    const int col0 = n_blk + warp_n * 64;
#pragma unroll
    for (int mt = 0; mt < 4; mt++) {
#pragma unroll
        for (int nt = 0; nt < 8; nt++) {
            const int col = col0 + nt * 8 + cc;
            float2 b2 = *(const float2*)(bias + col);
            float2 g2 = make_float2(0.f, 0.f);
            if (MODE == 1) g2 = *(const float2*)(gamma + col);
#pragma unroll
            for (int half = 0; half < 2; half++) {
                const int row = row0 + mt * 16 + rr + half * 8;
                const size_t off = (size_t)row * N + col;
                float v0 = acc[mt][nt][half*2 + 0] + b2.x;
                float v1 = acc[mt][nt][half*2 + 1] + b2.y;
                if (MODE == 1) {
                    float2 rv = *(const float2*)(resid + off);
                    v0 = rv.x + g2.x * v0;
                    v1 = rv.y + g2.y * v1;
                } else if (MODE == 2) {
                    v0 = 0.5f * v0 * (1.0f + erff(v0 * 0.70710678118654752f));
                    v1 = 0.5f * v1 * (1.0f + erff(v1 * 0.70710678118654752f));
                }
                if (OBF) *(u32*)((__nv_bfloat16*)CoutV + off) = pack_bf16(v0, v1);
                else     *(float2*)((float*)CoutV + off) = make_float2(v0, v1);
            }
        }
    }
}

// ---------------- Flash attention: 128 queries/CTA, 8 warps ----------------
#define KV_ROWB  144
#define QTILE_B  (128*KV_ROWB)
#define KVTILE_B (64*KV_ROWB)
#define SQ_OFF   0
#define SK_OFF   (QTILE_B)
#define SV_OFF   (QTILE_B + 2*KVTILE_B)
#define SMSK_OFF (QTILE_B + 4*KVTILE_B)
#define ATTN_SMEM (SMSK_OFF + 2*64*4)

__device__ __forceinline__ void attn_issue_kv(const __nv_bfloat16* __restrict__ qkv,
                                              u32 smb, int buf, int kt, int b, int h, int tid)
{
    const __nv_bfloat16* gK = qkv + ((size_t)(b*T_) + kt*64) * C3 + C_ + h*D_;
    const __nv_bfloat16* gV = gK + C_;
    u32 dK = smb + SK_OFF + buf*KVTILE_B;
    u32 dV = smb + SV_OFF + buf*KVTILE_B;
#pragma unroll
    for (int k = 0; k < 2; k++) {
        int c = tid + k*256;
        int row = c >> 3, col16 = c & 7;
        cp16(dK + row*KV_ROWB + col16*16, gK + (size_t)row*C3 + col16*8);
        cp16(dV + row*KV_ROWB + col16*16, gV + (size_t)row*C3 + col16*8);
    }
}

__global__ void __launch_bounds__(256) attn_kernel(
    const __nv_bfloat16* __restrict__ qkv, const int* __restrict__ mask,
    __nv_bfloat16* __restrict__ Out)
{
    extern __shared__ char attn_sm[];
    u32 smb = (u32)__cvta_generic_to_shared(attn_sm);
    float* sMask = (float*)(attn_sm + SMSK_OFF);

    const int tid = threadIdx.x;
    const int lane = tid & 31, warp = tid >> 5;
    const int b = blockIdx.z, h = blockIdx.y;
    const int q0 = blockIdx.x << 7;
    const int g = lane >> 3, r8 = lane & 7;
    const int qd = lane >> 2, qi = lane & 3;

    {
        const __nv_bfloat16* gQ = qkv + ((size_t)(b*T_ + q0)) * C3 + h*D_;
#pragma unroll
        for (int k = 0; k < 4; k++) {
            int c = tid + k*256;
            int row = c >> 3, col16 = c & 7;
            cp16(smb + SQ_OFF + row*KV_ROWB + col16*16, gQ + (size_t)row*C3 + col16*8);
        }
        attn_issue_kv(qkv, smb, 0, 0, b, h, tid);
        if (tid < 64) sMask[tid] = mask[b*T_ + tid] ? 0.f : -1e30f;
        cp_commit();
    }

    float ofrag[8][4];
#pragma unroll
    for (int nt = 0; nt < 8; nt++)
#pragma unroll
        for (int i = 0; i < 4; i++) ofrag[nt][i] = 0.f;
    float mrow0 = -1e30f, mrow1 = -1e30f, lrow0 = 0.f, lrow1 = 0.f;
    u32 qf[4][4];

    const int NKT = T_ / 64;
    for (int kt = 0; kt < NKT; kt++) {
        const int cur = kt & 1;
        if (kt + 1 < NKT) {
            attn_issue_kv(qkv, smb, cur ^ 1, kt + 1, b, h, tid);
            if (tid < 64) sMask[(cur^1)*64 + tid] = mask[b*T_ + (kt+1)*64 + tid] ? 0.f : -1e30f;
            cp_commit();
            asm volatile("cp.async.wait_group 1;");
        } else {
            asm volatile("cp.async.wait_group 0;");
        }
        __syncthreads();

        if (kt == 0) {
#pragma unroll
            for (int ks = 0; ks < 4; ks++) {
                u32 addr = smb + SQ_OFF
                         + (u32)(warp*16 + r8 + (g&1)*8) * KV_ROWB
                         + (u32)(ks*16 + (g>>1)*8) * 2;
                ldsm_x4(qf[ks][0], qf[ks][1], qf[ks][2], qf[ks][3], addr);
            }
        }

        float sfrag[8][4];
#pragma unroll
        for (int nt = 0; nt < 8; nt++)
#pragma unroll
            for (int i = 0; i < 4; i++) sfrag[nt][i] = 0.f;
        const u32 kBase = smb + SK_OFF + cur*KVTILE_B;
#pragma unroll
        for (int ks = 0; ks < 4; ks++) {
#pragma unroll
            for (int np = 0; np < 4; np++) {
                u32 k0, k1, k2, k3;
                u32 addr = kBase + (u32)(np*16 + (g>>1)*8 + r8) * KV_ROWB
                                 + (u32)(ks*16 + (g&1)*8) * 2;
                ldsm_x4(k0, k1, k2, k3, addr);
                mma_bf16(sfrag[2*np],   qf[ks], k0, k1);
                mma_bf16(sfrag[2*np+1], qf[ks], k2, k3);
            }
        }

        const float* msk = sMask + cur*64;
        float mx0 = -1e30f, mx1 = -1e30f;
#pragma unroll
        for (int nt = 0; nt < 8; nt++) {
            float2 am = *(const float2*)(msk + nt*8 + 2*qi);
            sfrag[nt][0] = fmaf(sfrag[nt][0], 0.125f, am.x);
            sfrag[nt][1] = fmaf(sfrag[nt][1], 0.125f, am.y);
            sfrag[nt][2] = fmaf(sfrag[nt][2], 0.125f, am.x);
            sfrag[nt][3] = fmaf(sfrag[nt][3], 0.125f, am.y);
            mx0 = fmaxf(mx0, fmaxf(sfrag[nt][0], sfrag[nt][1]));
            mx1 = fmaxf(mx1, fmaxf(sfrag[nt][2], sfrag[nt][3]));
        }
        mx0 = fmaxf(mx0, __shfl_xor_sync(~0u, mx0, 1));
        mx0 = fmaxf(mx0, __shfl_xor_sync(~0u, mx0, 2));
        mx1 = fmaxf(mx1, __shfl_xor_sync(~0u, mx1, 1));
        mx1 = fmaxf(mx1, __shfl_xor_sync(~0u, mx1, 2));
        float mnew0 = fmaxf(mrow0, mx0), mnew1 = fmaxf(mrow1, mx1);
        float cor0 = fexp(mrow0 - mnew0), cor1 = fexp(mrow1 - mnew1);
        mrow0 = mnew0; mrow1 = mnew1;
        float ps0 = 0.f, ps1 = 0.f;
#pragma unroll
        for (int nt = 0; nt < 8; nt++) {
            sfrag[nt][0] = fexp(sfrag[nt][0] - mnew0);
            sfrag[nt][1] = fexp(sfrag[nt][1] - mnew0);
            sfrag[nt][2] = fexp(sfrag[nt][2] - mnew1);
            sfrag[nt][3] = fexp(sfrag[nt][3] - mnew1);
            ps0 += sfrag[nt][0] + sfrag[nt][1];
            ps1 += sfrag[nt][2] + sfrag[nt][3];
        }
        ps0 += __shfl_xor_sync(~0u, ps0, 1);
        ps0 += __shfl_xor_sync(~0u, ps0, 2);
        ps1 += __shfl_xor_sync(~0u, ps1, 1);
        ps1 += __shfl_xor_sync(~0u, ps1, 2);
        lrow0 = lrow0 * cor0 + ps0;
        lrow1 = lrow1 * cor1 + ps1;
#pragma unroll
        for (int nt = 0; nt < 8; nt++) {
            ofrag[nt][0] *= cor0; ofrag[nt][1] *= cor0;
            ofrag[nt][2] *= cor1; ofrag[nt][3] *= cor1;
        }

        const u32 vBase = smb + SV_OFF + cur*KVTILE_B;
#pragma unroll
        for (int kk = 0; kk < 4; kk++) {
            u32 a[4];
            a[0] = pack_bf16(sfrag[2*kk][0],   sfrag[2*kk][1]);
            a[1] = pack_bf16(sfrag[2*kk][2],   sfrag[2*kk][3]);
            a[2] = pack_bf16(sfrag[2*kk+1][0], sfrag[2*kk+1][1]);
            a[3] = pack_bf16(sfrag[2*kk+1][2], sfrag[2*kk+1][3]);
#pragma unroll
            for (int dp = 0; dp < 4; dp++) {
                u32 v0, v1, v2, v3;
                u32 addr = vBase + (u32)(kk*16 + r8 + (g&1)*8) * KV_ROWB
                                 + (u32)(dp*16 + (g>>1)*8) * 2;
                ldsm_x4_t(v0, v1, v2, v3, addr);
                mma_bf16(ofrag[2*dp],   a, v0, v1);
                mma_bf16(ofrag[2*dp+1], a, v2, v3);
            }
        }
        __syncthreads();
    }

    const float inv0 = 1.0f / lrow0, inv1 = 1.0f / lrow1;
    const int r0 = q0 + warp*16 + qd;
    const int r1 = r0 + 8;
    __nv_bfloat16* o0 = Out + (size_t)(b*T_ + r0) * C_ + h*D_ + 2*qi;
    __nv_bfloat16* o1 = Out + (size_t)(b*T_ + r1) * C_ + h*D_ + 2*qi;
#pragma unroll
    for (int nt = 0; nt < 8; nt++) {
        *(u32*)(o0 + nt*8) = pack_bf16(ofrag[nt][0]*inv0, ofrag[nt][1]*inv0);
        *(u32*)(o1 + nt*8) = pack_bf16(ofrag[nt][2]*inv1, ofrag[nt][3]*inv1);
    }
}

// ---------------- host launcher ----------------
extern "C" void kernel_launch(void* const* d_in, const int* in_sizes, int n_in,
                              void* d_out, int out_size)
{
    const float* x    = (const float*)d_in[0];
    const int*   mask = (const int*)  d_in[1];
    const float* ln1w = (const float*)d_in[2];
    const float* ln1b = (const float*)d_in[3];
    const float* ln2w = (const float*)d_in[4];
    const float* ln2b = (const float*)d_in[5];
    const float* qw   = (const float*)d_in[6];
    const float* qb   = (const float*)d_in[7];
    const float* kw   = (const float*)d_in[8];
    const float* kb   = (const float*)d_in[9];
    const float* vw   = (const float*)d_in[10];
    const float* vb   = (const float*)d_in[11];
    const float* ow   = (const float*)d_in[12];
    const float* ob   = (const float*)d_in[13];
    const float* f1w  = (const float*)d_in[14];
    const float* f1b  = (const float*)d_in[15];
    const float* f2w  = (const float*)d_in[16];
    const float* f2b  = (const float*)d_in[17];
    const float* gm1  = (const float*)d_in[18];
    const float* gm2  = (const float*)d_in[19];
    float* out = (float*)d_out;

    __nv_bfloat16 *b_h, *b_h2, *b_qkv, *b_att, *b_f1, *b_wqkv, *b_wo, *b_wf1, *b_wf2;
    float *b_x1, *b_bqkv;
    cudaGetSymbolAddress((void**)&b_h,    g_hb);
    cudaGetSymbolAddress((void**)&b_h2,   g_h2b);
    cudaGetSymbolAddress((void**)&b_qkv,  g_qkv);
    cudaGetSymbolAddress((void**)&b_att,  g_attb);
    cudaGetSymbolAddress((void**)&b_f1,   g_f1b);
    cudaGetSymbolAddress((void**)&b_x1,   g_x1);
    cudaGetSymbolAddress((void**)&b_wqkv, g_wqkv);
    cudaGetSymbolAddress((void**)&b_wo,   g_wo);
    cudaGetSymbolAddress((void**)&b_wf1,  g_wf1);
    cudaGetSymbolAddress((void**)&b_wf2,  g_wf2);
    cudaGetSymbolAddress((void**)&b_bqkv, g_bqkv);

    cudaFuncSetAttribute(attn_kernel,
                         cudaFuncAttributeMaxDynamicSharedMemorySize, ATTN_SMEM);
    cudaFuncSetAttribute(bgemm_kernel<0,1>,
                         cudaFuncAttributeMaxDynamicSharedMemorySize, GEMM_SMEM);
    cudaFuncSetAttribute(bgemm_kernel<1,0>,
                         cudaFuncAttributeMaxDynamicSharedMemorySize, GEMM_SMEM);
    cudaFuncSetAttribute(bgemm_kernel<2,1>,
                         cudaFuncAttributeMaxDynamicSharedMemorySize, GEMM_SMEM);

    cvt_all_kernel<<<2048, 256>>>(qw, kw, vw, qb, kb, vb, ow, f1w, f2w);

    dim3 gridQKV(C3 / 128, NTOK / 128);
    dim3 gridC  (C_ / 128, NTOK / 128);
    dim3 gridF  (DFF / 128, NTOK / 128);

    ln_kernel<<<NTOK, 256>>>(x, ln1w, ln1b, b_h);
    bgemm_kernel<0,1><<<gridQKV, 128, GEMM_SMEM>>>(b_h, b_wqkv, b_bqkv, nullptr, nullptr, b_qkv, NTOK, C3, C_);
    attn_kernel<<<dim3(T_/128, H_, B_), 256, ATTN_SMEM>>>(b_qkv, mask, b_att);
    bgemm_kernel<1,0><<<gridC, 128, GEMM_SMEM>>>(b_att, b_wo, ob, x, gm1, b_x1, NTOK, C_, C_);
    ln_kernel<<<NTOK, 256>>>(b_x1, ln2w, ln2b, b_h2);
    bgemm_kernel<2,1><<<gridF, 128, GEMM_SMEM>>>(b_h2, b_wf1, f1b, nullptr, nullptr, b_f1, NTOK, DFF, C_);
    bgemm_kernel<1,0><<<gridC, 128, GEMM_SMEM>>>(b_f1, b_wf2, f2b, b_x1, gm2, out, NTOK, C_, DFF);
}

// round 14
// speedup vs baseline: 1.2753x; 1.0355x over previous
#include <cuda_runtime.h>
#include <cuda_bf16.h>
#include <cstdint>
#include <math.h>

typedef unsigned int u32;

#define B_   2
#define T_   2048
#define C_   1024
#define H_   16
#define D_   64
#define NTOK (B_*T_)
#define DFF  4096
#define C3   (3*C_)

// ---------------- scratch (no allocation allowed) ----------------
__device__ __nv_bfloat16 g_hb  [NTOK*C_];
__device__ __nv_bfloat16 g_h2b [NTOK*C_];
__device__ __nv_bfloat16 g_qkv [NTOK*C3];
__device__ __nv_bfloat16 g_attb[NTOK*C_];
__device__ __nv_bfloat16 g_f1b [(size_t)NTOK*DFF];
__device__ float         g_x1  [NTOK*C_];
__device__ __nv_bfloat16 g_wqkv[C_*C3];
__device__ __nv_bfloat16 g_wo  [C_*C_];
__device__ __nv_bfloat16 g_wf1 [C_*DFF];
__device__ __nv_bfloat16 g_wf2 [DFF*C_];
__device__ float         g_bqkv[C3];

// ---------------- small helpers ----------------
__device__ __forceinline__ u32 pack_bf16(float x, float y) {
    __nv_bfloat162 t = __floats2bfloat162_rn(x, y);
    u32 r; memcpy(&r, &t, 4); return r;
}
__device__ __forceinline__ void cp16(u32 sdst, const void* gsrc) {
    asm volatile("cp.async.cg.shared.global [%0], [%1], 16;" :: "r"(sdst), "l"(gsrc));
}
__device__ __forceinline__ void cp_commit() { asm volatile("cp.async.commit_group;"); }
__device__ __forceinline__ void ldsm_x4(u32& r0, u32& r1, u32& r2, u32& r3, u32 addr) {
    asm volatile("ldmatrix.sync.aligned.m8n8.x4.shared.b16 {%0,%1,%2,%3},[%4];"
                 : "=r"(r0), "=r"(r1), "=r"(r2), "=r"(r3) : "r"(addr));
}
__device__ __forceinline__ void ldsm_x4_t(u32& r0, u32& r1, u32& r2, u32& r3, u32 addr) {
    asm volatile("ldmatrix.sync.aligned.m8n8.x4.trans.shared.b16 {%0,%1,%2,%3},[%4];"
                 : "=r"(r0), "=r"(r1), "=r"(r2), "=r"(r3) : "r"(addr));
}
__device__ __forceinline__ void mma_bf16(float* c, const u32* a, u32 b0, u32 b1) {
    asm volatile("mma.sync.aligned.m16n8k16.row.col.f32.bf16.bf16.f32 "
                 "{%0,%1,%2,%3},{%4,%5,%6,%7},{%8,%9},{%0,%1,%2,%3};"
                 : "+f"(c[0]), "+f"(c[1]), "+f"(c[2]), "+f"(c[3])
                 : "r"(a[0]), "r"(a[1]), "r"(a[2]), "r"(a[3]), "r"(b0), "r"(b1));
}
// FFMA-only exp: no MUFU, no FRND/F2I (conversion pipe untouched).
// Magic 12582912 = 1.5*2^23: low 9 bits zero, so (bits<<23) splices the
// exponent exactly. Valid for |x| <= ~88 after clamp. Deg-4 Taylor, err ~4e-5.
__device__ __forceinline__ float fexp(float x) {
    x = fmaxf(x, -80.0f);
    float y  = fmaf(x, 1.4426950408889634f, 12582912.0f);
    int  ki  = __float_as_int(y);
    float kf = y - 12582912.0f;
    float t  = fmaf(kf, -0.6931471805599453f, x);
    float p  = fmaf(t, fmaf(t, fmaf(t, fmaf(t, 4.1666667e-2f, 0.16666667f),
                  0.5f), 1.0f), 1.0f);
    return __int_as_float(__float_as_int(p) + (ki << 23));
}

// ---------------- single fused weight conversion ----------------
__global__ void cvt_all_kernel(const float* __restrict__ qw, const float* __restrict__ kw,
                               const float* __restrict__ vw, const float* __restrict__ qb,
                               const float* __restrict__ kb, const float* __restrict__ vb,
                               const float* __restrict__ ow, const float* __restrict__ f1w,
                               const float* __restrict__ f2w)
{
    int gtid = blockIdx.x * blockDim.x + threadIdx.x;
    int stride = gridDim.x * blockDim.x;
    const int n_qkv = C_*C_/4;
    const int n_o   = C_*C_/4;
    const int n_f   = C_*DFF/4;
    for (int i = gtid; i < n_qkv; i += stride) {
        int c = i / (C_/4), j = (i % (C_/4)) * 4;
        float4 q4 = *(const float4*)(qw + (size_t)c*C_ + j);
        float4 k4 = *(const float4*)(kw + (size_t)c*C_ + j);
        float4 v4 = *(const float4*)(vw + (size_t)c*C_ + j);
        *(uint2*)(g_wqkv + (size_t)c*C3 + j)        = make_uint2(pack_bf16(q4.x,q4.y), pack_bf16(q4.z,q4.w));
        *(uint2*)(g_wqkv + (size_t)c*C3 + C_ + j)   = make_uint2(pack_bf16(k4.x,k4.y), pack_bf16(k4.z,k4.w));
        *(uint2*)(g_wqkv + (size_t)c*C3 + 2*C_ + j) = make_uint2(pack_bf16(v4.x,v4.y), pack_bf16(v4.z,v4.w));
    }
    for (int i = gtid; i < n_o; i += stride) {
        float4 s = *(const float4*)(ow + (size_t)i*4);
        *(uint2*)(g_wo + (size_t)i*4) = make_uint2(pack_bf16(s.x,s.y), pack_bf16(s.z,s.w));
    }
    for (int i = gtid; i < n_f; i += stride) {
        float4 s = *(const float4*)(f1w + (size_t)i*4);
        *(uint2*)(g_wf1 + (size_t)i*4) = make_uint2(pack_bf16(s.x,s.y), pack_bf16(s.z,s.w));
    }
    for (int i = gtid; i < n_f; i += stride) {
        float4 s = *(const float4*)(f2w + (size_t)i*4);
        *(uint2*)(g_wf2 + (size_t)i*4) = make_uint2(pack_bf16(s.x,s.y), pack_bf16(s.z,s.w));
    }
    if (gtid < C_) {
        g_bqkv[gtid]        = qb[gtid];
        g_bqkv[C_ + gtid]   = kb[gtid];
        g_bqkv[2*C_ + gtid] = vb[gtid];
    }
}

// ---------------- LayerNorm: fp32 in -> bf16 out ----------------
__global__ void __launch_bounds__(256) ln_kernel(const float* __restrict__ x,
                                                 const float* __restrict__ w,
                                                 const float* __restrict__ b,
                                                 __nv_bfloat16* __restrict__ y)
{
    __shared__ float red[8];
    int row = blockIdx.x, tid = threadIdx.x;
    const float* xr = x + (size_t)row * C_;
    float4 v = *(const float4*)(xr + 4*tid);

    float s = v.x + v.y + v.z + v.w;
#pragma unroll
    for (int o = 16; o > 0; o >>= 1) s += __shfl_xor_sync(~0u, s, o);
    if ((tid & 31) == 0) red[tid >> 5] = s;
    __syncthreads();
    if (tid < 32) {
        float t = (tid < 8) ? red[tid] : 0.f;
#pragma unroll
        for (int o = 4; o > 0; o >>= 1) t += __shfl_xor_sync(~0u, t, o);
        if (tid == 0) red[0] = t;
    }
    __syncthreads();
    float mu = red[0] * (1.0f / C_);
    __syncthreads();

    float dx = v.x-mu, dy = v.y-mu, dz = v.z-mu, dw = v.w-mu;
    float sq = dx*dx + dy*dy + dz*dz + dw*dw;
#pragma unroll
    for (int o = 16; o > 0; o >>= 1) sq += __shfl_xor_sync(~0u, sq, o);
    if ((tid & 31) == 0) red[tid >> 5] = sq;
    __syncthreads();
    if (tid < 32) {
        float t = (tid < 8) ? red[tid] : 0.f;
#pragma unroll
        for (int o = 4; o > 0; o >>= 1) t += __shfl_xor_sync(~0u, t, o);
        if (tid == 0) red[0] = t;
    }
    __syncthreads();
    float rs = rsqrtf(red[0] * (1.0f / C_) + 1e-5f);
    float4 w4 = *(const float4*)(w + 4*tid);
    float4 b4 = *(const float4*)(b + 4*tid);
    float o0 = dx*rs*w4.x + b4.x, o1 = dy*rs*w4.y + b4.y;
    float o2 = dz*rs*w4.z + b4.z, o3 = dw*rs*w4.w + b4.w;
    *(uint2*)(y + (size_t)row*C_ + 4*tid) = make_uint2(pack_bf16(o0,o1), pack_bf16(o2,o3));
}

// ---------------- GEMM 128x128x32, 4 warps, warp tile 64x64, 4-stage ----------------
#define GA_ROWB   80
#define GB_ROWB   272
#define GA_BYTES  (128*GA_ROWB)
#define GB_BYTES  (32*GB_ROWB)
#define STAGE_B   (GA_BYTES + GB_BYTES)
#define NSTAGE    4
#define GEMM_SMEM (NSTAGE*STAGE_B)

template<int MODE, int OBF>
__global__ void __launch_bounds__(128) bgemm_kernel(
    const __nv_bfloat16* __restrict__ A, const __nv_bfloat16* __restrict__ Bw,
    const float* __restrict__ bias,
    const float* __restrict__ resid, const float* __restrict__ gamma,
    void* __restrict__ CoutV, int M, int N, int K)
{
    extern __shared__ char gsm[];
    const u32 smb = (u32)__cvta_generic_to_shared(gsm);

    const int tid  = threadIdx.x;
    const int lane = tid & 31, warp = tid >> 5;
    const int warp_m = warp >> 1, warp_n = warp & 1;
    const int m_blk = blockIdx.y << 7, n_blk = blockIdx.x << 7;

    const int ar = tid >> 2, ac = tid & 3;
    const int br = tid >> 4, bc = tid & 15;
    const __nv_bfloat16* Ag = A  + (size_t)(m_blk + ar) * K + ac*8;
    const __nv_bfloat16* Bg = Bw + (size_t)br * N + n_blk + bc*8;
    const u32 dA0 = smb + ar*GA_ROWB + ac*16;
    const u32 dB0 = smb + GA_BYTES + br*GB_ROWB + bc*16;

    const int g  = lane >> 3;
    const int r8 = lane & 7;
    const u32 aAddr0 = smb + (u32)(warp_m*64 + r8 + (g&1)*8) * GA_ROWB + (u32)((g>>1)*16);
    const u32 bAddr0 = smb + GA_BYTES + (u32)(r8 + (g&1)*8) * GB_ROWB
                           + (u32)(warp_n*64 + (g>>1)*8) * 2;

    float acc[4][8][4];
#pragma unroll
    for (int mt = 0; mt < 4; mt++)
#pragma unroll
        for (int nt = 0; nt < 8; nt++)
#pragma unroll
            for (int i = 0; i < 4; i++) acc[mt][nt][i] = 0.f;

    const int nk = K >> 5;

    auto issue = [&](int kt) {
        const u32 sb = (kt & (NSTAGE-1)) * STAGE_B;
        const __nv_bfloat16* Ak = Ag + (kt << 5);
        const __nv_bfloat16* Bk = Bg + (size_t)(kt << 5) * N;
#pragma unroll
        for (int p = 0; p < 4; p++)
            cp16(dA0 + sb + p*32*GA_ROWB, Ak + (size_t)(p*32)*K);
#pragma unroll
        for (int p = 0; p < 4; p++)
            cp16(dB0 + sb + p*8*GB_ROWB,  Bk + (size_t)(p*8)*N);
        cp_commit();
    };

    issue(0);
    if (nk > 1) issue(1);
    if (nk > 2) issue(2);

    for (int kt = 0; kt < nk; kt++) {
        if      (kt + 2 < nk) asm volatile("cp.async.wait_group 2;");
        else if (kt + 1 < nk) asm volatile("cp.async.wait_group 1;");
        else                  asm volatile("cp.async.wait_group 0;");
        __syncthreads();

        if (kt + 3 < nk) issue(kt + 3);

        const u32 sb = (kt & (NSTAGE-1)) * STAGE_B;
        const u32 aB = aAddr0 + sb;
        const u32 bB = bAddr0 + sb;
#pragma unroll
        for (int ks = 0; ks < 2; ks++) {
            u32 af[4][4];
#pragma unroll
            for (int mt = 0; mt < 4; mt++)
                ldsm_x4(af[mt][0], af[mt][1], af[mt][2], af[mt][3],
                        aB + (u32)(mt*16) * GA_ROWB + (u32)(ks*32));
#pragma unroll
            for (int np = 0; np < 4; np++) {
                u32 b0, b1, b2, b3;
                ldsm_x4_t(b0, b1, b2, b3,
                          bB + (u32)(ks*16) * GB_ROWB + (u32)(np*32));
#pragma unroll
                for (int mt = 0; mt < 4; mt++) {
                    mma_bf16(acc[mt][2*np],   af[mt], b0, b1);
                    mma_bf16(acc[mt][2*np+1], af[mt], b2, b3);
                }
            }
        }
    }

    const int rr = lane >> 2, cc = (lane & 3) << 1;
    const int row0 = m_blk + warp_m * 64;
    const int col0 = n_blk + warp_n * 64;
#pragma unroll
    for (int mt = 0; mt < 4; mt++) {
#pragma unroll
        for (int nt = 0; nt < 8; nt++) {
            const int col = col0 + nt * 8 + cc;
            float2 b2 = *(const float2*)(bias + col);
            float2 g2 = make_float2(0.f, 0.f);
            if (MODE == 1) g2 = *(const float2*)(gamma + col);
#pragma unroll
            for (int half = 0; half < 2; half++) {
                const int row = row0 + mt * 16 + rr + half * 8;
                const size_t off = (size_t)row * N + col;
                float v0 = acc[mt][nt][half*2 + 0] + b2.x;
                float v1 = acc[mt][nt][half*2 + 1] + b2.y;
                if (MODE == 1) {
                    float2 rv = *(const float2*)(resid + off);
                    v0 = rv.x + g2.x * v0;
                    v1 = rv.y + g2.y * v1;
                } else if (MODE == 2) {
                    v0 = 0.5f * v0 * (1.0f + erff(v0 * 0.70710678118654752f));
                    v1 = 0.5f * v1 * (1.0f + erff(v1 * 0.70710678118654752f));
                }
                if (OBF) *(u32*)((__nv_bfloat16*)CoutV + off) = pack_bf16(v0, v1);
                else     *(float2*)((float*)CoutV + off) = make_float2(v0, v1);
            }
        }
    }
}

// ---------------- Flash attention: 128 queries/CTA, 8 warps ----------------
#define KV_ROWB  144
#define QTILE_B  (128*KV_ROWB)
#define KVTILE_B (64*KV_ROWB)
#define SQ_OFF   0
#define SK_OFF   (QTILE_B)
#define SV_OFF   (QTILE_B + 2*KVTILE_B)
#define SMSK_OFF (QTILE_B + 4*KVTILE_B)
#define ATTN_SMEM (SMSK_OFF + 2*64*4)

__device__ __forceinline__ void attn_issue_kv(const __nv_bfloat16* __restrict__ qkv,
                                              u32 smb, int buf, int kt, int b, int h, int tid)
{
    const __nv_bfloat16* gK = qkv + ((size_t)(b*T_) + kt*64) * C3 + C_ + h*D_;
    const __nv_bfloat16* gV = gK + C_;
    u32 dK = smb + SK_OFF + buf*KVTILE_B;
    u32 dV = smb + SV_OFF + buf*KVTILE_B;
#pragma unroll
    for (int k = 0; k < 2; k++) {
        int c = tid + k*256;
        int row = c >> 3, col16 = c & 7;
        cp16(dK + row*KV_ROWB + col16*16, gK + (size_t)row*C3 + col16*8);
        cp16(dV + row*KV_ROWB + col16*16, gV + (size_t)row*C3 + col16*8);
    }
}

__global__ void __launch_bounds__(256) attn_kernel(
    const __nv_bfloat16* __restrict__ qkv, const int* __restrict__ mask,
    __nv_bfloat16* __restrict__ Out)
{
    extern __shared__ char attn_sm[];
    u32 smb = (u32)__cvta_generic_to_shared(attn_sm);
    float* sMask = (float*)(attn_sm + SMSK_OFF);

    const int tid = threadIdx.x;
    const int lane = tid & 31, warp = tid >> 5;
    const int b = blockIdx.z, h = blockIdx.y;
    const int q0 = blockIdx.x << 7;
    const int g = lane >> 3, r8 = lane & 7;
    const int qd = lane >> 2, qi = lane & 3;

    {
        const __nv_bfloat16* gQ = qkv + ((size_t)(b*T_ + q0)) * C3 + h*D_;
#pragma unroll
        for (int k = 0; k < 4; k++) {
            int c = tid + k*256;
            int row = c >> 3, col16 = c & 7;
            cp16(smb + SQ_OFF + row*KV_ROWB + col16*16, gQ + (size_t)row*C3 + col16*8);
        }
        attn_issue_kv(qkv, smb, 0, 0, b, h, tid);
        if (tid < 64) sMask[tid] = mask[b*T_ + tid] ? 0.f : -1e30f;
        cp_commit();
    }

    float ofrag[8][4];
#pragma unroll
    for (int nt = 0; nt < 8; nt++)
#pragma unroll
        for (int i = 0; i < 4; i++) ofrag[nt][i] = 0.f;
    float mrow0 = -1e30f, mrow1 = -1e30f, lrow0 = 0.f, lrow1 = 0.f;
    u32 qf[4][4];

    const int NKT = T_ / 64;
    for (int kt = 0; kt < NKT; kt++) {
        const int cur = kt & 1;
        if (kt + 1 < NKT) {
            attn_issue_kv(qkv, smb, cur ^ 1, kt + 1, b, h, tid);
            if (tid < 64) sMask[(cur^1)*64 + tid] = mask[b*T_ + (kt+1)*64 + tid] ? 0.f : -1e30f;
            cp_commit();
            asm volatile("cp.async.wait_group 1;");
        } else {
            asm volatile("cp.async.wait_group 0;");
        }
        __syncthreads();

        if (kt == 0) {
#pragma unroll
            for (int ks = 0; ks < 4; ks++) {
                u32 addr = smb + SQ_OFF
                         + (u32)(warp*16 + r8 + (g&1)*8) * KV_ROWB
                         + (u32)(ks*16 + (g>>1)*8) * 2;
                ldsm_x4(qf[ks][0], qf[ks][1], qf[ks][2], qf[ks][3], addr);
            }
        }

        float sfrag[8][4];
#pragma unroll
        for (int nt = 0; nt < 8; nt++)
#pragma unroll
            for (int i = 0; i < 4; i++) sfrag[nt][i] = 0.f;
        const u32 kBase = smb + SK_OFF + cur*KVTILE_B;
#pragma unroll
        for (int ks = 0; ks < 4; ks++) {
#pragma unroll
            for (int np = 0; np < 4; np++) {
                u32 k0, k1, k2, k3;
                u32 addr = kBase + (u32)(np*16 + (g>>1)*8 + r8) * KV_ROWB
                                 + (u32)(ks*16 + (g&1)*8) * 2;
                ldsm_x4(k0, k1, k2, k3, addr);
                mma_bf16(sfrag[2*np],   qf[ks], k0, k1);
                mma_bf16(sfrag[2*np+1], qf[ks], k2, k3);
            }
        }

        const float* msk = sMask + cur*64;
        float mx0 = -1e30f, mx1 = -1e30f;
#pragma unroll
        for (int nt = 0; nt < 8; nt++) {
            float2 am = *(const float2*)(msk + nt*8 + 2*qi);
            sfrag[nt][0] = fmaf(sfrag[nt][0], 0.125f, am.x);
            sfrag[nt][1] = fmaf(sfrag[nt][1], 0.125f, am.y);
            sfrag[nt][2] = fmaf(sfrag[nt][2], 0.125f, am.x);
            sfrag[nt][3] = fmaf(sfrag[nt][3], 0.125f, am.y);
            mx0 = fmaxf(mx0, fmaxf(sfrag[nt][0], sfrag[nt][1]));
            mx1 = fmaxf(mx1, fmaxf(sfrag[nt][2], sfrag[nt][3]));
        }
        mx0 = fmaxf(mx0, __shfl_xor_sync(~0u, mx0, 1));
        mx0 = fmaxf(mx0, __shfl_xor_sync(~0u, mx0, 2));
        mx1 = fmaxf(mx1, __shfl_xor_sync(~0u, mx1, 1));
        mx1 = fmaxf(mx1, __shfl_xor_sync(~0u, mx1, 2));
        float mnew0 = fmaxf(mrow0, mx0), mnew1 = fmaxf(mrow1, mx1);
        float cor0 = fexp(mrow0 - mnew0), cor1 = fexp(mrow1 - mnew1);
        mrow0 = mnew0; mrow1 = mnew1;
        float ps0 = 0.f, ps1 = 0.f;
#pragma unroll
        for (int nt = 0; nt < 8; nt++) {
            sfrag[nt][0] = fexp(sfrag[nt][0] - mnew0);
            sfrag[nt][1] = fexp(sfrag[nt][1] - mnew0);
            sfrag[nt][2] = fexp(sfrag[nt][2] - mnew1);
            sfrag[nt][3] = fexp(sfrag[nt][3] - mnew1);
            ps0 += sfrag[nt][0] + sfrag[nt][1];
            ps1 += sfrag[nt][2] + sfrag[nt][3];
        }
        ps0 += __shfl_xor_sync(~0u, ps0, 1);
        ps0 += __shfl_xor_sync(~0u, ps0, 2);
        ps1 += __shfl_xor_sync(~0u, ps1, 1);
        ps1 += __shfl_xor_sync(~0u, ps1, 2);
        lrow0 = lrow0 * cor0 + ps0;
        lrow1 = lrow1 * cor1 + ps1;
#pragma unroll
        for (int nt = 0; nt < 8; nt++) {
            ofrag[nt][0] *= cor0; ofrag[nt][1] *= cor0;
            ofrag[nt][2] *= cor1; ofrag[nt][3] *= cor1;
        }

        const u32 vBase = smb + SV_OFF + cur*KVTILE_B;
#pragma unroll
        for (int kk = 0; kk < 4; kk++) {
            u32 a[4];
            a[0] = pack_bf16(sfrag[2*kk][0],   sfrag[2*kk][1]);
            a[1] = pack_bf16(sfrag[2*kk][2],   sfrag[2*kk][3]);
            a[2] = pack_bf16(sfrag[2*kk+1][0], sfrag[2*kk+1][1]);
            a[3] = pack_bf16(sfrag[2*kk+1][2], sfrag[2*kk+1][3]);
#pragma unroll
            for (int dp = 0; dp < 4; dp++) {
                u32 v0, v1, v2, v3;
                u32 addr = vBase + (u32)(kk*16 + r8 + (g&1)*8) * KV_ROWB
                                 + (u32)(dp*16 + (g>>1)*8) * 2;
                ldsm_x4_t(v0, v1, v2, v3, addr);
                mma_bf16(ofrag[2*dp],   a, v0, v1);
                mma_bf16(ofrag[2*dp+1], a, v2, v3);
            }
        }
        __syncthreads();
    }

    const float inv0 = 1.0f / lrow0, inv1 = 1.0f / lrow1;
    const int r0 = q0 + warp*16 + qd;
    const int r1 = r0 + 8;
    __nv_bfloat16* o0 = Out + (size_t)(b*T_ + r0) * C_ + h*D_ + 2*qi;
    __nv_bfloat16* o1 = Out + (size_t)(b*T_ + r1) * C_ + h*D_ + 2*qi;
#pragma unroll
    for (int nt = 0; nt < 8; nt++) {
        *(u32*)(o0 + nt*8) = pack_bf16(ofrag[nt][0]*inv0, ofrag[nt][1]*inv0);
        *(u32*)(o1 + nt*8) = pack_bf16(ofrag[nt][2]*inv1, ofrag[nt][3]*inv1);
    }
}

// ---------------- host launcher ----------------
extern "C" void kernel_launch(void* const* d_in, const int* in_sizes, int n_in,
                              void* d_out, int out_size)
{
    const float* x    = (const float*)d_in[0];
    const int*   mask = (const int*)  d_in[1];
    const float* ln1w = (const float*)d_in[2];
    const float* ln1b = (const float*)d_in[3];
    const float* ln2w = (const float*)d_in[4];
    const float* ln2b = (const float*)d_in[5];
    const float* qw   = (const float*)d_in[6];
    const float* qb   = (const float*)d_in[7];
    const float* kw   = (const float*)d_in[8];
    const float* kb   = (const float*)d_in[9];
    const float* vw   = (const float*)d_in[10];
    const float* vb   = (const float*)d_in[11];
    const float* ow   = (const float*)d_in[12];
    const float* ob   = (const float*)d_in[13];
    const float* f1w  = (const float*)d_in[14];
    const float* f1b  = (const float*)d_in[15];
    const float* f2w  = (const float*)d_in[16];
    const float* f2b  = (const float*)d_in[17];
    const float* gm1  = (const float*)d_in[18];
    const float* gm2  = (const float*)d_in[19];
    float* out = (float*)d_out;

    __nv_bfloat16 *b_h, *b_h2, *b_qkv, *b_att, *b_f1, *b_wqkv, *b_wo, *b_wf1, *b_wf2;
    float *b_x1, *b_bqkv;
    cudaGetSymbolAddress((void**)&b_h,    g_hb);
    cudaGetSymbolAddress((void**)&b_h2,   g_h2b);
    cudaGetSymbolAddress((void**)&b_qkv,  g_qkv);
    cudaGetSymbolAddress((void**)&b_att,  g_attb);
    cudaGetSymbolAddress((void**)&b_f1,   g_f1b);
    cudaGetSymbolAddress((void**)&b_x1,   g_x1);
    cudaGetSymbolAddress((void**)&b_wqkv, g_wqkv);
    cudaGetSymbolAddress((void**)&b_wo,   g_wo);
    cudaGetSymbolAddress((void**)&b_wf1,  g_wf1);
    cudaGetSymbolAddress((void**)&b_wf2,  g_wf2);
    cudaGetSymbolAddress((void**)&b_bqkv, g_bqkv);

    cudaFuncSetAttribute(attn_kernel,
                         cudaFuncAttributeMaxDynamicSharedMemorySize, ATTN_SMEM);
    cudaFuncSetAttribute(bgemm_kernel<0,1>,
                         cudaFuncAttributeMaxDynamicSharedMemorySize, GEMM_SMEM);
    cudaFuncSetAttribute(bgemm_kernel<1,0>,
                         cudaFuncAttributeMaxDynamicSharedMemorySize, GEMM_SMEM);
    cudaFuncSetAttribute(bgemm_kernel<2,1>,
                         cudaFuncAttributeMaxDynamicSharedMemorySize, GEMM_SMEM);

    cvt_all_kernel<<<2048, 256>>>(qw, kw, vw, qb, kb, vb, ow, f1w, f2w);

    dim3 gridQKV(C3 / 128, NTOK / 128);
    dim3 gridC  (C_ / 128, NTOK / 128);
    dim3 gridF  (DFF / 128, NTOK / 128);

    ln_kernel<<<NTOK, 256>>>(x, ln1w, ln1b, b_h);
    bgemm_kernel<0,1><<<gridQKV, 128, GEMM_SMEM>>>(b_h, b_wqkv, b_bqkv, nullptr, nullptr, b_qkv, NTOK, C3, C_);
    attn_kernel<<<dim3(T_/128, H_, B_), 256, ATTN_SMEM>>>(b_qkv, mask, b_att);
    bgemm_kernel<1,0><<<gridC, 128, GEMM_SMEM>>>(b_att, b_wo, ob, x, gm1, b_x1, NTOK, C_, C_);
    ln_kernel<<<NTOK, 256>>>(b_x1, ln2w, ln2b, b_h2);
    bgemm_kernel<2,1><<<gridF, 128, GEMM_SMEM>>>(b_h2, b_wf1, f1b, nullptr, nullptr, b_f1, NTOK, DFF, C_);
    bgemm_kernel<1,0><<<gridC, 128, GEMM_SMEM>>>(b_f1, b_wf2, f2b, b_x1, gm2, out, NTOK, C_, DFF);
}

// round 15
// speedup vs baseline: 1.2825x; 1.0056x over previous
#include <cuda_runtime.h>
#include <cuda_bf16.h>
#include <cstdint>
#include <math.h>

typedef unsigned int u32;

#define B_   2
#define T_   2048
#define C_   1024
#define H_   16
#define D_   64
#define NTOK (B_*T_)
#define DFF  4096
#define C3   (3*C_)

// ---------------- scratch (no allocation allowed) ----------------
__device__ __nv_bfloat16 g_hb  [NTOK*C_];
__device__ __nv_bfloat16 g_h2b [NTOK*C_];
__device__ __nv_bfloat16 g_qkv [NTOK*C3];
__device__ __nv_bfloat16 g_attb[NTOK*C_];
__device__ __nv_bfloat16 g_f1b [(size_t)NTOK*DFF];
__device__ float         g_x1  [NTOK*C_];
__device__ __nv_bfloat16 g_wqkv[C_*C3];
__device__ __nv_bfloat16 g_wo  [C_*C_];
__device__ __nv_bfloat16 g_wf1 [C_*DFF];
__device__ __nv_bfloat16 g_wf2 [DFF*C_];
__device__ float         g_bqkv[C3];

// ---------------- small helpers ----------------
__device__ __forceinline__ u32 pack_bf16(float x, float y) {
    __nv_bfloat162 t = __floats2bfloat162_rn(x, y);
    u32 r; memcpy(&r, &t, 4); return r;
}
__device__ __forceinline__ void cp16(u32 sdst, const void* gsrc) {
    asm volatile("cp.async.cg.shared.global [%0], [%1], 16;" :: "r"(sdst), "l"(gsrc));
}
__device__ __forceinline__ void cp_commit() { asm volatile("cp.async.commit_group;"); }
__device__ __forceinline__ void ldsm_x4(u32& r0, u32& r1, u32& r2, u32& r3, u32 addr) {
    asm volatile("ldmatrix.sync.aligned.m8n8.x4.shared.b16 {%0,%1,%2,%3},[%4];"
                 : "=r"(r0), "=r"(r1), "=r"(r2), "=r"(r3) : "r"(addr));
}
__device__ __forceinline__ void ldsm_x4_t(u32& r0, u32& r1, u32& r2, u32& r3, u32 addr) {
    asm volatile("ldmatrix.sync.aligned.m8n8.x4.trans.shared.b16 {%0,%1,%2,%3},[%4];"
                 : "=r"(r0), "=r"(r1), "=r"(r2), "=r"(r3) : "r"(addr));
}
__device__ __forceinline__ void mma_bf16(float* c, const u32* a, u32 b0, u32 b1) {
    asm volatile("mma.sync.aligned.m16n8k16.row.col.f32.bf16.bf16.f32 "
                 "{%0,%1,%2,%3},{%4,%5,%6,%7},{%8,%9},{%0,%1,%2,%3};"
                 : "+f"(c[0]), "+f"(c[1]), "+f"(c[2]), "+f"(c[3])
                 : "r"(a[0]), "r"(a[1]), "r"(a[2]), "r"(a[3]), "r"(b0), "r"(b1));
}
// FFMA-only exp: no MUFU, no FRND/F2I. Magic 12582912 = 1.5*2^23.
// Deg-3 Taylor on |t|<=0.347: rel err ~6e-4 (invisible after bf16 rounding of P).
__device__ __forceinline__ float fexp(float x) {
    x = fmaxf(x, -80.0f);
    float y  = fmaf(x, 1.4426950408889634f, 12582912.0f);
    int  ki  = __float_as_int(y);
    float kf = y - 12582912.0f;
    float t  = fmaf(kf, -0.6931471805599453f, x);
    float p  = fmaf(t, fmaf(t, fmaf(t, 0.16666667f, 0.5f), 1.0f), 1.0f);
    return __int_as_float(__float_as_int(p) + (ki << 23));
}

// ---------------- single fused weight conversion ----------------
__global__ void cvt_all_kernel(const float* __restrict__ qw, const float* __restrict__ kw,
                               const float* __restrict__ vw, const float* __restrict__ qb,
                               const float* __restrict__ kb, const float* __restrict__ vb,
                               const float* __restrict__ ow, const float* __restrict__ f1w,
                               const float* __restrict__ f2w)
{
    int gtid = blockIdx.x * blockDim.x + threadIdx.x;
    int stride = gridDim.x * blockDim.x;
    const int n_qkv = C_*C_/4;
    const int n_o   = C_*C_/4;
    const int n_f   = C_*DFF/4;
    for (int i = gtid; i < n_qkv; i += stride) {
        int c = i / (C_/4), j = (i % (C_/4)) * 4;
        float4 q4 = *(const float4*)(qw + (size_t)c*C_ + j);
        float4 k4 = *(const float4*)(kw + (size_t)c*C_ + j);
        float4 v4 = *(const float4*)(vw + (size_t)c*C_ + j);
        *(uint2*)(g_wqkv + (size_t)c*C3 + j)        = make_uint2(pack_bf16(q4.x,q4.y), pack_bf16(q4.z,q4.w));
        *(uint2*)(g_wqkv + (size_t)c*C3 + C_ + j)   = make_uint2(pack_bf16(k4.x,k4.y), pack_bf16(k4.z,k4.w));
        *(uint2*)(g_wqkv + (size_t)c*C3 + 2*C_ + j) = make_uint2(pack_bf16(v4.x,v4.y), pack_bf16(v4.z,v4.w));
    }
    for (int i = gtid; i < n_o; i += stride) {
        float4 s = *(const float4*)(ow + (size_t)i*4);
        *(uint2*)(g_wo + (size_t)i*4) = make_uint2(pack_bf16(s.x,s.y), pack_bf16(s.z,s.w));
    }
    for (int i = gtid; i < n_f; i += stride) {
        float4 s = *(const float4*)(f1w + (size_t)i*4);
        *(uint2*)(g_wf1 + (size_t)i*4) = make_uint2(pack_bf16(s.x,s.y), pack_bf16(s.z,s.w));
    }
    for (int i = gtid; i < n_f; i += stride) {
        float4 s = *(const float4*)(f2w + (size_t)i*4);
        *(uint2*)(g_wf2 + (size_t)i*4) = make_uint2(pack_bf16(s.x,s.y), pack_bf16(s.z,s.w));
    }
    if (gtid < C_) {
        g_bqkv[gtid]        = qb[gtid];
        g_bqkv[C_ + gtid]   = kb[gtid];
        g_bqkv[2*C_ + gtid] = vb[gtid];
    }
}

// ---------------- LayerNorm: fp32 in -> bf16 out ----------------
__global__ void __launch_bounds__(256) ln_kernel(const float* __restrict__ x,
                                                 const float* __restrict__ w,
                                                 const float* __restrict__ b,
                                                 __nv_bfloat16* __restrict__ y)
{
    __shared__ float red[8];
    int row = blockIdx.x, tid = threadIdx.x;
    const float* xr = x + (size_t)row * C_;
    float4 v = *(const float4*)(xr + 4*tid);

    float s = v.x + v.y + v.z + v.w;
#pragma unroll
    for (int o = 16; o > 0; o >>= 1) s += __shfl_xor_sync(~0u, s, o);
    if ((tid & 31) == 0) red[tid >> 5] = s;
    __syncthreads();
    if (tid < 32) {
        float t = (tid < 8) ? red[tid] : 0.f;
#pragma unroll
        for (int o = 4; o > 0; o >>= 1) t += __shfl_xor_sync(~0u, t, o);
        if (tid == 0) red[0] = t;
    }
    __syncthreads();
    float mu = red[0] * (1.0f / C_);
    __syncthreads();

    float dx = v.x-mu, dy = v.y-mu, dz = v.z-mu, dw = v.w-mu;
    float sq = dx*dx + dy*dy + dz*dz + dw*dw;
#pragma unroll
    for (int o = 16; o > 0; o >>= 1) sq += __shfl_xor_sync(~0u, sq, o);
    if ((tid & 31) == 0) red[tid >> 5] = sq;
    __syncthreads();
    if (tid < 32) {
        float t = (tid < 8) ? red[tid] : 0.f;
#pragma unroll
        for (int o = 4; o > 0; o >>= 1) t += __shfl_xor_sync(~0u, t, o);
        if (tid == 0) red[0] = t;
    }
    __syncthreads();
    float rs = rsqrtf(red[0] * (1.0f / C_) + 1e-5f);
    float4 w4 = *(const float4*)(w + 4*tid);
    float4 b4 = *(const float4*)(b + 4*tid);
    float o0 = dx*rs*w4.x + b4.x, o1 = dy*rs*w4.y + b4.y;
    float o2 = dz*rs*w4.z + b4.z, o3 = dw*rs*w4.w + b4.w;
    *(uint2*)(y + (size_t)row*C_ + 4*tid) = make_uint2(pack_bf16(o0,o1), pack_bf16(o2,o3));
}

// ---------------- GEMM 128x128x32, 4 warps, warp tile 64x64, 4-stage ----------------
#define GA_ROWB   80
#define GB_ROWB   272
#define GA_BYTES  (128*GA_ROWB)
#define GB_BYTES  (32*GB_ROWB)
#define STAGE_B   (GA_BYTES + GB_BYTES)
#define NSTAGE    4
#define GEMM_SMEM (NSTAGE*STAGE_B)

template<int MODE, int OBF>
__global__ void __launch_bounds__(128) bgemm_kernel(
    const __nv_bfloat16* __restrict__ A, const __nv_bfloat16* __restrict__ Bw,
    const float* __restrict__ bias,
    const float* __restrict__ resid, const float* __restrict__ gamma,
    void* __restrict__ CoutV, int M, int N, int K)
{
    extern __shared__ char gsm[];
    const u32 smb = (u32)__cvta_generic_to_shared(gsm);

    const int tid  = threadIdx.x;
    const int lane = tid & 31, warp = tid >> 5;
    const int warp_m = warp >> 1, warp_n = warp & 1;
    const int m_blk = blockIdx.y << 7, n_blk = blockIdx.x << 7;

    const int ar = tid >> 2, ac = tid & 3;
    const int br = tid >> 4, bc = tid & 15;
    const __nv_bfloat16* Ag = A  + (size_t)(m_blk + ar) * K + ac*8;
    const __nv_bfloat16* Bg = Bw + (size_t)br * N + n_blk + bc*8;
    const u32 dA0 = smb + ar*GA_ROWB + ac*16;
    const u32 dB0 = smb + GA_BYTES + br*GB_ROWB + bc*16;

    const int g  = lane >> 3;
    const int r8 = lane & 7;
    const u32 aAddr0 = smb + (u32)(warp_m*64 + r8 + (g&1)*8) * GA_ROWB + (u32)((g>>1)*16);
    const u32 bAddr0 = smb + GA_BYTES + (u32)(r8 + (g&1)*8) * GB_ROWB
                           + (u32)(warp_n*64 + (g>>1)*8) * 2;

    float acc[4][8][4];
#pragma unroll
    for (int mt = 0; mt < 4; mt++)
#pragma unroll
        for (int nt = 0; nt < 8; nt++)
#pragma unroll
            for (int i = 0; i < 4; i++) acc[mt][nt][i] = 0.f;

    const int nk = K >> 5;

    auto issue = [&](int kt) {
        const u32 sb = (kt & (NSTAGE-1)) * STAGE_B;
        const __nv_bfloat16* Ak = Ag + (kt << 5);
        const __nv_bfloat16* Bk = Bg + (size_t)(kt << 5) * N;
#pragma unroll
        for (int p = 0; p < 4; p++)
            cp16(dA0 + sb + p*32*GA_ROWB, Ak + (size_t)(p*32)*K);
#pragma unroll
        for (int p = 0; p < 4; p++)
            cp16(dB0 + sb + p*8*GB_ROWB,  Bk + (size_t)(p*8)*N);
        cp_commit();
    };

    issue(0);
    if (nk > 1) issue(1);
    if (nk > 2) issue(2);

    for (int kt = 0; kt < nk; kt++) {
        if      (kt + 2 < nk) asm volatile("cp.async.wait_group 2;");
        else if (kt + 1 < nk) asm volatile("cp.async.wait_group 1;");
        else                  asm volatile("cp.async.wait_group 0;");
        __syncthreads();

        if (kt + 3 < nk) issue(kt + 3);

        const u32 sb = (kt & (NSTAGE-1)) * STAGE_B;
        const u32 aB = aAddr0 + sb;
        const u32 bB = bAddr0 + sb;
#pragma unroll
        for (int ks = 0; ks < 2; ks++) {
            u32 af[4][4];
#pragma unroll
            for (int mt = 0; mt < 4; mt++)
                ldsm_x4(af[mt][0], af[mt][1], af[mt][2], af[mt][3],
                        aB + (u32)(mt*16) * GA_ROWB + (u32)(ks*32));
#pragma unroll
            for (int np = 0; np < 4; np++) {
                u32 b0, b1, b2, b3;
                ldsm_x4_t(b0, b1, b2, b3,
                          bB + (u32)(ks*16) * GB_ROWB + (u32)(np*32));
#pragma unroll
                for (int mt = 0; mt < 4; mt++) {
                    mma_bf16(acc[mt][2*np],   af[mt], b0, b1);
                    mma_bf16(acc[mt][2*np+1], af[mt], b2, b3);
                }
            }
        }
    }

    const int rr = lane >> 2, cc = (lane & 3) << 1;
    const int row0 = m_blk + warp_m * 64;
    const int col0 = n_blk + warp_n * 64;
#pragma unroll
    for (int mt = 0; mt < 4; mt++) {
#pragma unroll
        for (int nt = 0; nt < 8; nt++) {
            const int col = col0 + nt * 8 + cc;
            float2 b2 = *(const float2*)(bias + col);
            float2 g2 = make_float2(0.f, 0.f);
            if (MODE == 1) g2 = *(const float2*)(gamma + col);
#pragma unroll
            for (int half = 0; half < 2; half++) {
                const int row = row0 + mt * 16 + rr + half * 8;
                const size_t off = (size_t)row * N + col;
                float v0 = acc[mt][nt][half*2 + 0] + b2.x;
                float v1 = acc[mt][nt][half*2 + 1] + b2.y;
                if (MODE == 1) {
                    float2 rv = *(const float2*)(resid + off);
                    v0 = rv.x + g2.x * v0;
                    v1 = rv.y + g2.y * v1;
                } else if (MODE == 2) {
                    v0 = 0.5f * v0 * (1.0f + erff(v0 * 0.70710678118654752f));
                    v1 = 0.5f * v1 * (1.0f + erff(v1 * 0.70710678118654752f));
                }
                if (OBF) *(u32*)((__nv_bfloat16*)CoutV + off) = pack_bf16(v0, v1);
                else     *(float2*)((float*)CoutV + off) = make_float2(v0, v1);
            }
        }
    }
}

// ---------------- Flash attention: 128 queries/CTA, 8 warps, 3-buffer KV ----------------
#define KV_ROWB  144
#define QTILE_B  (128*KV_ROWB)
#define KVTILE_B (64*KV_ROWB)
#define SQ_OFF   0
#define SK_OFF   (QTILE_B)
#define SV_OFF   (QTILE_B + 3*KVTILE_B)
#define SMSK_OFF (QTILE_B + 6*KVTILE_B)
#define ATTN_SMEM (SMSK_OFF + 3*64*4)

__device__ __forceinline__ void attn_issue_kv(const __nv_bfloat16* __restrict__ qkv,
                                              u32 smb, int buf, int kt, int b, int h, int tid)
{
    const __nv_bfloat16* gK = qkv + ((size_t)(b*T_) + kt*64) * C3 + C_ + h*D_;
    const __nv_bfloat16* gV = gK + C_;
    u32 dK = smb + SK_OFF + buf*KVTILE_B;
    u32 dV = smb + SV_OFF + buf*KVTILE_B;
#pragma unroll
    for (int k = 0; k < 2; k++) {
        int c = tid + k*256;
        int row = c >> 3, col16 = c & 7;
        cp16(dK + row*KV_ROWB + col16*16, gK + (size_t)row*C3 + col16*8);
        cp16(dV + row*KV_ROWB + col16*16, gV + (size_t)row*C3 + col16*8);
    }
}

__global__ void __launch_bounds__(256, 2) attn_kernel(
    const __nv_bfloat16* __restrict__ qkv, const int* __restrict__ mask,
    __nv_bfloat16* __restrict__ Out)
{
    extern __shared__ char attn_sm[];
    u32 smb = (u32)__cvta_generic_to_shared(attn_sm);
    float* sMask = (float*)(attn_sm + SMSK_OFF);

    const int tid = threadIdx.x;
    const int lane = tid & 31, warp = tid >> 5;
    const int b = blockIdx.z, h = blockIdx.y;
    const int q0 = blockIdx.x << 7;
    const int g = lane >> 3, r8 = lane & 7;
    const int qd = lane >> 2, qi = lane & 3;

    {
        const __nv_bfloat16* gQ = qkv + ((size_t)(b*T_ + q0)) * C3 + h*D_;
#pragma unroll
        for (int k = 0; k < 4; k++) {
            int c = tid + k*256;
            int row = c >> 3, col16 = c & 7;
            cp16(smb + SQ_OFF + row*KV_ROWB + col16*16, gQ + (size_t)row*C3 + col16*8);
        }
        attn_issue_kv(qkv, smb, 0, 0, b, h, tid);
        if (tid < 64) sMask[tid] = mask[b*T_ + tid] ? 0.f : -1e30f;
        cp_commit();
    }

    float ofrag[8][4];
#pragma unroll
    for (int nt = 0; nt < 8; nt++)
#pragma unroll
        for (int i = 0; i < 4; i++) ofrag[nt][i] = 0.f;
    float mrow0 = -1e30f, mrow1 = -1e30f, lrow0 = 0.f, lrow1 = 0.f;
    u32 qf[4][4];

    const int NKT = T_ / 64;
    for (int kt = 0; kt < NKT; kt++) {
        const int cur = kt % 3;
        if (kt + 1 < NKT) {
            const int nbuf = (kt + 1) % 3;
            attn_issue_kv(qkv, smb, nbuf, kt + 1, b, h, tid);
            if (tid < 64) sMask[nbuf*64 + tid] = mask[b*T_ + (kt+1)*64 + tid] ? 0.f : -1e30f;
            cp_commit();
            asm volatile("cp.async.wait_group 1;");
        } else {
            asm volatile("cp.async.wait_group 0;");
        }
        __syncthreads();

        if (kt == 0) {
#pragma unroll
            for (int ks = 0; ks < 4; ks++) {
                u32 addr = smb + SQ_OFF
                         + (u32)(warp*16 + r8 + (g&1)*8) * KV_ROWB
                         + (u32)(ks*16 + (g>>1)*8) * 2;
                ldsm_x4(qf[ks][0], qf[ks][1], qf[ks][2], qf[ks][3], addr);
            }
        }

        float sfrag[8][4];
#pragma unroll
        for (int nt = 0; nt < 8; nt++)
#pragma unroll
            for (int i = 0; i < 4; i++) sfrag[nt][i] = 0.f;
        const u32 kBase = smb + SK_OFF + cur*KVTILE_B;
#pragma unroll
        for (int ks = 0; ks < 4; ks++) {
#pragma unroll
            for (int np = 0; np < 4; np++) {
                u32 k0, k1, k2, k3;
                u32 addr = kBase + (u32)(np*16 + (g>>1)*8 + r8) * KV_ROWB
                                 + (u32)(ks*16 + (g&1)*8) * 2;
                ldsm_x4(k0, k1, k2, k3, addr);
                mma_bf16(sfrag[2*np],   qf[ks], k0, k1);
                mma_bf16(sfrag[2*np+1], qf[ks], k2, k3);
            }
        }

        // ---- mask + scale + row max ----
        const float* msk = sMask + cur*64;
        float mx0 = -1e30f, mx1 = -1e30f;
#pragma unroll
        for (int nt = 0; nt < 8; nt++) {
            float2 am = *(const float2*)(msk + nt*8 + 2*qi);
            sfrag[nt][0] = fmaf(sfrag[nt][0], 0.125f, am.x);
            sfrag[nt][1] = fmaf(sfrag[nt][1], 0.125f, am.y);
            sfrag[nt][2] = fmaf(sfrag[nt][2], 0.125f, am.x);
            sfrag[nt][3] = fmaf(sfrag[nt][3], 0.125f, am.y);
            mx0 = fmaxf(mx0, fmaxf(sfrag[nt][0], sfrag[nt][1]));
            mx1 = fmaxf(mx1, fmaxf(sfrag[nt][2], sfrag[nt][3]));
        }
        mx0 = fmaxf(mx0, __shfl_xor_sync(~0u, mx0, 1));
        mx0 = fmaxf(mx0, __shfl_xor_sync(~0u, mx0, 2));
        mx1 = fmaxf(mx1, __shfl_xor_sync(~0u, mx1, 1));
        mx1 = fmaxf(mx1, __shfl_xor_sync(~0u, mx1, 2));
        float mnew0 = fmaxf(mrow0, mx0), mnew1 = fmaxf(mrow1, mx1);
        float cor0 = fexp(mrow0 - mnew0), cor1 = fexp(mrow1 - mnew1);
        mrow0 = mnew0; mrow1 = mnew1;

        // ---- exp + per-thread partial sums ----
        float ps0 = 0.f, ps1 = 0.f;
#pragma unroll
        for (int nt = 0; nt < 8; nt++) {
            sfrag[nt][0] = fexp(sfrag[nt][0] - mnew0);
            sfrag[nt][1] = fexp(sfrag[nt][1] - mnew0);
            sfrag[nt][2] = fexp(sfrag[nt][2] - mnew1);
            sfrag[nt][3] = fexp(sfrag[nt][3] - mnew1);
            ps0 += sfrag[nt][0] + sfrag[nt][1];
            ps1 += sfrag[nt][2] + sfrag[nt][3];
        }

        // ---- rescale O, then launch PV mma (sum shuffles hidden under it) ----
#pragma unroll
        for (int nt = 0; nt < 8; nt++) {
            ofrag[nt][0] *= cor0; ofrag[nt][1] *= cor0;
            ofrag[nt][2] *= cor1; ofrag[nt][3] *= cor1;
        }
        const u32 vBase = smb + SV_OFF + cur*KVTILE_B;
#pragma unroll
        for (int kk = 0; kk < 4; kk++) {
            u32 a[4];
            a[0] = pack_bf16(sfrag[2*kk][0],   sfrag[2*kk][1]);
            a[1] = pack_bf16(sfrag[2*kk][2],   sfrag[2*kk][3]);
            a[2] = pack_bf16(sfrag[2*kk+1][0], sfrag[2*kk+1][1]);
            a[3] = pack_bf16(sfrag[2*kk+1][2], sfrag[2*kk+1][3]);
#pragma unroll
            for (int dp = 0; dp < 4; dp++) {
                u32 v0, v1, v2, v3;
                u32 addr = vBase + (u32)(kk*16 + r8 + (g&1)*8) * KV_ROWB
                                 + (u32)(dp*16 + (g>>1)*8) * 2;
                ldsm_x4_t(v0, v1, v2, v3, addr);
                mma_bf16(ofrag[2*dp],   a, v0, v1);
                mma_bf16(ofrag[2*dp+1], a, v2, v3);
            }
        }

        // ---- deferred sum reduction + l update ----
        ps0 += __shfl_xor_sync(~0u, ps0, 1);
        ps0 += __shfl_xor_sync(~0u, ps0, 2);
        ps1 += __shfl_xor_sync(~0u, ps1, 1);
        ps1 += __shfl_xor_sync(~0u, ps1, 2);
        lrow0 = lrow0 * cor0 + ps0;
        lrow1 = lrow1 * cor1 + ps1;
        // no trailing __syncthreads: 3-deep ring makes next prefetch safe
    }

    const float inv0 = 1.0f / lrow0, inv1 = 1.0f / lrow1;
    const int r0 = q0 + warp*16 + qd;
    const int r1 = r0 + 8;
    __nv_bfloat16* o0 = Out + (size_t)(b*T_ + r0) * C_ + h*D_ + 2*qi;
    __nv_bfloat16* o1 = Out + (size_t)(b*T_ + r1) * C_ + h*D_ + 2*qi;
#pragma unroll
    for (int nt = 0; nt < 8; nt++) {
        *(u32*)(o0 + nt*8) = pack_bf16(ofrag[nt][0]*inv0, ofrag[nt][1]*inv0);
        *(u32*)(o1 + nt*8) = pack_bf16(ofrag[nt][2]*inv1, ofrag[nt][3]*inv1);
    }
}

// ---------------- host launcher ----------------
extern "C" void kernel_launch(void* const* d_in, const int* in_sizes, int n_in,
                              void* d_out, int out_size)
{
    const float* x    = (const float*)d_in[0];
    const int*   mask = (const int*)  d_in[1];
    const float* ln1w = (const float*)d_in[2];
    const float* ln1b = (const float*)d_in[3];
    const float* ln2w = (const float*)d_in[4];
    const float* ln2b = (const float*)d_in[5];
    const float* qw   = (const float*)d_in[6];
    const float* qb   = (const float*)d_in[7];
    const float* kw   = (const float*)d_in[8];
    const float* kb   = (const float*)d_in[9];
    const float* vw   = (const float*)d_in[10];
    const float* vb   = (const float*)d_in[11];
    const float* ow   = (const float*)d_in[12];
    const float* ob   = (const float*)d_in[13];
    const float* f1w  = (const float*)d_in[14];
    const float* f1b  = (const float*)d_in[15];
    const float* f2w  = (const float*)d_in[16];
    const float* f2b  = (const float*)d_in[17];
    const float* gm1  = (const float*)d_in[18];
    const float* gm2  = (const float*)d_in[19];
    float* out = (float*)d_out;

    __nv_bfloat16 *b_h, *b_h2, *b_qkv, *b_att, *b_f1, *b_wqkv, *b_wo, *b_wf1, *b_wf2;
    float *b_x1, *b_bqkv;
    cudaGetSymbolAddress((void**)&b_h,    g_hb);
    cudaGetSymbolAddress((void**)&b_h2,   g_h2b);
    cudaGetSymbolAddress((void**)&b_qkv,  g_qkv);
    cudaGetSymbolAddress((void**)&b_att,  g_attb);
    cudaGetSymbolAddress((void**)&b_f1,   g_f1b);
    cudaGetSymbolAddress((void**)&b_x1,   g_x1);
    cudaGetSymbolAddress((void**)&b_wqkv, g_wqkv);
    cudaGetSymbolAddress((void**)&b_wo,   g_wo);
    cudaGetSymbolAddress((void**)&b_wf1,  g_wf1);
    cudaGetSymbolAddress((void**)&b_wf2,  g_wf2);
    cudaGetSymbolAddress((void**)&b_bqkv, g_bqkv);

    cudaFuncSetAttribute(attn_kernel,
                         cudaFuncAttributeMaxDynamicSharedMemorySize, ATTN_SMEM);
    cudaFuncSetAttribute(bgemm_kernel<0,1>,
                         cudaFuncAttributeMaxDynamicSharedMemorySize, GEMM_SMEM);
    cudaFuncSetAttribute(bgemm_kernel<1,0>,
                         cudaFuncAttributeMaxDynamicSharedMemorySize, GEMM_SMEM);
    cudaFuncSetAttribute(bgemm_kernel<2,1>,
                         cudaFuncAttributeMaxDynamicSharedMemorySize, GEMM_SMEM);

    cvt_all_kernel<<<2048, 256>>>(qw, kw, vw, qb, kb, vb, ow, f1w, f2w);

    dim3 gridQKV(C3 / 128, NTOK / 128);
    dim3 gridC  (C_ / 128, NTOK / 128);
    dim3 gridF  (DFF / 128, NTOK / 128);

    ln_kernel<<<NTOK, 256>>>(x, ln1w, ln1b, b_h);
    bgemm_kernel<0,1><<<gridQKV, 128, GEMM_SMEM>>>(b_h, b_wqkv, b_bqkv, nullptr, nullptr, b_qkv, NTOK, C3, C_);
    attn_kernel<<<dim3(T_/128, H_, B_), 256, ATTN_SMEM>>>(b_qkv, mask, b_att);
    bgemm_kernel<1,0><<<gridC, 128, GEMM_SMEM>>>(b_att, b_wo, ob, x, gm1, b_x1, NTOK, C_, C_);
    ln_kernel<<<NTOK, 256>>>(b_x1, ln2w, ln2b, b_h2);
    bgemm_kernel<2,1><<<gridF, 128, GEMM_SMEM>>>(b_h2, b_wf1, f1b, nullptr, nullptr, b_f1, NTOK, DFF, C_);
    bgemm_kernel<1,0><<<gridC, 128, GEMM_SMEM>>>(b_f1, b_wf2, f2b, b_x1, gm2, out, NTOK, C_, DFF);
}

// round 16
// speedup vs baseline: 1.2924x; 1.0077x over previous
#include <cuda_runtime.h>
#include <cuda_bf16.h>
#include <cstdint>
#include <math.h>

typedef unsigned int u32;

#define B_   2
#define T_   2048
#define C_   1024
#define H_   16
#define D_   64
#define NTOK (B_*T_)
#define DFF  4096
#define C3   (3*C_)

// ---------------- scratch (no allocation allowed) ----------------
__device__ __nv_bfloat16 g_hb  [NTOK*C_];
__device__ __nv_bfloat16 g_h2b [NTOK*C_];
__device__ __nv_bfloat16 g_qkv [NTOK*C3];
__device__ __nv_bfloat16 g_attb[NTOK*C_];
__device__ __nv_bfloat16 g_f1b [(size_t)NTOK*DFF];
__device__ float         g_x1  [NTOK*C_];
__device__ __nv_bfloat16 g_wqkv[C_*C3];
__device__ __nv_bfloat16 g_wo  [C_*C_];
__device__ __nv_bfloat16 g_wf1 [C_*DFF];
__device__ __nv_bfloat16 g_wf2 [DFF*C_];
__device__ float         g_bqkv[C3];

// ---------------- small helpers ----------------
__device__ __forceinline__ u32 pack_bf16(float x, float y) {
    __nv_bfloat162 t = __floats2bfloat162_rn(x, y);
    u32 r; memcpy(&r, &t, 4); return r;
}
__device__ __forceinline__ void cp16(u32 sdst, const void* gsrc) {
    asm volatile("cp.async.cg.shared.global [%0], [%1], 16;" :: "r"(sdst), "l"(gsrc));
}
__device__ __forceinline__ void cp_commit() { asm volatile("cp.async.commit_group;"); }
__device__ __forceinline__ void ldsm_x4(u32& r0, u32& r1, u32& r2, u32& r3, u32 addr) {
    asm volatile("ldmatrix.sync.aligned.m8n8.x4.shared.b16 {%0,%1,%2,%3},[%4];"
                 : "=r"(r0), "=r"(r1), "=r"(r2), "=r"(r3) : "r"(addr));
}
__device__ __forceinline__ void ldsm_x4_t(u32& r0, u32& r1, u32& r2, u32& r3, u32 addr) {
    asm volatile("ldmatrix.sync.aligned.m8n8.x4.trans.shared.b16 {%0,%1,%2,%3},[%4];"
                 : "=r"(r0), "=r"(r1), "=r"(r2), "=r"(r3) : "r"(addr));
}
__device__ __forceinline__ void mma_bf16(float* c, const u32* a, u32 b0, u32 b1) {
    asm volatile("mma.sync.aligned.m16n8k16.row.col.f32.bf16.bf16.f32 "
                 "{%0,%1,%2,%3},{%4,%5,%6,%7},{%8,%9},{%0,%1,%2,%3};"
                 : "+f"(c[0]), "+f"(c[1]), "+f"(c[2]), "+f"(c[3])
                 : "r"(a[0]), "r"(a[1]), "r"(a[2]), "r"(a[3]), "r"(b0), "r"(b1));
}
// FFMA-only exp: no MUFU, no FRND/F2I. Magic 12582912 = 1.5*2^23.
// Deg-3 Taylor: rel err ~6e-4 (invisible after bf16 rounding of P).
__device__ __forceinline__ float fexp(float x) {
    x = fmaxf(x, -80.0f);
    float y  = fmaf(x, 1.4426950408889634f, 12582912.0f);
    int  ki  = __float_as_int(y);
    float kf = y - 12582912.0f;
    float t  = fmaf(kf, -0.6931471805599453f, x);
    float p  = fmaf(t, fmaf(t, fmaf(t, 0.16666667f, 0.5f), 1.0f), 1.0f);
    return __int_as_float(__float_as_int(p) + (ki << 23));
}

// ---------------- single fused weight conversion ----------------
__global__ void cvt_all_kernel(const float* __restrict__ qw, const float* __restrict__ kw,
                               const float* __restrict__ vw, const float* __restrict__ qb,
                               const float* __restrict__ kb, const float* __restrict__ vb,
                               const float* __restrict__ ow, const float* __restrict__ f1w,
                               const float* __restrict__ f2w)
{
    int gtid = blockIdx.x * blockDim.x + threadIdx.x;
    int stride = gridDim.x * blockDim.x;
    const int n_qkv = C_*C_/4;
    const int n_o   = C_*C_/4;
    const int n_f   = C_*DFF/4;
    for (int i = gtid; i < n_qkv; i += stride) {
        int c = i / (C_/4), j = (i % (C_/4)) * 4;
        float4 q4 = *(const float4*)(qw + (size_t)c*C_ + j);
        float4 k4 = *(const float4*)(kw + (size_t)c*C_ + j);
        float4 v4 = *(const float4*)(vw + (size_t)c*C_ + j);
        *(uint2*)(g_wqkv + (size_t)c*C3 + j)        = make_uint2(pack_bf16(q4.x,q4.y), pack_bf16(q4.z,q4.w));
        *(uint2*)(g_wqkv + (size_t)c*C3 + C_ + j)   = make_uint2(pack_bf16(k4.x,k4.y), pack_bf16(k4.z,k4.w));
        *(uint2*)(g_wqkv + (size_t)c*C3 + 2*C_ + j) = make_uint2(pack_bf16(v4.x,v4.y), pack_bf16(v4.z,v4.w));
    }
    for (int i = gtid; i < n_o; i += stride) {
        float4 s = *(const float4*)(ow + (size_t)i*4);
        *(uint2*)(g_wo + (size_t)i*4) = make_uint2(pack_bf16(s.x,s.y), pack_bf16(s.z,s.w));
    }
    for (int i = gtid; i < n_f; i += stride) {
        float4 s = *(const float4*)(f1w + (size_t)i*4);
        *(uint2*)(g_wf1 + (size_t)i*4) = make_uint2(pack_bf16(s.x,s.y), pack_bf16(s.z,s.w));
    }
    for (int i = gtid; i < n_f; i += stride) {
        float4 s = *(const float4*)(f2w + (size_t)i*4);
        *(uint2*)(g_wf2 + (size_t)i*4) = make_uint2(pack_bf16(s.x,s.y), pack_bf16(s.z,s.w));
    }
    if (gtid < C_) {
        g_bqkv[gtid]        = qb[gtid];
        g_bqkv[C_ + gtid]   = kb[gtid];
        g_bqkv[2*C_ + gtid] = vb[gtid];
    }
}

// ---------------- LayerNorm: fp32 in -> bf16 out ----------------
__global__ void __launch_bounds__(256) ln_kernel(const float* __restrict__ x,
                                                 const float* __restrict__ w,
                                                 const float* __restrict__ b,
                                                 __nv_bfloat16* __restrict__ y)
{
    __shared__ float red[8];
    int row = blockIdx.x, tid = threadIdx.x;
    const float* xr = x + (size_t)row * C_;
    float4 v = *(const float4*)(xr + 4*tid);

    float s = v.x + v.y + v.z + v.w;
#pragma unroll
    for (int o = 16; o > 0; o >>= 1) s += __shfl_xor_sync(~0u, s, o);
    if ((tid & 31) == 0) red[tid >> 5] = s;
    __syncthreads();
    if (tid < 32) {
        float t = (tid < 8) ? red[tid] : 0.f;
#pragma unroll
        for (int o = 4; o > 0; o >>= 1) t += __shfl_xor_sync(~0u, t, o);
        if (tid == 0) red[0] = t;
    }
    __syncthreads();
    float mu = red[0] * (1.0f / C_);
    __syncthreads();

    float dx = v.x-mu, dy = v.y-mu, dz = v.z-mu, dw = v.w-mu;
    float sq = dx*dx + dy*dy + dz*dz + dw*dw;
#pragma unroll
    for (int o = 16; o > 0; o >>= 1) sq += __shfl_xor_sync(~0u, sq, o);
    if ((tid & 31) == 0) red[tid >> 5] = sq;
    __syncthreads();
    if (tid < 32) {
        float t = (tid < 8) ? red[tid] : 0.f;
#pragma unroll
        for (int o = 4; o > 0; o >>= 1) t += __shfl_xor_sync(~0u, t, o);
        if (tid == 0) red[0] = t;
    }
    __syncthreads();
    float rs = rsqrtf(red[0] * (1.0f / C_) + 1e-5f);
    float4 w4 = *(const float4*)(w + 4*tid);
    float4 b4 = *(const float4*)(b + 4*tid);
    float o0 = dx*rs*w4.x + b4.x, o1 = dy*rs*w4.y + b4.y;
    float o2 = dz*rs*w4.z + b4.z, o3 = dw*rs*w4.w + b4.w;
    *(uint2*)(y + (size_t)row*C_ + 4*tid) = make_uint2(pack_bf16(o0,o1), pack_bf16(o2,o3));
}

// ---------------- GEMM 128x128x32, 4 warps, warp tile 64x64, 4-stage ----------------
#define GA_ROWB   80
#define GB_ROWB   272
#define GA_BYTES  (128*GA_ROWB)
#define GB_BYTES  (32*GB_ROWB)
#define STAGE_B   (GA_BYTES + GB_BYTES)
#define NSTAGE    4
#define GEMM_SMEM (NSTAGE*STAGE_B)

template<int MODE, int OBF>
__global__ void __launch_bounds__(128) bgemm_kernel(
    const __nv_bfloat16* __restrict__ A, const __nv_bfloat16* __restrict__ Bw,
    const float* __restrict__ bias,
    const float* __restrict__ resid, const float* __restrict__ gamma,
    void* __restrict__ CoutV, int M, int N, int K)
{
    extern __shared__ char gsm[];
    const u32 smb = (u32)__cvta_generic_to_shared(gsm);

    const int tid  = threadIdx.x;
    const int lane = tid & 31, warp = tid >> 5;
    const int warp_m = warp >> 1, warp_n = warp & 1;
    const int m_blk = blockIdx.y << 7, n_blk = blockIdx.x << 7;

    const int ar = tid >> 2, ac = tid & 3;
    const int br = tid >> 4, bc = tid & 15;
    const __nv_bfloat16* Ag = A  + (size_t)(m_blk + ar) * K + ac*8;
    const __nv_bfloat16* Bg = Bw + (size_t)br * N + n_blk + bc*8;
    const u32 dA0 = smb + ar*GA_ROWB + ac*16;
    const u32 dB0 = smb + GA_BYTES + br*GB_ROWB + bc*16;

    const int g  = lane >> 3;
    const int r8 = lane & 7;
    const u32 aAddr0 = smb + (u32)(warp_m*64 + r8 + (g&1)*8) * GA_ROWB + (u32)((g>>1)*16);
    const u32 bAddr0 = smb + GA_BYTES + (u32)(r8 + (g&1)*8) * GB_ROWB
                           + (u32)(warp_n*64 + (g>>1)*8) * 2;

    float acc[4][8][4];
#pragma unroll
    for (int mt = 0; mt < 4; mt++)
#pragma unroll
        for (int nt = 0; nt < 8; nt++)
#pragma unroll
            for (int i = 0; i < 4; i++) acc[mt][nt][i] = 0.f;

    const int nk = K >> 5;

    auto issue = [&](int kt) {
        const u32 sb = (kt & (NSTAGE-1)) * STAGE_B;
        const __nv_bfloat16* Ak = Ag + (kt << 5);
        const __nv_bfloat16* Bk = Bg + (size_t)(kt << 5) * N;
#pragma unroll
        for (int p = 0; p < 4; p++)
            cp16(dA0 + sb + p*32*GA_ROWB, Ak + (size_t)(p*32)*K);
#pragma unroll
        for (int p = 0; p < 4; p++)
            cp16(dB0 + sb + p*8*GB_ROWB,  Bk + (size_t)(p*8)*N);
        cp_commit();
    };

    issue(0);
    if (nk > 1) issue(1);
    if (nk > 2) issue(2);

    for (int kt = 0; kt < nk; kt++) {
        if      (kt + 2 < nk) asm volatile("cp.async.wait_group 2;");
        else if (kt + 1 < nk) asm volatile("cp.async.wait_group 1;");
        else                  asm volatile("cp.async.wait_group 0;");
        __syncthreads();

        if (kt + 3 < nk) issue(kt + 3);

        const u32 sb = (kt & (NSTAGE-1)) * STAGE_B;
        const u32 aB = aAddr0 + sb;
        const u32 bB = bAddr0 + sb;
#pragma unroll
        for (int ks = 0; ks < 2; ks++) {
            u32 af[4][4];
#pragma unroll
            for (int mt = 0; mt < 4; mt++)
                ldsm_x4(af[mt][0], af[mt][1], af[mt][2], af[mt][3],
                        aB + (u32)(mt*16) * GA_ROWB + (u32)(ks*32));
#pragma unroll
            for (int np = 0; np < 4; np++) {
                u32 b0, b1, b2, b3;
                ldsm_x4_t(b0, b1, b2, b3,
                          bB + (u32)(ks*16) * GB_ROWB + (u32)(np*32));
#pragma unroll
                for (int mt = 0; mt < 4; mt++) {
                    mma_bf16(acc[mt][2*np],   af[mt], b0, b1);
                    mma_bf16(acc[mt][2*np+1], af[mt], b2, b3);
                }
            }
        }
    }

    const int rr = lane >> 2, cc = (lane & 3) << 1;
    const int row0 = m_blk + warp_m * 64;
    const int col0 = n_blk + warp_n * 64;
#pragma unroll
    for (int mt = 0; mt < 4; mt++) {
#pragma unroll
        for (int nt = 0; nt < 8; nt++) {
            const int col = col0 + nt * 8 + cc;
            float2 b2 = *(const float2*)(bias + col);
            float2 g2 = make_float2(0.f, 0.f);
            if (MODE == 1) g2 = *(const float2*)(gamma + col);
#pragma unroll
            for (int half = 0; half < 2; half++) {
                const int row = row0 + mt * 16 + rr + half * 8;
                const size_t off = (size_t)row * N + col;
                float v0 = acc[mt][nt][half*2 + 0] + b2.x;
                float v1 = acc[mt][nt][half*2 + 1] + b2.y;
                if (MODE == 1) {
                    float2 rv = *(const float2*)(resid + off);
                    v0 = rv.x + g2.x * v0;
                    v1 = rv.y + g2.y * v1;
                } else if (MODE == 2) {
                    v0 = 0.5f * v0 * (1.0f + erff(v0 * 0.70710678118654752f));
                    v1 = 0.5f * v1 * (1.0f + erff(v1 * 0.70710678118654752f));
                }
                if (OBF) *(u32*)((__nv_bfloat16*)CoutV + off) = pack_bf16(v0, v1);
                else     *(float2*)((float*)CoutV + off) = make_float2(v0, v1);
            }
        }
    }
}

// ---------------- Flash attention: 128 queries/CTA, 8 warps, 3-buffer KV ----------------
// Full mask row (T_ floats, 8KB) hoisted into smem once per CTA.
#define KV_ROWB  144
#define QTILE_B  (128*KV_ROWB)
#define KVTILE_B (64*KV_ROWB)
#define SQ_OFF   0
#define SK_OFF   (QTILE_B)
#define SV_OFF   (QTILE_B + 3*KVTILE_B)
#define SMSK_OFF (QTILE_B + 6*KVTILE_B)
#define ATTN_SMEM (SMSK_OFF + T_*4)

__device__ __forceinline__ void attn_issue_kv(const __nv_bfloat16* __restrict__ qkv,
                                              u32 smb, int buf, int kt, int b, int h, int tid)
{
    const __nv_bfloat16* gK = qkv + ((size_t)(b*T_) + kt*64) * C3 + C_ + h*D_;
    const __nv_bfloat16* gV = gK + C_;
    u32 dK = smb + SK_OFF + buf*KVTILE_B;
    u32 dV = smb + SV_OFF + buf*KVTILE_B;
#pragma unroll
    for (int k = 0; k < 2; k++) {
        int c = tid + k*256;
        int row = c >> 3, col16 = c & 7;
        cp16(dK + row*KV_ROWB + col16*16, gK + (size_t)row*C3 + col16*8);
        cp16(dV + row*KV_ROWB + col16*16, gV + (size_t)row*C3 + col16*8);
    }
}

__global__ void __launch_bounds__(256, 2) attn_kernel(
    const __nv_bfloat16* __restrict__ qkv, const int* __restrict__ mask,
    __nv_bfloat16* __restrict__ Out)
{
    extern __shared__ char attn_sm[];
    u32 smb = (u32)__cvta_generic_to_shared(attn_sm);
    float* sMask = (float*)(attn_sm + SMSK_OFF);

    const int tid = threadIdx.x;
    const int lane = tid & 31, warp = tid >> 5;
    const int b = blockIdx.z, h = blockIdx.y;
    const int q0 = blockIdx.x << 7;
    const int g = lane >> 3, r8 = lane & 7;
    const int qd = lane >> 2, qi = lane & 3;

    {
        const __nv_bfloat16* gQ = qkv + ((size_t)(b*T_ + q0)) * C3 + h*D_;
#pragma unroll
        for (int k = 0; k < 4; k++) {
            int c = tid + k*256;
            int row = c >> 3, col16 = c & 7;
            cp16(smb + SQ_OFF + row*KV_ROWB + col16*16, gQ + (size_t)row*C3 + col16*8);
        }
        attn_issue_kv(qkv, smb, 0, 0, b, h, tid);
        // hoist full mask row into smem (once)
#pragma unroll
        for (int k = 0; k < T_/256; k++) {
            int idx = tid + k*256;
            sMask[idx] = mask[b*T_ + idx] ? 0.f : -1e30f;
        }
        cp_commit();
    }
    __syncthreads();   // mask visible to all warps

    float ofrag[8][4];
#pragma unroll
    for (int nt = 0; nt < 8; nt++)
#pragma unroll
        for (int i = 0; i < 4; i++) ofrag[nt][i] = 0.f;
    float mrow0 = -1e30f, mrow1 = -1e30f, lrow0 = 0.f, lrow1 = 0.f;
    u32 qf[4][4];

    const int NKT = T_ / 64;
    for (int kt = 0; kt < NKT; kt++) {
        const int cur = kt % 3;
        if (kt + 1 < NKT) {
            attn_issue_kv(qkv, smb, (kt + 1) % 3, kt + 1, b, h, tid);
            cp_commit();
            asm volatile("cp.async.wait_group 1;");
        } else {
            asm volatile("cp.async.wait_group 0;");
        }
        __syncthreads();

        if (kt == 0) {
#pragma unroll
            for (int ks = 0; ks < 4; ks++) {
                u32 addr = smb + SQ_OFF
                         + (u32)(warp*16 + r8 + (g&1)*8) * KV_ROWB
                         + (u32)(ks*16 + (g>>1)*8) * 2;
                ldsm_x4(qf[ks][0], qf[ks][1], qf[ks][2], qf[ks][3], addr);
            }
        }

        float sfrag[8][4];
#pragma unroll
        for (int nt = 0; nt < 8; nt++)
#pragma unroll
            for (int i = 0; i < 4; i++) sfrag[nt][i] = 0.f;
        const u32 kBase = smb + SK_OFF + cur*KVTILE_B;
#pragma unroll
        for (int ks = 0; ks < 4; ks++) {
#pragma unroll
            for (int np = 0; np < 4; np++) {
                u32 k0, k1, k2, k3;
                u32 addr = kBase + (u32)(np*16 + (g>>1)*8 + r8) * KV_ROWB
                                 + (u32)(ks*16 + (g&1)*8) * 2;
                ldsm_x4(k0, k1, k2, k3, addr);
                mma_bf16(sfrag[2*np],   qf[ks], k0, k1);
                mma_bf16(sfrag[2*np+1], qf[ks], k2, k3);
            }
        }

        // ---- mask + scale + row max ----
        const float* msk = sMask + kt*64;
        float mx0 = -1e30f, mx1 = -1e30f;
#pragma unroll
        for (int nt = 0; nt < 8; nt++) {
            float2 am = *(const float2*)(msk + nt*8 + 2*qi);
            sfrag[nt][0] = fmaf(sfrag[nt][0], 0.125f, am.x);
            sfrag[nt][1] = fmaf(sfrag[nt][1], 0.125f, am.y);
            sfrag[nt][2] = fmaf(sfrag[nt][2], 0.125f, am.x);
            sfrag[nt][3] = fmaf(sfrag[nt][3], 0.125f, am.y);
            mx0 = fmaxf(mx0, fmaxf(sfrag[nt][0], sfrag[nt][1]));
            mx1 = fmaxf(mx1, fmaxf(sfrag[nt][2], sfrag[nt][3]));
        }
        mx0 = fmaxf(mx0, __shfl_xor_sync(~0u, mx0, 1));
        mx0 = fmaxf(mx0, __shfl_xor_sync(~0u, mx0, 2));
        mx1 = fmaxf(mx1, __shfl_xor_sync(~0u, mx1, 1));
        mx1 = fmaxf(mx1, __shfl_xor_sync(~0u, mx1, 2));

        // warp-voted correction: skip rescale when no row in the warp updated
        const bool upd = (mx0 > mrow0) || (mx1 > mrow1);
        const bool any_upd = __any_sync(~0u, upd);
        float cor0 = 1.f, cor1 = 1.f;
        if (any_upd) {
            float mnew0 = fmaxf(mrow0, mx0), mnew1 = fmaxf(mrow1, mx1);
            cor0 = fexp(mrow0 - mnew0); cor1 = fexp(mrow1 - mnew1);
            mrow0 = mnew0; mrow1 = mnew1;
        }

        // ---- exp + per-thread partial sums ----
        float ps0 = 0.f, ps1 = 0.f;
#pragma unroll
        for (int nt = 0; nt < 8; nt++) {
            sfrag[nt][0] = fexp(sfrag[nt][0] - mrow0);
            sfrag[nt][1] = fexp(sfrag[nt][1] - mrow0);
            sfrag[nt][2] = fexp(sfrag[nt][2] - mrow1);
            sfrag[nt][3] = fexp(sfrag[nt][3] - mrow1);
            ps0 += sfrag[nt][0] + sfrag[nt][1];
            ps1 += sfrag[nt][2] + sfrag[nt][3];
        }

        // ---- conditional O rescale, then PV mma (sum shuffles hidden) ----
        if (any_upd) {
#pragma unroll
            for (int nt = 0; nt < 8; nt++) {
                ofrag[nt][0] *= cor0; ofrag[nt][1] *= cor0;
                ofrag[nt][2] *= cor1; ofrag[nt][3] *= cor1;
            }
        }
        const u32 vBase = smb + SV_OFF + cur*KVTILE_B;
#pragma unroll
        for (int kk = 0; kk < 4; kk++) {
            u32 a[4];
            a[0] = pack_bf16(sfrag[2*kk][0],   sfrag[2*kk][1]);
            a[1] = pack_bf16(sfrag[2*kk][2],   sfrag[2*kk][3]);
            a[2] = pack_bf16(sfrag[2*kk+1][0], sfrag[2*kk+1][1]);
            a[3] = pack_bf16(sfrag[2*kk+1][2], sfrag[2*kk+1][3]);
#pragma unroll
            for (int dp = 0; dp < 4; dp++) {
                u32 v0, v1, v2, v3;
                u32 addr = vBase + (u32)(kk*16 + r8 + (g&1)*8) * KV_ROWB
                                 + (u32)(dp*16 + (g>>1)*8) * 2;
                ldsm_x4_t(v0, v1, v2, v3, addr);
                mma_bf16(ofrag[2*dp],   a, v0, v1);
                mma_bf16(ofrag[2*dp+1], a, v2, v3);
            }
        }

        // ---- deferred sum reduction + l update ----
        ps0 += __shfl_xor_sync(~0u, ps0, 1);
        ps0 += __shfl_xor_sync(~0u, ps0, 2);
        ps1 += __shfl_xor_sync(~0u, ps1, 1);
        ps1 += __shfl_xor_sync(~0u, ps1, 2);
        lrow0 = fmaf(lrow0, cor0, ps0);
        lrow1 = fmaf(lrow1, cor1, ps1);
    }

    const float inv0 = 1.0f / lrow0, inv1 = 1.0f / lrow1;
    const int r0 = q0 + warp*16 + qd;
    const int r1 = r0 + 8;
    __nv_bfloat16* o0 = Out + (size_t)(b*T_ + r0) * C_ + h*D_ + 2*qi;
    __nv_bfloat16* o1 = Out + (size_t)(b*T_ + r1) * C_ + h*D_ + 2*qi;
#pragma unroll
    for (int nt = 0; nt < 8; nt++) {
        *(u32*)(o0 + nt*8) = pack_bf16(ofrag[nt][0]*inv0, ofrag[nt][1]*inv0);
        *(u32*)(o1 + nt*8) = pack_bf16(ofrag[nt][2]*inv1, ofrag[nt][3]*inv1);
    }
}

// ---------------- host launcher ----------------
extern "C" void kernel_launch(void* const* d_in, const int* in_sizes, int n_in,
                              void* d_out, int out_size)
{
    const float* x    = (const float*)d_in[0];
    const int*   mask = (const int*)  d_in[1];
    const float* ln1w = (const float*)d_in[2];
    const float* ln1b = (const float*)d_in[3];
    const float* ln2w = (const float*)d_in[4];
    const float* ln2b = (const float*)d_in[5];
    const float* qw   = (const float*)d_in[6];
    const float* qb   = (const float*)d_in[7];
    const float* kw   = (const float*)d_in[8];
    const float* kb   = (const float*)d_in[9];
    const float* vw   = (const float*)d_in[10];
    const float* vb   = (const float*)d_in[11];
    const float* ow   = (const float*)d_in[12];
    const float* ob   = (const float*)d_in[13];
    const float* f1w  = (const float*)d_in[14];
    const float* f1b  = (const float*)d_in[15];
    const float* f2w  = (const float*)d_in[16];
    const float* f2b  = (const float*)d_in[17];
    const float* gm1  = (const float*)d_in[18];
    const float* gm2  = (const float*)d_in[19];
    float* out = (float*)d_out;

    __nv_bfloat16 *b_h, *b_h2, *b_qkv, *b_att, *b_f1, *b_wqkv, *b_wo, *b_wf1, *b_wf2;
    float *b_x1, *b_bqkv;
    cudaGetSymbolAddress((void**)&b_h,    g_hb);
    cudaGetSymbolAddress((void**)&b_h2,   g_h2b);
    cudaGetSymbolAddress((void**)&b_qkv,  g_qkv);
    cudaGetSymbolAddress((void**)&b_att,  g_attb);
    cudaGetSymbolAddress((void**)&b_f1,   g_f1b);
    cudaGetSymbolAddress((void**)&b_x1,   g_x1);
    cudaGetSymbolAddress((void**)&b_wqkv, g_wqkv);
    cudaGetSymbolAddress((void**)&b_wo,   g_wo);
    cudaGetSymbolAddress((void**)&b_wf1,  g_wf1);
    cudaGetSymbolAddress((void**)&b_wf2,  g_wf2);
    cudaGetSymbolAddress((void**)&b_bqkv, g_bqkv);

    cudaFuncSetAttribute(attn_kernel,
                         cudaFuncAttributeMaxDynamicSharedMemorySize, ATTN_SMEM);
    cudaFuncSetAttribute(bgemm_kernel<0,1>,
                         cudaFuncAttributeMaxDynamicSharedMemorySize, GEMM_SMEM);
    cudaFuncSetAttribute(bgemm_kernel<1,0>,
                         cudaFuncAttributeMaxDynamicSharedMemorySize, GEMM_SMEM);
    cudaFuncSetAttribute(bgemm_kernel<2,1>,
                         cudaFuncAttributeMaxDynamicSharedMemorySize, GEMM_SMEM);

    cvt_all_kernel<<<2048, 256>>>(qw, kw, vw, qb, kb, vb, ow, f1w, f2w);

    dim3 gridQKV(C3 / 128, NTOK / 128);
    dim3 gridC  (C_ / 128, NTOK / 128);
    dim3 gridF  (DFF / 128, NTOK / 128);

    ln_kernel<<<NTOK, 256>>>(x, ln1w, ln1b, b_h);
    bgemm_kernel<0,1><<<gridQKV, 128, GEMM_SMEM>>>(b_h, b_wqkv, b_bqkv, nullptr, nullptr, b_qkv, NTOK, C3, C_);
    attn_kernel<<<dim3(T_/128, H_, B_), 256, ATTN_SMEM>>>(b_qkv, mask, b_att);
    bgemm_kernel<1,0><<<gridC, 128, GEMM_SMEM>>>(b_att, b_wo, ob, x, gm1, b_x1, NTOK, C_, C_);
    ln_kernel<<<NTOK, 256>>>(b_x1, ln2w, ln2b, b_h2);
    bgemm_kernel<2,1><<<gridF, 128, GEMM_SMEM>>>(b_h2, b_wf1, f1b, nullptr, nullptr, b_f1, NTOK, DFF, C_);
    bgemm_kernel<1,0><<<gridC, 128, GEMM_SMEM>>>(b_f1, b_wf2, f2b, b_x1, gm2, out, NTOK, C_, DFF);
}

// round 17
// speedup vs baseline: 1.2972x; 1.0037x over previous
#include <cuda_runtime.h>
#include <cuda_bf16.h>
#include <cstdint>
#include <math.h>

typedef unsigned int u32;

#define B_   2
#define T_   2048
#define C_   1024
#define H_   16
#define D_   64
#define NTOK (B_*T_)
#define DFF  4096
#define C3   (3*C_)

// ---------------- scratch (no allocation allowed) ----------------
__device__ __nv_bfloat16 g_hb  [NTOK*C_];
__device__ __nv_bfloat16 g_h2b [NTOK*C_];
__device__ __nv_bfloat16 g_qkv [NTOK*C3];
__device__ __nv_bfloat16 g_attb[NTOK*C_];
__device__ __nv_bfloat16 g_f1b [(size_t)NTOK*DFF];
__device__ float         g_x1  [NTOK*C_];
__device__ __nv_bfloat16 g_wqkv[C_*C3];
__device__ __nv_bfloat16 g_wo  [C_*C_];
__device__ __nv_bfloat16 g_wf1 [C_*DFF];
__device__ __nv_bfloat16 g_wf2 [DFF*C_];
__device__ float         g_bqkv[C3];

// ---------------- small helpers ----------------
__device__ __forceinline__ u32 pack_bf16(float x, float y) {
    __nv_bfloat162 t = __floats2bfloat162_rn(x, y);
    u32 r; memcpy(&r, &t, 4); return r;
}
__device__ __forceinline__ void cp16(u32 sdst, const void* gsrc) {
    asm volatile("cp.async.cg.shared.global [%0], [%1], 16;" :: "r"(sdst), "l"(gsrc));
}
__device__ __forceinline__ void cp_commit() { asm volatile("cp.async.commit_group;"); }
__device__ __forceinline__ void ldsm_x4(u32& r0, u32& r1, u32& r2, u32& r3, u32 addr) {
    asm volatile("ldmatrix.sync.aligned.m8n8.x4.shared.b16 {%0,%1,%2,%3},[%4];"
                 : "=r"(r0), "=r"(r1), "=r"(r2), "=r"(r3) : "r"(addr));
}
__device__ __forceinline__ void ldsm_x4_t(u32& r0, u32& r1, u32& r2, u32& r3, u32 addr) {
    asm volatile("ldmatrix.sync.aligned.m8n8.x4.trans.shared.b16 {%0,%1,%2,%3},[%4];"
                 : "=r"(r0), "=r"(r1), "=r"(r2), "=r"(r3) : "r"(addr));
}
__device__ __forceinline__ void mma_bf16(float* c, const u32* a, u32 b0, u32 b1) {
    asm volatile("mma.sync.aligned.m16n8k16.row.col.f32.bf16.bf16.f32 "
                 "{%0,%1,%2,%3},{%4,%5,%6,%7},{%8,%9},{%0,%1,%2,%3};"
                 : "+f"(c[0]), "+f"(c[1]), "+f"(c[2]), "+f"(c[3])
                 : "r"(a[0]), "r"(a[1]), "r"(a[2]), "r"(a[3]), "r"(b0), "r"(b1));
}
// FFMA-only exp: no MUFU, no FRND/F2I. Magic 12582912 = 1.5*2^23.
__device__ __forceinline__ float fexp(float x) {
    x = fmaxf(x, -80.0f);
    float y  = fmaf(x, 1.4426950408889634f, 12582912.0f);
    int  ki  = __float_as_int(y);
    float kf = y - 12582912.0f;
    float t  = fmaf(kf, -0.6931471805599453f, x);
    float p  = fmaf(t, fmaf(t, fmaf(t, 0.16666667f, 0.5f), 1.0f), 1.0f);
    return __int_as_float(__float_as_int(p) + (ki << 23));
}

// ---------------- single fused weight conversion ----------------
__global__ void cvt_all_kernel(const float* __restrict__ qw, const float* __restrict__ kw,
                               const float* __restrict__ vw, const float* __restrict__ qb,
                               const float* __restrict__ kb, const float* __restrict__ vb,
                               const float* __restrict__ ow, const float* __restrict__ f1w,
                               const float* __restrict__ f2w)
{
    int gtid = blockIdx.x * blockDim.x + threadIdx.x;
    int stride = gridDim.x * blockDim.x;
    const int n_qkv = C_*C_/4;
    const int n_o   = C_*C_/4;
    const int n_f   = C_*DFF/4;
    for (int i = gtid; i < n_qkv; i += stride) {
        int c = i / (C_/4), j = (i % (C_/4)) * 4;
        float4 q4 = *(const float4*)(qw + (size_t)c*C_ + j);
        float4 k4 = *(const float4*)(kw + (size_t)c*C_ + j);
        float4 v4 = *(const float4*)(vw + (size_t)c*C_ + j);
        *(uint2*)(g_wqkv + (size_t)c*C3 + j)        = make_uint2(pack_bf16(q4.x,q4.y), pack_bf16(q4.z,q4.w));
        *(uint2*)(g_wqkv + (size_t)c*C3 + C_ + j)   = make_uint2(pack_bf16(k4.x,k4.y), pack_bf16(k4.z,k4.w));
        *(uint2*)(g_wqkv + (size_t)c*C3 + 2*C_ + j) = make_uint2(pack_bf16(v4.x,v4.y), pack_bf16(v4.z,v4.w));
    }
    for (int i = gtid; i < n_o; i += stride) {
        float4 s = *(const float4*)(ow + (size_t)i*4);
        *(uint2*)(g_wo + (size_t)i*4) = make_uint2(pack_bf16(s.x,s.y), pack_bf16(s.z,s.w));
    }
    for (int i = gtid; i < n_f; i += stride) {
        float4 s = *(const float4*)(f1w + (size_t)i*4);
        *(uint2*)(g_wf1 + (size_t)i*4) = make_uint2(pack_bf16(s.x,s.y), pack_bf16(s.z,s.w));
    }
    for (int i = gtid; i < n_f; i += stride) {
        float4 s = *(const float4*)(f2w + (size_t)i*4);
        *(uint2*)(g_wf2 + (size_t)i*4) = make_uint2(pack_bf16(s.x,s.y), pack_bf16(s.z,s.w));
    }
    if (gtid < C_) {
        g_bqkv[gtid]        = qb[gtid];
        g_bqkv[C_ + gtid]   = kb[gtid];
        g_bqkv[2*C_ + gtid] = vb[gtid];
    }
}

// ---------------- LayerNorm: single-pass fused sum/sumsq reduction ----------------
__global__ void __launch_bounds__(256) ln_kernel(const float* __restrict__ x,
                                                 const float* __restrict__ w,
                                                 const float* __restrict__ b,
                                                 __nv_bfloat16* __restrict__ y)
{
    __shared__ float redS[8];
    __shared__ float redQ[8];
    int row = blockIdx.x, tid = threadIdx.x;
    const float* xr = x + (size_t)row * C_;
    float4 v = *(const float4*)(xr + 4*tid);

    float s = v.x + v.y + v.z + v.w;
    float q = fmaf(v.x, v.x, fmaf(v.y, v.y, fmaf(v.z, v.z, v.w*v.w)));
#pragma unroll
    for (int o = 16; o > 0; o >>= 1) {
        s += __shfl_xor_sync(~0u, s, o);
        q += __shfl_xor_sync(~0u, q, o);
    }
    if ((tid & 31) == 0) { redS[tid >> 5] = s; redQ[tid >> 5] = q; }
    __syncthreads();
    if (tid < 32) {
        float ts = (tid < 8) ? redS[tid] : 0.f;
        float tq = (tid < 8) ? redQ[tid] : 0.f;
#pragma unroll
        for (int o = 4; o > 0; o >>= 1) {
            ts += __shfl_xor_sync(~0u, ts, o);
            tq += __shfl_xor_sync(~0u, tq, o);
        }
        if (tid == 0) { redS[0] = ts; redQ[0] = tq; }
    }
    __syncthreads();
    float mu  = redS[0] * (1.0f / C_);
    float var = fmaf(-mu, mu, redQ[0] * (1.0f / C_));
    float rs  = rsqrtf(var + 1e-5f);
    float4 w4 = *(const float4*)(w + 4*tid);
    float4 b4 = *(const float4*)(b + 4*tid);
    float o0 = (v.x - mu)*rs*w4.x + b4.x, o1 = (v.y - mu)*rs*w4.y + b4.y;
    float o2 = (v.z - mu)*rs*w4.z + b4.z, o3 = (v.w - mu)*rs*w4.w + b4.w;
    *(uint2*)(y + (size_t)row*C_ + 4*tid) = make_uint2(pack_bf16(o0,o1), pack_bf16(o2,o3));
}

// ---------------- GEMM 128x128x32, 4 warps, warp tile 64x64, 4-stage ----------------
#define GA_ROWB   80
#define GB_ROWB   272
#define GA_BYTES  (128*GA_ROWB)
#define GB_BYTES  (32*GB_ROWB)
#define STAGE_B   (GA_BYTES + GB_BYTES)
#define NSTAGE    4
#define GEMM_SMEM (NSTAGE*STAGE_B)

template<int MODE, int OBF>
__global__ void __launch_bounds__(128) bgemm_kernel(
    const __nv_bfloat16* __restrict__ A, const __nv_bfloat16* __restrict__ Bw,
    const float* __restrict__ bias,
    const float* __restrict__ resid, const float* __restrict__ gamma,
    void* __restrict__ CoutV, int M, int N, int K)
{
    extern __shared__ char gsm[];
    const u32 smb = (u32)__cvta_generic_to_shared(gsm);

    const int tid  = threadIdx.x;
    const int lane = tid & 31, warp = tid >> 5;
    const int warp_m = warp >> 1, warp_n = warp & 1;
    const int m_blk = blockIdx.y << 7, n_blk = blockIdx.x << 7;

    const int ar = tid >> 2, ac = tid & 3;
    const int br = tid >> 4, bc = tid & 15;
    const __nv_bfloat16* Ag = A  + (size_t)(m_blk + ar) * K + ac*8;
    const __nv_bfloat16* Bg = Bw + (size_t)br * N + n_blk + bc*8;
    const u32 dA0 = smb + ar*GA_ROWB + ac*16;
    const u32 dB0 = smb + GA_BYTES + br*GB_ROWB + bc*16;

    const int g  = lane >> 3;
    const int r8 = lane & 7;
    const u32 aAddr0 = smb + (u32)(warp_m*64 + r8 + (g&1)*8) * GA_ROWB + (u32)((g>>1)*16);
    const u32 bAddr0 = smb + GA_BYTES + (u32)(r8 + (g&1)*8) * GB_ROWB
                           + (u32)(warp_n*64 + (g>>1)*8) * 2;

    float acc[4][8][4];
#pragma unroll
    for (int mt = 0; mt < 4; mt++)
#pragma unroll
        for (int nt = 0; nt < 8; nt++)
#pragma unroll
            for (int i = 0; i < 4; i++) acc[mt][nt][i] = 0.f;

    const int nk = K >> 5;

    auto issue = [&](int kt) {
        const u32 sb = (kt & (NSTAGE-1)) * STAGE_B;
        const __nv_bfloat16* Ak = Ag + (kt << 5);
        const __nv_bfloat16* Bk = Bg + (size_t)(kt << 5) * N;
#pragma unroll
        for (int p = 0; p < 4; p++)
            cp16(dA0 + sb + p*32*GA_ROWB, Ak + (size_t)(p*32)*K);
#pragma unroll
        for (int p = 0; p < 4; p++)
            cp16(dB0 + sb + p*8*GB_ROWB,  Bk + (size_t)(p*8)*N);
        cp_commit();
    };

    issue(0);
    if (nk > 1) issue(1);
    if (nk > 2) issue(2);

    for (int kt = 0; kt < nk; kt++) {
        if      (kt + 2 < nk) asm volatile("cp.async.wait_group 2;");
        else if (kt + 1 < nk) asm volatile("cp.async.wait_group 1;");
        else                  asm volatile("cp.async.wait_group 0;");
        __syncthreads();

        if (kt + 3 < nk) issue(kt + 3);

        const u32 sb = (kt & (NSTAGE-1)) * STAGE_B;
        const u32 aB = aAddr0 + sb;
        const u32 bB = bAddr0 + sb;
#pragma unroll
        for (int ks = 0; ks < 2; ks++) {
            u32 af[4][4];
#pragma unroll
            for (int mt = 0; mt < 4; mt++)
                ldsm_x4(af[mt][0], af[mt][1], af[mt][2], af[mt][3],
                        aB + (u32)(mt*16) * GA_ROWB + (u32)(ks*32));
#pragma unroll
            for (int np = 0; np < 4; np++) {
                u32 b0, b1, b2, b3;
                ldsm_x4_t(b0, b1, b2, b3,
                          bB + (u32)(ks*16) * GB_ROWB + (u32)(np*32));
#pragma unroll
                for (int mt = 0; mt < 4; mt++) {
                    mma_bf16(acc[mt][2*np],   af[mt], b0, b1);
                    mma_bf16(acc[mt][2*np+1], af[mt], b2, b3);
                }
            }
        }
    }

    const int rr = lane >> 2, cc = (lane & 3) << 1;
    const int row0 = m_blk + warp_m * 64;
    const int col0 = n_blk + warp_n * 64;
#pragma unroll
    for (int mt = 0; mt < 4; mt++) {
#pragma unroll
        for (int nt = 0; nt < 8; nt++) {
            const int col = col0 + nt * 8 + cc;
            float2 b2 = *(const float2*)(bias + col);
            float2 g2 = make_float2(0.f, 0.f);
            if (MODE == 1) g2 = *(const float2*)(gamma + col);
#pragma unroll
            for (int half = 0; half < 2; half++) {
                const int row = row0 + mt * 16 + rr + half * 8;
                const size_t off = (size_t)row * N + col;
                float v0 = acc[mt][nt][half*2 + 0] + b2.x;
                float v1 = acc[mt][nt][half*2 + 1] + b2.y;
                if (MODE == 1) {
                    float2 rv = *(const float2*)(resid + off);
                    v0 = rv.x + g2.x * v0;
                    v1 = rv.y + g2.y * v1;
                } else if (MODE == 2) {
                    v0 = 0.5f * v0 * (1.0f + erff(v0 * 0.70710678118654752f));
                    v1 = 0.5f * v1 * (1.0f + erff(v1 * 0.70710678118654752f));
                }
                if (OBF) *(u32*)((__nv_bfloat16*)CoutV + off) = pack_bf16(v0, v1);
                else     *(float2*)((float*)CoutV + off) = make_float2(v0, v1);
            }
        }
    }
}

// ---------------- Flash attention: 128 queries/CTA, 8 warps, 3-buffer KV ----------------
#define KV_ROWB  144
#define QTILE_B  (128*KV_ROWB)
#define KVTILE_B (64*KV_ROWB)
#define SQ_OFF   0
#define SK_OFF   (QTILE_B)
#define SV_OFF   (QTILE_B + 3*KVTILE_B)
#define SMSK_OFF (QTILE_B + 6*KVTILE_B)
#define ATTN_SMEM (SMSK_OFF + T_*4)

__device__ __forceinline__ void attn_issue_kv(const __nv_bfloat16* __restrict__ qkv,
                                              u32 smb, int buf, int kt, int b, int h, int tid)
{
    const __nv_bfloat16* gK = qkv + ((size_t)(b*T_) + kt*64) * C3 + C_ + h*D_;
    const __nv_bfloat16* gV = gK + C_;
    u32 dK = smb + SK_OFF + buf*KVTILE_B;
    u32 dV = smb + SV_OFF + buf*KVTILE_B;
#pragma unroll
    for (int k = 0; k < 2; k++) {
        int c = tid + k*256;
        int row = c >> 3, col16 = c & 7;
        cp16(dK + row*KV_ROWB + col16*16, gK + (size_t)row*C3 + col16*8);
        cp16(dV + row*KV_ROWB + col16*16, gV + (size_t)row*C3 + col16*8);
    }
}

__global__ void __launch_bounds__(256, 2) attn_kernel(
    const __nv_bfloat16* __restrict__ qkv, const int* __restrict__ mask,
    __nv_bfloat16* __restrict__ Out)
{
    extern __shared__ char attn_sm[];
    u32 smb = (u32)__cvta_generic_to_shared(attn_sm);
    float* sMask = (float*)(attn_sm + SMSK_OFF);

    const int tid = threadIdx.x;
    const int lane = tid & 31, warp = tid >> 5;
    const int b = blockIdx.z, h = blockIdx.y;
    const int q0 = blockIdx.x << 7;
    const int g = lane >> 3, r8 = lane & 7;
    const int qd = lane >> 2, qi = lane & 3;

    {
        const __nv_bfloat16* gQ = qkv + ((size_t)(b*T_ + q0)) * C3 + h*D_;
#pragma unroll
        for (int k = 0; k < 4; k++) {
            int c = tid + k*256;
            int row = c >> 3, col16 = c & 7;
            cp16(smb + SQ_OFF + row*KV_ROWB + col16*16, gQ + (size_t)row*C3 + col16*8);
        }
        attn_issue_kv(qkv, smb, 0, 0, b, h, tid);
#pragma unroll
        for (int k = 0; k < T_/256; k++) {
            int idx = tid + k*256;
            sMask[idx] = mask[b*T_ + idx] ? 0.f : -1e30f;
        }
        cp_commit();
    }
    __syncthreads();

    float ofrag[8][4];
#pragma unroll
    for (int nt = 0; nt < 8; nt++)
#pragma unroll
        for (int i = 0; i < 4; i++) ofrag[nt][i] = 0.f;
    float mrow0 = -1e30f, mrow1 = -1e30f, lrow0 = 0.f, lrow1 = 0.f;
    u32 qf[4][4];

    const int NKT = T_ / 64;
    for (int kt = 0; kt < NKT; kt++) {
        const int cur = kt % 3;
        if (kt + 1 < NKT) {
            attn_issue_kv(qkv, smb, (kt + 1) % 3, kt + 1, b, h, tid);
            cp_commit();
            asm volatile("cp.async.wait_group 1;");
        } else {
            asm volatile("cp.async.wait_group 0;");
        }
        __syncthreads();

        if (kt == 0) {
#pragma unroll
            for (int ks = 0; ks < 4; ks++) {
                u32 addr = smb + SQ_OFF
                         + (u32)(warp*16 + r8 + (g&1)*8) * KV_ROWB
                         + (u32)(ks*16 + (g>>1)*8) * 2;
                ldsm_x4(qf[ks][0], qf[ks][1], qf[ks][2], qf[ks][3], addr);
            }
        }

        float sfrag[8][4];
#pragma unroll
        for (int nt = 0; nt < 8; nt++)
#pragma unroll
            for (int i = 0; i < 4; i++) sfrag[nt][i] = 0.f;
        const u32 kBase = smb + SK_OFF + cur*KVTILE_B;
#pragma unroll
        for (int ks = 0; ks < 4; ks++) {
#pragma unroll
            for (int np = 0; np < 4; np++) {
                u32 k0, k1, k2, k3;
                u32 addr = kBase + (u32)(np*16 + (g>>1)*8 + r8) * KV_ROWB
                                 + (u32)(ks*16 + (g&1)*8) * 2;
                ldsm_x4(k0, k1, k2, k3, addr);
                mma_bf16(sfrag[2*np],   qf[ks], k0, k1);
                mma_bf16(sfrag[2*np+1], qf[ks], k2, k3);
            }
        }

        const float* msk = sMask + kt*64;
        float mx0 = -1e30f, mx1 = -1e30f;
#pragma unroll
        for (int nt = 0; nt < 8; nt++) {
            float2 am = *(const float2*)(msk + nt*8 + 2*qi);
            sfrag[nt][0] = fmaf(sfrag[nt][0], 0.125f, am.x);
            sfrag[nt][1] = fmaf(sfrag[nt][1], 0.125f, am.y);
            sfrag[nt][2] = fmaf(sfrag[nt][2], 0.125f, am.x);
            sfrag[nt][3] = fmaf(sfrag[nt][3], 0.125f, am.y);
            mx0 = fmaxf(mx0, fmaxf(sfrag[nt][0], sfrag[nt][1]));
            mx1 = fmaxf(mx1, fmaxf(sfrag[nt][2], sfrag[nt][3]));
        }
        mx0 = fmaxf(mx0, __shfl_xor_sync(~0u, mx0, 1));
        mx0 = fmaxf(mx0, __shfl_xor_sync(~0u, mx0, 2));
        mx1 = fmaxf(mx1, __shfl_xor_sync(~0u, mx1, 1));
        mx1 = fmaxf(mx1, __shfl_xor_sync(~0u, mx1, 2));

        const bool upd = (mx0 > mrow0) || (mx1 > mrow1);
        const bool any_upd = __any_sync(~0u, upd);
        float cor0 = 1.f, cor1 = 1.f;
        if (any_upd) {
            float mnew0 = fmaxf(mrow0, mx0), mnew1 = fmaxf(mrow1, mx1);
            cor0 = fexp(mrow0 - mnew0); cor1 = fexp(mrow1 - mnew1);
            mrow0 = mnew0; mrow1 = mnew1;
        }

        float ps0 = 0.f, ps1 = 0.f;
#pragma unroll
        for (int nt = 0; nt < 8; nt++) {
            sfrag[nt][0] = fexp(sfrag[nt][0] - mrow0);
            sfrag[nt][1] = fexp(sfrag[nt][1] - mrow0);
            sfrag[nt][2] = fexp(sfrag[nt][2] - mrow1);
            sfrag[nt][3] = fexp(sfrag[nt][3] - mrow1);
            ps0 += sfrag[nt][0] + sfrag[nt][1];
            ps1 += sfrag[nt][2] + sfrag[nt][3];
        }

        if (any_upd) {
#pragma unroll
            for (int nt = 0; nt < 8; nt++) {
                ofrag[nt][0] *= cor0; ofrag[nt][1] *= cor0;
                ofrag[nt][2] *= cor1; ofrag[nt][3] *= cor1;
            }
        }
        const u32 vBase = smb + SV_OFF + cur*KVTILE_B;
#pragma unroll
        for (int kk = 0; kk < 4; kk++) {
            u32 a[4];
            a[0] = pack_bf16(sfrag[2*kk][0],   sfrag[2*kk][1]);
            a[1] = pack_bf16(sfrag[2*kk][2],   sfrag[2*kk][3]);
            a[2] = pack_bf16(sfrag[2*kk+1][0], sfrag[2*kk+1][1]);
            a[3] = pack_bf16(sfrag[2*kk+1][2], sfrag[2*kk+1][3]);
#pragma unroll
            for (int dp = 0; dp < 4; dp++) {
                u32 v0, v1, v2, v3;
                u32 addr = vBase + (u32)(kk*16 + r8 + (g&1)*8) * KV_ROWB
                                 + (u32)(dp*16 + (g>>1)*8) * 2;
                ldsm_x4_t(v0, v1, v2, v3, addr);
                mma_bf16(ofrag[2*dp],   a, v0, v1);
                mma_bf16(ofrag[2*dp+1], a, v2, v3);
            }
        }

        ps0 += __shfl_xor_sync(~0u, ps0, 1);
        ps0 += __shfl_xor_sync(~0u, ps0, 2);
        ps1 += __shfl_xor_sync(~0u, ps1, 1);
        ps1 += __shfl_xor_sync(~0u, ps1, 2);
        lrow0 = fmaf(lrow0, cor0, ps0);
        lrow1 = fmaf(lrow1, cor1, ps1);
    }

    const float inv0 = 1.0f / lrow0, inv1 = 1.0f / lrow1;
    const int r0 = q0 + warp*16 + qd;
    const int r1 = r0 + 8;
    __nv_bfloat16* o0 = Out + (size_t)(b*T_ + r0) * C_ + h*D_ + 2*qi;
    __nv_bfloat16* o1 = Out + (size_t)(b*T_ + r1) * C_ + h*D_ + 2*qi;
#pragma unroll
    for (int nt = 0; nt < 8; nt++) {
        *(u32*)(o0 + nt*8) = pack_bf16(ofrag[nt][0]*inv0, ofrag[nt][1]*inv0);
        *(u32*)(o1 + nt*8) = pack_bf16(ofrag[nt][2]*inv1, ofrag[nt][3]*inv1);
    }
}

// ---------------- host launcher ----------------
extern "C" void kernel_launch(void* const* d_in, const int* in_sizes, int n_in,
                              void* d_out, int out_size)
{
    const float* x    = (const float*)d_in[0];
    const int*   mask = (const int*)  d_in[1];
    const float* ln1w = (const float*)d_in[2];
    const float* ln1b = (const float*)d_in[3];
    const float* ln2w = (const float*)d_in[4];
    const float* ln2b = (const float*)d_in[5];
    const float* qw   = (const float*)d_in[6];
    const float* qb   = (const float*)d_in[7];
    const float* kw   = (const float*)d_in[8];
    const float* kb   = (const float*)d_in[9];
    const float* vw   = (const float*)d_in[10];
    const float* vb   = (const float*)d_in[11];
    const float* ow   = (const float*)d_in[12];
    const float* ob   = (const float*)d_in[13];
    const float* f1w  = (const float*)d_in[14];
    const float* f1b  = (const float*)d_in[15];
    const float* f2w  = (const float*)d_in[16];
    const float* f2b  = (const float*)d_in[17];
    const float* gm1  = (const float*)d_in[18];
    const float* gm2  = (const float*)d_in[19];
    float* out = (float*)d_out;

    __nv_bfloat16 *b_h, *b_h2, *b_qkv, *b_att, *b_f1, *b_wqkv, *b_wo, *b_wf1, *b_wf2;
    float *b_x1, *b_bqkv;
    cudaGetSymbolAddress((void**)&b_h,    g_hb);
    cudaGetSymbolAddress((void**)&b_h2,   g_h2b);
    cudaGetSymbolAddress((void**)&b_qkv,  g_qkv);
    cudaGetSymbolAddress((void**)&b_att,  g_attb);
    cudaGetSymbolAddress((void**)&b_f1,   g_f1b);
    cudaGetSymbolAddress((void**)&b_x1,   g_x1);
    cudaGetSymbolAddress((void**)&b_wqkv, g_wqkv);
    cudaGetSymbolAddress((void**)&b_wo,   g_wo);
    cudaGetSymbolAddress((void**)&b_wf1,  g_wf1);
    cudaGetSymbolAddress((void**)&b_wf2,  g_wf2);
    cudaGetSymbolAddress((void**)&b_bqkv, g_bqkv);

    cudaFuncSetAttribute(attn_kernel,
                         cudaFuncAttributeMaxDynamicSharedMemorySize, ATTN_SMEM);
    cudaFuncSetAttribute(bgemm_kernel<0,1>,
                         cudaFuncAttributeMaxDynamicSharedMemorySize, GEMM_SMEM);
    cudaFuncSetAttribute(bgemm_kernel<1,0>,
                         cudaFuncAttributeMaxDynamicSharedMemorySize, GEMM_SMEM);
    cudaFuncSetAttribute(bgemm_kernel<2,1>,
                         cudaFuncAttributeMaxDynamicSharedMemorySize, GEMM_SMEM);

    cvt_all_kernel<<<2048, 256>>>(qw, kw, vw, qb, kb, vb, ow, f1w, f2w);

    dim3 gridQKV(C3 / 128, NTOK / 128);
    dim3 gridC  (C_ / 128, NTOK / 128);
    dim3 gridF  (DFF / 128, NTOK / 128);

    ln_kernel<<<NTOK, 256>>>(x, ln1w, ln1b, b_h);
    bgemm_kernel<0,1><<<gridQKV, 128, GEMM_SMEM>>>(b_h, b_wqkv, b_bqkv, nullptr, nullptr, b_qkv, NTOK, C3, C_);
    attn_kernel<<<dim3(T_/128, H_, B_), 256, ATTN_SMEM>>>(b_qkv, mask, b_att);
    bgemm_kernel<1,0><<<gridC, 128, GEMM_SMEM>>>(b_att, b_wo, ob, x, gm1, b_x1, NTOK, C_, C_);
    ln_kernel<<<NTOK, 256>>>(b_x1, ln2w, ln2b, b_h2);
    bgemm_kernel<2,1><<<gridF, 128, GEMM_SMEM>>>(b_h2, b_wf1, f1b, nullptr, nullptr, b_f1, NTOK, DFF, C_);
    bgemm_kernel<1,0><<<gridC, 128, GEMM_SMEM>>>(b_f1, b_wf2, f2b, b_x1, gm2, out, NTOK, C_, DFF);
}